// round 7
// baseline (speedup 1.0000x reference)
#include <cuda_runtime.h>
#include <math.h>

typedef unsigned long long u64;

// ---- problem dims ----
#define NB      32
#define NUMPTS  2048
#define PN      1024
#define TILEP   8
#define FCS     100
#define BNI     0.9999950000374996f

// scratch
__device__ float g_ftsl[NB * NUMPTS * 64];        // lifted features
__device__ float g_X0 [32768 * 256];              // X-transform stage 0
__device__ float g_X1 [32768 * 256];
__device__ float g_X2 [32768 * 256];
__device__ float g_FCg[(size_t)32768 * 1536];     // fts_cat, compact [pt][16][96]

__device__ __forceinline__ float eluf(float x) {
    return x > 0.0f ? x : expm1f(x);
}
__device__ __forceinline__ u64 fma2(u64 a, u64 b, u64 c) {
    u64 d; asm("fma.rn.f32x2 %0,%1,%2,%3;" : "=l"(d) : "l"(a), "l"(b), "l"(c)); return d;
}
__device__ __forceinline__ u64 dup2(float x) {
    u64 d; asm("mov.b64 %0,{%1,%1};" : "=l"(d) : "f"(x)); return d;
}
__device__ __forceinline__ float2 unpk(u64 v) {
    float2 r; asm("mov.b64 {%0,%1},%2;" : "=f"(r.x), "=f"(r.y) : "l"(v)); return r;
}

// ============================================================================
// Kernel A: dense0 -> g_ftsl
// ============================================================================
__global__ void __launch_bounds__(256) dense0_kernel(
    const float* __restrict__ fts, const float* __restrict__ W,
    const float* __restrict__ b,   const float* __restrict__ g,
    const float* __restrict__ be)
{
    __shared__ float Ws[64 * 64];
    __shared__ float xs[16 * 64];
    const int t = threadIdx.x;
    const size_t row0 = (size_t)blockIdx.x * 16;

#pragma unroll
    for (int u = 0; u < 16; u++) Ws[t + 256 * u] = W[t + 256 * u];
    ((float4*)xs)[t] = ((const float4*)(fts + row0 * 64))[t];
    __syncthreads();

    const int r  = t >> 4;
    const int cb = (t & 15) * 4;
    u64 a0 = 0ull, a1 = 0ull;
#pragma unroll 8
    for (int k = 0; k < 64; k++) {
        u64 xd = dup2(xs[r * 64 + k]);
        ulonglong2 w = *(const ulonglong2*)&Ws[k * 64 + cb];
        a0 = fma2(xd, w.x, a0);
        a1 = fma2(xd, w.y, a1);
    }
    float2 f0 = unpk(a0), f1 = unpk(a1);
    float4 b4 = *(const float4*)&b[cb];
    float4 g4 = *(const float4*)&g[cb];
    float4 e4 = *(const float4*)&be[cb];
    float4 o;
    o.x = g4.x * (eluf(f0.x + b4.x) * BNI) + e4.x;
    o.y = g4.y * (eluf(f0.y + b4.y) * BNI) + e4.y;
    o.z = g4.z * (eluf(f1.x + b4.z) * BNI) + e4.z;
    o.w = g4.w * (eluf(f1.y + b4.w) * BNI) + e4.w;
    *(float4*)&g_ftsl[(row0 + r) * 64 + cb] = o;
}

// ============================================================================
// Kernel B (prep): gather + lift MLP + X0 conv. Writes g_X0, g_FCg.
// smem layout identical to prior kernel (B/C slots reused).
// ============================================================================
#define SM_FLOATS 18720
#define SMEM_B    (SM_FLOATS * 4)

__global__ void __launch_bounds__(256, 2) prep_kernel(
    const float* __restrict__ rep_pts, const float* __restrict__ pts,
    const int*   __restrict__ pts_idx,
    const float* __restrict__ d1W, const float* __restrict__ d1b,
    const float* __restrict__ d1g, const float* __restrict__ d1be,
    const float* __restrict__ d2W, const float* __restrict__ d2b,
    const float* __restrict__ d2g, const float* __restrict__ d2be,
    const float* __restrict__ xcW, const float* __restrict__ xcb)
{
    extern __shared__ float sm[];
    float* PT   = sm;            // [48][8]
    float* XA   = sm + 384;      // [256][8] X0
    float* H    = sm + 384;      // [32][128] (E phase, spans XA+XB)
    float* FC   = sm + 4480;     // [8][16][FCS]
    int*   SIDX = (int*)(sm + 17280);
    float* SD1W = sm + 17408; float* SD1B  = sm + 17504;
    float* SD1G = sm + 17536; float* SD1BE = sm + 17568;
    float* SD2W = sm + 17600; float* SD2B  = sm + 18624;
    float* SD2G = sm + 18656; float* SD2BE = sm + 18688;

    const int t   = threadIdx.x;
    const int gp0 = blockIdx.x * TILEP;
    const int n   = gp0 >> 10;

    for (int u = t; u < 96 + 1024; u += 256) {
        if (u < 96) SD1W[u] = d1W[u];
        else        SD2W[u - 96] = d2W[u - 96];
    }
    if (t < 32) {
        SD1B[t] = d1b[t]; SD1G[t] = d1g[t]; SD1BE[t] = d1be[t];
        SD2B[t] = d2b[t]; SD2G[t] = d2g[t]; SD2BE[t] = d2be[t];
    }
    if (t < 128) SIDX[t] = pts_idx[(size_t)gp0 * 16 + t];
    __syncthreads();

    if (t < 128) {
        int i = t >> 4, k = t & 15;
        int gi = SIDX[t];
        const float* pp = pts + ((size_t)n * NUMPTS + gi) * 3;
        const float* rp = rep_pts + (size_t)(gp0 + i) * 3;
        PT[( 0 + k) * 8 + i] = pp[0] - rp[0];
        PT[(16 + k) * 8 + i] = pp[1] - rp[1];
        PT[(32 + k) * 8 + i] = pp[2] - rp[2];
    }
    {
        int row = t >> 1, half = t & 1;
        int gi = SIDX[row];
        const float4* src = (const float4*)(g_ftsl + ((size_t)n * NUMPTS + gi) * 64 + half * 32);
        float4* dst = (float4*)&FC[row * FCS + 32 + half * 32];
#pragma unroll
        for (int u = 0; u < 8; u++) dst[u] = src[u];
    }
    __syncthreads();

    // E1: dense1 (3 -> 32) into H[c][row]
    {
        const int row = t & 127, hc = t >> 7;
        const int i = row >> 4, k = row & 15;
        float px = PT[k * 8 + i];
        float py = PT[(16 + k) * 8 + i];
        float pz = PT[(32 + k) * 8 + i];
#pragma unroll
        for (int u = 0; u < 16; u++) {
            int c = hc * 16 + u;
            float v = fmaf(px, SD1W[c], fmaf(py, SD1W[32 + c],
                      fmaf(pz, SD1W[64 + c], SD1B[c])));
            H[c * 128 + row] = SD1G[c] * (eluf(v) * BNI) + SD1BE[c];
        }
    }
    __syncthreads();

    // E2: dense2 (32 -> 32) -> FC[:,0:32]
    {
        const int row = t & 127, hc = t >> 7;
        float acc[16];
#pragma unroll
        for (int u = 0; u < 16; u++) acc[u] = SD2B[hc * 16 + u];
#pragma unroll 4
        for (int c = 0; c < 32; c++) {
            float hv = H[c * 128 + row];
            const float4* w4 = (const float4*)&SD2W[c * 32 + hc * 16];
#pragma unroll
            for (int q4 = 0; q4 < 4; q4++) {
                float4 w = w4[q4];
                acc[q4 * 4 + 0] += hv * w.x; acc[q4 * 4 + 1] += hv * w.y;
                acc[q4 * 4 + 2] += hv * w.z; acc[q4 * 4 + 3] += hv * w.w;
            }
        }
#pragma unroll
        for (int u = 0; u < 16; u++) {
            int c2 = hc * 16 + u;
            FC[row * FCS + c2] = SD2G[c2] * (eluf(acc[u]) * BNI) + SD2BE[c2];
        }
    }
    __syncthreads();   // H reused as XA next

    // Phase B: X0[q] = elu(sum_48 pls*xcW[q]) -> XA[q][i]
    {
        const int q = t;
        u64 acc[4] = {0ull, 0ull, 0ull, 0ull};
        const float4* w4p = (const float4*)(xcW + q * 48);
#pragma unroll 4
        for (int k4 = 0; k4 < 12; k4++) {
            float4 w = w4p[k4];
            float wv[4] = {w.x, w.y, w.z, w.w};
#pragma unroll
            for (int u = 0; u < 4; u++) {
                u64 wd = dup2(wv[u]);
                int k = k4 * 4 + u;
                ulonglong2 a0 = *(const ulonglong2*)&PT[k * 8];
                ulonglong2 a1 = *(const ulonglong2*)&PT[k * 8 + 4];
                acc[0] = fma2(a0.x, wd, acc[0]);
                acc[1] = fma2(a0.y, wd, acc[1]);
                acc[2] = fma2(a1.x, wd, acc[2]);
                acc[3] = fma2(a1.y, wd, acc[3]);
            }
        }
        float b = xcb[q];
        float2 f0 = unpk(acc[0]), f1 = unpk(acc[1]);
        float2 f2 = unpk(acc[2]), f3 = unpk(acc[3]);
        float x0v[8];
        x0v[0] = eluf(f0.x + b); x0v[1] = eluf(f0.y + b);
        x0v[2] = eluf(f1.x + b); x0v[3] = eluf(f1.y + b);
        x0v[4] = eluf(f2.x + b); x0v[5] = eluf(f2.y + b);
        x0v[6] = eluf(f3.x + b); x0v[7] = eluf(f3.y + b);
        // store X0 row-major [point][q] for the GEMM
#pragma unroll
        for (int i = 0; i < 8; i++)
            g_X0[(size_t)(gp0 + i) * 256 + q] = x0v[i];
    }

    // store fts_cat compact [pt][16][96]
    for (int idx = t; idx < 8 * 1536; idx += 256) {
        int row = idx / 96, c = idx - row * 96;
        g_FCg[(size_t)gp0 * 1536 + idx] = FC[row * FCS + c];
    }
}

// ============================================================================
// GEMM: C[M,256] = act(A[M,256] @ W[256,256] + bias). 128x128 tile, BK=16,
// 8x8 register tile per thread via fma.f32x2.
// ============================================================================
template<bool ELU>
__global__ void __launch_bounds__(256, 2) gemm256(
    const float* __restrict__ A, const float* __restrict__ W,
    const float* __restrict__ bias, float* __restrict__ C)
{
    __shared__ float As[16][132];   // transposed A tile, padded
    __shared__ float Bs[16][128];
    const int t  = threadIdx.x;
    const int m0 = blockIdx.y << 7;
    const int n0 = blockIdx.x << 7;
    const int tx = t & 15, ty = t >> 4;

    u64 acc[4][8];
#pragma unroll
    for (int i = 0; i < 4; i++)
#pragma unroll
        for (int j = 0; j < 8; j++) acc[i][j] = 0ull;

    const int ar = t >> 1, ak = (t & 1) * 8;
    const int bk = t >> 4, bn = (t & 15) * 8;

#pragma unroll 1
    for (int k0 = 0; k0 < 256; k0 += 16) {
        float4 a0 = *(const float4*)&A[(size_t)(m0 + ar) * 256 + k0 + ak];
        float4 a1 = *(const float4*)&A[(size_t)(m0 + ar) * 256 + k0 + ak + 4];
        float4 b0 = *(const float4*)&W[(size_t)(k0 + bk) * 256 + n0 + bn];
        float4 b1 = *(const float4*)&W[(size_t)(k0 + bk) * 256 + n0 + bn + 4];
        __syncthreads();
        As[ak + 0][ar] = a0.x; As[ak + 1][ar] = a0.y;
        As[ak + 2][ar] = a0.z; As[ak + 3][ar] = a0.w;
        As[ak + 4][ar] = a1.x; As[ak + 5][ar] = a1.y;
        As[ak + 6][ar] = a1.z; As[ak + 7][ar] = a1.w;
        *(float4*)&Bs[bk][bn]     = b0;
        *(float4*)&Bs[bk][bn + 4] = b1;
        __syncthreads();
#pragma unroll
        for (int kk = 0; kk < 16; kk++) {
            ulonglong2 aa0 = *(const ulonglong2*)&As[kk][ty * 8];
            ulonglong2 aa1 = *(const ulonglong2*)&As[kk][ty * 8 + 4];
            u64 am[4] = {aa0.x, aa0.y, aa1.x, aa1.y};
            float4 bb0 = *(const float4*)&Bs[kk][tx * 8];
            float4 bb1 = *(const float4*)&Bs[kk][tx * 8 + 4];
            float bs[8] = {bb0.x, bb0.y, bb0.z, bb0.w,
                           bb1.x, bb1.y, bb1.z, bb1.w};
#pragma unroll
            for (int nj = 0; nj < 8; nj++) {
                u64 bd = dup2(bs[nj]);
#pragma unroll
                for (int mi = 0; mi < 4; mi++)
                    acc[mi][nj] = fma2(am[mi], bd, acc[mi][nj]);
            }
        }
    }

    // epilogue
#pragma unroll
    for (int nj = 0; nj < 8; nj++) {
        int nn = n0 + tx * 8 + nj;
        float bv = __ldg(&bias[nn]);
#pragma unroll
        for (int mi = 0; mi < 4; mi++) {
            float2 f = unpk(acc[mi][nj]);
            float v0 = f.x + bv, v1 = f.y + bv;
            if (ELU) { v0 = eluf(v0); v1 = eluf(v1); }
            size_t m = (size_t)(m0 + ty * 8 + 2 * mi);
            C[m * 256 + nn]       = v0;
            C[(m + 1) * 256 + nn] = v1;
        }
    }
}

// ============================================================================
// Kernel E (epilogue): X2 + fts_cat -> phases F, G1, G2 -> out
// ============================================================================
__global__ void __launch_bounds__(256, 2) epi_kernel(
    const float* __restrict__ dwW,  const float* __restrict__ dwb,
    const float* __restrict__ pwW,  const float* __restrict__ pwb,
    const float* __restrict__ endg, const float* __restrict__ endbe,
    float* __restrict__ out)
{
    extern __shared__ float sm[];
    float* XA = sm + 384;    // [8][256]  X2
    float* XB = sm + 2432;   // [8][256]  DWS
    float* FC = sm + 4480;   // [8][16][FCS]

    const int t   = threadIdx.x;
    const int gp0 = blockIdx.x * TILEP;

    // load X2
    {
        const float4* src = (const float4*)(g_X2 + (size_t)gp0 * 256);
        float4* dst = (float4*)XA;
        dst[t] = src[t];
        dst[t + 256] = src[t + 256];
    }
    // load fts_cat into padded FC
    for (int idx = t * 4; idx < 8 * 1536; idx += 1024) {
        int row = idx / 96, c = idx - row * 96;
        *(float4*)&FC[row * FCS + c] =
            *(const float4*)&g_FCg[(size_t)gp0 * 1536 + idx];
    }
    __syncthreads();

    // Phase F: fts_X = X2(16x16) @ FC(16x96), in place
    {
        const int i = t >> 5, lane = t & 31;
        const float* X2 = &XA[i * 256];
#pragma unroll
        for (int u = 0; u < 3; u++) {
            int c = lane + 32 * u;
            float f[16];
#pragma unroll
            for (int cc = 0; cc < 16; cc++) f[cc] = FC[(i * 16 + cc) * FCS + c];
#pragma unroll
            for (int r = 0; r < 16; r++) {
                float acc = 0.f;
                const float4* xr = (const float4*)&X2[r * 16];
#pragma unroll
                for (int c4 = 0; c4 < 4; c4++) {
                    float4 xv = xr[c4];
                    acc += xv.x * f[c4 * 4] + xv.y * f[c4 * 4 + 1]
                         + xv.z * f[c4 * 4 + 2] + xv.w * f[c4 * 4 + 3];
                }
                FC[(i * 16 + r) * FCS + c] = acc;
            }
        }
    }
    __syncthreads();

    // Phase G1: depthwise
    float* DWS = XB;
    {
        const int i = t >> 5, lane = t & 31;
#pragma unroll
        for (int u = 0; u < 6; u++) {
            int cm = lane + 32 * u;
            int c = cm >> 1, m = cm & 1;
            float w[16];
            const float4* wp = (const float4*)(dwW + c * 32 + m * 16);
            *(float4*)&w[0]  = wp[0]; *(float4*)&w[4]  = wp[1];
            *(float4*)&w[8]  = wp[2]; *(float4*)&w[12] = wp[3];
            float acc = dwb[cm];
#pragma unroll
            for (int k = 0; k < 16; k++) acc += FC[(i * 16 + k) * FCS + c] * w[k];
            DWS[i * 256 + cm] = acc;
        }
    }
    __syncthreads();

    // Phase G2: pointwise + elu + BN
    {
        const int i = t >> 5, lane = t & 31;
        const int ob = lane * 4;
        ulonglong2 bi = *(const ulonglong2*)&pwb[ob];
        u64 acc0 = bi.x, acc1 = bi.y;
        const float* pwp = pwW + ob;
#pragma unroll 1
        for (int jt = 0; jt < 192; jt += 4) {
            ulonglong2 w[4];
#pragma unroll
            for (int u = 0; u < 4; u++)
                w[u] = *(const ulonglong2*)&pwp[(jt + u) * 128];
#pragma unroll
            for (int u = 0; u < 4; u++) {
                u64 vd = dup2(DWS[i * 256 + jt + u]);
                acc0 = fma2(vd, w[u].x, acc0);
                acc1 = fma2(vd, w[u].y, acc1);
            }
        }
        float2 f0 = unpk(acc0), f1 = unpk(acc1);
        float4 g4 = *(const float4*)&endg[ob];
        float4 e4 = *(const float4*)&endbe[ob];
        float4 o;
        o.x = g4.x * (eluf(f0.x) * BNI) + e4.x;
        o.y = g4.y * (eluf(f0.y) * BNI) + e4.y;
        o.z = g4.z * (eluf(f1.x) * BNI) + e4.z;
        o.w = g4.w * (eluf(f1.y) * BNI) + e4.w;
        *(float4*)&out[(size_t)(gp0 + i) * 128 + ob] = o;
    }
}

// ============================================================================
extern "C" void kernel_launch(void* const* d_in, const int* in_sizes, int n_in,
                              void* d_out, int out_size)
{
    const float* rep_pts = (const float*)d_in[0];
    const float* pts     = (const float*)d_in[1];
    const float* fts     = (const float*)d_in[2];
    const int*   pts_idx = (const int*)d_in[3];
    const float* d0W  = (const float*)d_in[4];
    const float* d0b  = (const float*)d_in[5];
    const float* d0g  = (const float*)d_in[6];
    const float* d0be = (const float*)d_in[7];
    const float* d1W  = (const float*)d_in[8];
    const float* d1b  = (const float*)d_in[9];
    const float* d1g  = (const float*)d_in[10];
    const float* d1be = (const float*)d_in[11];
    const float* d2W  = (const float*)d_in[12];
    const float* d2b  = (const float*)d_in[13];
    const float* d2g  = (const float*)d_in[14];
    const float* d2be = (const float*)d_in[15];
    const float* xcW  = (const float*)d_in[16];
    const float* xcb  = (const float*)d_in[17];
    const float* xd1W = (const float*)d_in[18];
    const float* xd1b = (const float*)d_in[19];
    const float* xd2W = (const float*)d_in[20];
    const float* xd2b = (const float*)d_in[21];
    const float* dwW  = (const float*)d_in[22];
    const float* dwb  = (const float*)d_in[23];
    const float* pwW  = (const float*)d_in[24];
    const float* pwb  = (const float*)d_in[25];
    const float* endg = (const float*)d_in[26];
    const float* endbe= (const float*)d_in[27];
    float* out = (float*)d_out;

    float *pX0, *pX1, *pX2;
    cudaGetSymbolAddress((void**)&pX0, g_X0);
    cudaGetSymbolAddress((void**)&pX1, g_X1);
    cudaGetSymbolAddress((void**)&pX2, g_X2);

    dense0_kernel<<<4096, 256>>>(fts, d0W, d0b, d0g, d0be);

    cudaFuncSetAttribute(prep_kernel,
                         cudaFuncAttributeMaxDynamicSharedMemorySize, SMEM_B);
    prep_kernel<<<32768 / TILEP, 256, SMEM_B>>>(
        rep_pts, pts, pts_idx,
        d1W, d1b, d1g, d1be, d2W, d2b, d2g, d2be, xcW, xcb);

    dim3 ggrid(2, 256);
    gemm256<true><<<ggrid, 256>>>(pX0, xd1W, xd1b, pX1);
    gemm256<false><<<ggrid, 256>>>(pX1, xd2W, xd2b, pX2);

    cudaFuncSetAttribute(epi_kernel,
                         cudaFuncAttributeMaxDynamicSharedMemorySize, SMEM_B);
    epi_kernel<<<32768 / TILEP, 256, SMEM_B>>>(
        dwW, dwb, pwW, pwb, endg, endbe, out);
}

// round 8
// speedup vs baseline: 1.1437x; 1.1437x over previous
#include <cuda_runtime.h>
#include <math.h>

typedef unsigned long long u64;

// ---- problem dims ----
#define NB      32
#define NUMPTS  2048
#define PN      1024
#define TILEP   8
#define FCS     100
#define BNI     0.9999950000374996f

// scratch
__device__ float g_ftsl[NB * NUMPTS * 64];
__device__ float g_X0 [32768 * 256];
__device__ float g_X1 [32768 * 256];
__device__ float g_X2 [32768 * 256];
__device__ float g_DW [(size_t)32768 * 192];
__device__ float g_FCg[(size_t)32768 * 1536];

__device__ __forceinline__ float eluf(float x) {
    return x > 0.0f ? x : expm1f(x);
}
__device__ __forceinline__ u64 fma2(u64 a, u64 b, u64 c) {
    u64 d; asm("fma.rn.f32x2 %0,%1,%2,%3;" : "=l"(d) : "l"(a), "l"(b), "l"(c)); return d;
}
__device__ __forceinline__ u64 dup2(float x) {
    u64 d; asm("mov.b64 %0,{%1,%1};" : "=l"(d) : "f"(x)); return d;
}
__device__ __forceinline__ float2 unpk(u64 v) {
    float2 r; asm("mov.b64 {%0,%1},%2;" : "=f"(r.x), "=f"(r.y) : "l"(v)); return r;
}

// ============================================================================
// Kernel A: dense0 -> g_ftsl
// ============================================================================
__global__ void __launch_bounds__(256) dense0_kernel(
    const float* __restrict__ fts, const float* __restrict__ W,
    const float* __restrict__ b,   const float* __restrict__ g,
    const float* __restrict__ be)
{
    __shared__ float Ws[64 * 64];
    __shared__ float xs[16 * 64];
    const int t = threadIdx.x;
    const size_t row0 = (size_t)blockIdx.x * 16;

#pragma unroll
    for (int u = 0; u < 16; u++) Ws[t + 256 * u] = W[t + 256 * u];
    ((float4*)xs)[t] = ((const float4*)(fts + row0 * 64))[t];
    __syncthreads();

    const int r  = t >> 4;
    const int cb = (t & 15) * 4;
    u64 a0 = 0ull, a1 = 0ull;
#pragma unroll 8
    for (int k = 0; k < 64; k++) {
        u64 xd = dup2(xs[r * 64 + k]);
        ulonglong2 w = *(const ulonglong2*)&Ws[k * 64 + cb];
        a0 = fma2(xd, w.x, a0);
        a1 = fma2(xd, w.y, a1);
    }
    float2 f0 = unpk(a0), f1 = unpk(a1);
    float4 b4 = *(const float4*)&b[cb];
    float4 g4 = *(const float4*)&g[cb];
    float4 e4 = *(const float4*)&be[cb];
    float4 o;
    o.x = g4.x * (eluf(f0.x + b4.x) * BNI) + e4.x;
    o.y = g4.y * (eluf(f0.y + b4.y) * BNI) + e4.y;
    o.z = g4.z * (eluf(f1.x + b4.z) * BNI) + e4.z;
    o.w = g4.w * (eluf(f1.y + b4.w) * BNI) + e4.w;
    *(float4*)&g_ftsl[(row0 + r) * 64 + cb] = o;
}

// ============================================================================
// Kernel B (prep): gather + lift MLP + X0 conv. Writes g_X0, g_FCg.
// smem (floats):
//   PT [48][8] @0 | XA/H @384 (spans to 4480) | FC [8][16][FCS] @4480
//   SIDX @17280 | SD1W @17408(96) SD1B @17504 SD1G @17536 SD1BE @17568
//   SD2Wd @17600 (2048, duplicated) | SD2B @19648 SD2G @19680 SD2BE @19712
// total 19744 floats = 78976 B
// ============================================================================
#define SM_FLOATS 19744
#define SMEM_B    (SM_FLOATS * 4)

__global__ void __launch_bounds__(256, 2) prep_kernel(
    const float* __restrict__ rep_pts, const float* __restrict__ pts,
    const int*   __restrict__ pts_idx,
    const float* __restrict__ d1W, const float* __restrict__ d1b,
    const float* __restrict__ d1g, const float* __restrict__ d1be,
    const float* __restrict__ d2W, const float* __restrict__ d2b,
    const float* __restrict__ d2g, const float* __restrict__ d2be,
    const float* __restrict__ xcW, const float* __restrict__ xcb)
{
    extern __shared__ float sm[];
    float* PT    = sm;
    float* XA    = sm + 384;     // [256][8] X0 (phase B)
    float* H     = sm + 384;     // [32][128] (E phase)
    float* FC    = sm + 4480;
    int*   SIDX  = (int*)(sm + 17280);
    float* SD1W  = sm + 17408; float* SD1B  = sm + 17504;
    float* SD1G  = sm + 17536; float* SD1BE = sm + 17568;
    float* SD2Wd = sm + 17600;                      // duplicated [c][64]
    float* SD2B  = sm + 19648; float* SD2G = sm + 19680;
    float* SD2BE = sm + 19712;

    const int t   = threadIdx.x;
    const int gp0 = blockIdx.x * TILEP;
    const int n   = gp0 >> 10;

    for (int u = t; u < 96; u += 256) SD1W[u] = d1W[u];
    for (int u = t; u < 1024; u += 256) {
        float w = d2W[u];
        SD2Wd[2 * u] = w; SD2Wd[2 * u + 1] = w;
    }
    if (t < 32) {
        SD1B[t] = d1b[t]; SD1G[t] = d1g[t]; SD1BE[t] = d1be[t];
        SD2B[t] = d2b[t]; SD2G[t] = d2g[t]; SD2BE[t] = d2be[t];
    }
    if (t < 128) SIDX[t] = pts_idx[(size_t)gp0 * 16 + t];
    __syncthreads();

    if (t < 128) {
        int i = t >> 4, k = t & 15;
        int gi = SIDX[t];
        const float* pp = pts + ((size_t)n * NUMPTS + gi) * 3;
        const float* rp = rep_pts + (size_t)(gp0 + i) * 3;
        PT[( 0 + k) * 8 + i] = pp[0] - rp[0];
        PT[(16 + k) * 8 + i] = pp[1] - rp[1];
        PT[(32 + k) * 8 + i] = pp[2] - rp[2];
    }
    {
        int row = t >> 1, half = t & 1;
        int gi = SIDX[row];
        const float4* src = (const float4*)(g_ftsl + ((size_t)n * NUMPTS + gi) * 64 + half * 32);
        float4* dst = (float4*)&FC[row * FCS + 32 + half * 32];
#pragma unroll
        for (int u = 0; u < 8; u++) dst[u] = src[u];
    }
    __syncthreads();

    // E1: dense1 (3 -> 32) into H[c][row]
    {
        const int row = t & 127, hc = t >> 7;
        const int i = row >> 4, k = row & 15;
        float px = PT[k * 8 + i];
        float py = PT[(16 + k) * 8 + i];
        float pz = PT[(32 + k) * 8 + i];
#pragma unroll
        for (int u = 0; u < 16; u++) {
            int c = hc * 16 + u;
            float v = fmaf(px, SD1W[c], fmaf(py, SD1W[32 + c],
                      fmaf(pz, SD1W[64 + c], SD1B[c])));
            H[c * 128 + row] = SD1G[c] * (eluf(v) * BNI) + SD1BE[c];
        }
    }
    __syncthreads();

    // E2: dense2 (32 -> 32), row-pair packed fma2 -> FC[:,0:32]
    {
        const int rp = t & 63, cg = t >> 6;     // 64 row-pairs x 4 col-groups
        const int row0 = 2 * rp, c0 = cg * 8;
        u64 acc[8];
#pragma unroll
        for (int u = 0; u < 8; u++) acc[u] = dup2(SD2B[c0 + u]);
#pragma unroll 4
        for (int c = 0; c < 32; c++) {
            u64 hv = *(const u64*)&H[c * 128 + row0];
            const ulonglong2* wd = (const ulonglong2*)&SD2Wd[c * 64 + 2 * c0];
            ulonglong2 w0 = wd[0], w1 = wd[1], w2 = wd[2], w3 = wd[3];
            acc[0] = fma2(hv, w0.x, acc[0]); acc[1] = fma2(hv, w0.y, acc[1]);
            acc[2] = fma2(hv, w1.x, acc[2]); acc[3] = fma2(hv, w1.y, acc[3]);
            acc[4] = fma2(hv, w2.x, acc[4]); acc[5] = fma2(hv, w2.y, acc[5]);
            acc[6] = fma2(hv, w3.x, acc[6]); acc[7] = fma2(hv, w3.y, acc[7]);
        }
#pragma unroll
        for (int u = 0; u < 8; u++) {
            int c = c0 + u;
            float2 f = unpk(acc[u]);
            FC[row0 * FCS + c]       = SD2G[c] * (eluf(f.x) * BNI) + SD2BE[c];
            FC[(row0 + 1) * FCS + c] = SD2G[c] * (eluf(f.y) * BNI) + SD2BE[c];
        }
    }
    __syncthreads();   // H reused as XA next

    // Phase B: X0[q] = elu(sum_48 pls*xcW[q])
    {
        const int q = t;
        u64 acc[4] = {0ull, 0ull, 0ull, 0ull};
        const float4* w4p = (const float4*)(xcW + q * 48);
#pragma unroll 4
        for (int k4 = 0; k4 < 12; k4++) {
            float4 w = w4p[k4];
            float wv[4] = {w.x, w.y, w.z, w.w};
#pragma unroll
            for (int u = 0; u < 4; u++) {
                u64 wd = dup2(wv[u]);
                int k = k4 * 4 + u;
                ulonglong2 a0 = *(const ulonglong2*)&PT[k * 8];
                ulonglong2 a1 = *(const ulonglong2*)&PT[k * 8 + 4];
                acc[0] = fma2(a0.x, wd, acc[0]);
                acc[1] = fma2(a0.y, wd, acc[1]);
                acc[2] = fma2(a1.x, wd, acc[2]);
                acc[3] = fma2(a1.y, wd, acc[3]);
            }
        }
        float b = xcb[q];
        float2 f0 = unpk(acc[0]), f1 = unpk(acc[1]);
        float2 f2 = unpk(acc[2]), f3 = unpk(acc[3]);
        float x0v[8];
        x0v[0] = eluf(f0.x + b); x0v[1] = eluf(f0.y + b);
        x0v[2] = eluf(f1.x + b); x0v[3] = eluf(f1.y + b);
        x0v[4] = eluf(f2.x + b); x0v[5] = eluf(f2.y + b);
        x0v[6] = eluf(f3.x + b); x0v[7] = eluf(f3.y + b);
#pragma unroll
        for (int i = 0; i < 8; i++)
            g_X0[(size_t)(gp0 + i) * 256 + q] = x0v[i];
    }

    // store fts_cat compact [pt][16][96]
    for (int idx = t; idx < 8 * 1536; idx += 256) {
        int row = idx / 96, c = idx - row * 96;
        g_FCg[(size_t)gp0 * 1536 + idx] = FC[row * FCS + c];
    }
}

// ============================================================================
// GEMM: C[M,256] = act(A[M,256] @ W[256,256] + bias). 128x128, BK=16,
// double-buffered smem, single sync per k-step, 8x8 f32x2 thread tile.
// ============================================================================
template<bool ELU>
__global__ void __launch_bounds__(256, 2) gemm256(
    const float* __restrict__ A, const float* __restrict__ W,
    const float* __restrict__ bias, float* __restrict__ C)
{
    __shared__ float As[2][16][132];
    __shared__ float Bs[2][16][128];
    const int t  = threadIdx.x;
    const int m0 = blockIdx.y << 7;
    const int n0 = blockIdx.x << 7;
    const int tx = t & 15, ty = t >> 4;

    u64 acc[4][8];
#pragma unroll
    for (int i = 0; i < 4; i++)
#pragma unroll
        for (int j = 0; j < 8; j++) acc[i][j] = 0ull;

    const int ar = t >> 1, ak = (t & 1) * 8;
    const int bk = t >> 4, bn = (t & 15) * 8;
    const float* Arow = A + (size_t)(m0 + ar) * 256;

    float4 a0 = *(const float4*)&Arow[ak];
    float4 a1 = *(const float4*)&Arow[ak + 4];
    float4 b0 = *(const float4*)&W[(size_t)bk * 256 + n0 + bn];
    float4 b1 = *(const float4*)&W[(size_t)bk * 256 + n0 + bn + 4];

#pragma unroll 1
    for (int k0 = 0; k0 < 16; k0++) {
        const int buf = k0 & 1;
        As[buf][ak + 0][ar] = a0.x; As[buf][ak + 1][ar] = a0.y;
        As[buf][ak + 2][ar] = a0.z; As[buf][ak + 3][ar] = a0.w;
        As[buf][ak + 4][ar] = a1.x; As[buf][ak + 5][ar] = a1.y;
        As[buf][ak + 6][ar] = a1.z; As[buf][ak + 7][ar] = a1.w;
        *(float4*)&Bs[buf][bk][bn]     = b0;
        *(float4*)&Bs[buf][bk][bn + 4] = b1;
        __syncthreads();
        if (k0 < 15) {
            int kn = (k0 + 1) * 16;
            a0 = *(const float4*)&Arow[kn + ak];
            a1 = *(const float4*)&Arow[kn + ak + 4];
            b0 = *(const float4*)&W[(size_t)(kn + bk) * 256 + n0 + bn];
            b1 = *(const float4*)&W[(size_t)(kn + bk) * 256 + n0 + bn + 4];
        }
#pragma unroll
        for (int kk = 0; kk < 16; kk++) {
            ulonglong2 aa0 = *(const ulonglong2*)&As[buf][kk][ty * 8];
            ulonglong2 aa1 = *(const ulonglong2*)&As[buf][kk][ty * 8 + 4];
            u64 am[4] = {aa0.x, aa0.y, aa1.x, aa1.y};
            float4 bb0 = *(const float4*)&Bs[buf][kk][tx * 8];
            float4 bb1 = *(const float4*)&Bs[buf][kk][tx * 8 + 4];
            float bs[8] = {bb0.x, bb0.y, bb0.z, bb0.w,
                           bb1.x, bb1.y, bb1.z, bb1.w};
#pragma unroll
            for (int nj = 0; nj < 8; nj++) {
                u64 bd = dup2(bs[nj]);
#pragma unroll
                for (int mi = 0; mi < 4; mi++)
                    acc[mi][nj] = fma2(am[mi], bd, acc[mi][nj]);
            }
        }
    }

#pragma unroll
    for (int nj = 0; nj < 8; nj++) {
        int nn = n0 + tx * 8 + nj;
        float bv = __ldg(&bias[nn]);
#pragma unroll
        for (int mi = 0; mi < 4; mi++) {
            float2 f = unpk(acc[mi][nj]);
            float v0 = f.x + bv, v1 = f.y + bv;
            if (ELU) { v0 = eluf(v0); v1 = eluf(v1); }
            size_t m = (size_t)(m0 + ty * 8 + 2 * mi);
            C[m * 256 + nn]       = v0;
            C[(m + 1) * 256 + nn] = v1;
        }
    }
}

// ============================================================================
// GEMM-PW: out[M,128] = endg*(elu(DW[M,192] @ pwW[192,128] + pwb)*BNI)+endbe
// ============================================================================
__global__ void __launch_bounds__(256, 2) gemm_pw(
    const float* __restrict__ pwW, const float* __restrict__ pwb,
    const float* __restrict__ endg, const float* __restrict__ endbe,
    float* __restrict__ out)
{
    __shared__ float As[2][16][132];
    __shared__ float Bs[2][16][128];
    const int t  = threadIdx.x;
    const int m0 = blockIdx.x << 7;
    const int tx = t & 15, ty = t >> 4;

    u64 acc[4][8];
#pragma unroll
    for (int i = 0; i < 4; i++)
#pragma unroll
        for (int j = 0; j < 8; j++) acc[i][j] = 0ull;

    const int ar = t >> 1, ak = (t & 1) * 8;
    const int bk = t >> 4, bn = (t & 15) * 8;
    const float* Arow = g_DW + (size_t)(m0 + ar) * 192;

    float4 a0 = *(const float4*)&Arow[ak];
    float4 a1 = *(const float4*)&Arow[ak + 4];
    float4 b0 = *(const float4*)&pwW[(size_t)bk * 128 + bn];
    float4 b1 = *(const float4*)&pwW[(size_t)bk * 128 + bn + 4];

#pragma unroll 1
    for (int k0 = 0; k0 < 12; k0++) {
        const int buf = k0 & 1;
        As[buf][ak + 0][ar] = a0.x; As[buf][ak + 1][ar] = a0.y;
        As[buf][ak + 2][ar] = a0.z; As[buf][ak + 3][ar] = a0.w;
        As[buf][ak + 4][ar] = a1.x; As[buf][ak + 5][ar] = a1.y;
        As[buf][ak + 6][ar] = a1.z; As[buf][ak + 7][ar] = a1.w;
        *(float4*)&Bs[buf][bk][bn]     = b0;
        *(float4*)&Bs[buf][bk][bn + 4] = b1;
        __syncthreads();
        if (k0 < 11) {
            int kn = (k0 + 1) * 16;
            a0 = *(const float4*)&Arow[kn + ak];
            a1 = *(const float4*)&Arow[kn + ak + 4];
            b0 = *(const float4*)&pwW[(size_t)(kn + bk) * 128 + bn];
            b1 = *(const float4*)&pwW[(size_t)(kn + bk) * 128 + bn + 4];
        }
#pragma unroll
        for (int kk = 0; kk < 16; kk++) {
            ulonglong2 aa0 = *(const ulonglong2*)&As[buf][kk][ty * 8];
            ulonglong2 aa1 = *(const ulonglong2*)&As[buf][kk][ty * 8 + 4];
            u64 am[4] = {aa0.x, aa0.y, aa1.x, aa1.y};
            float4 bb0 = *(const float4*)&Bs[buf][kk][tx * 8];
            float4 bb1 = *(const float4*)&Bs[buf][kk][tx * 8 + 4];
            float bs[8] = {bb0.x, bb0.y, bb0.z, bb0.w,
                           bb1.x, bb1.y, bb1.z, bb1.w};
#pragma unroll
            for (int nj = 0; nj < 8; nj++) {
                u64 bd = dup2(bs[nj]);
#pragma unroll
                for (int mi = 0; mi < 4; mi++)
                    acc[mi][nj] = fma2(am[mi], bd, acc[mi][nj]);
            }
        }
    }

#pragma unroll
    for (int nj = 0; nj < 8; nj++) {
        int nn = tx * 8 + nj;
        float bv = __ldg(&pwb[nn]);
        float gv = __ldg(&endg[nn]);
        float ev = __ldg(&endbe[nn]);
#pragma unroll
        for (int mi = 0; mi < 4; mi++) {
            float2 f = unpk(acc[mi][nj]);
            float v0 = gv * (eluf(f.x + bv) * BNI) + ev;
            float v1 = gv * (eluf(f.y + bv) * BNI) + ev;
            size_t m = (size_t)(m0 + ty * 8 + 2 * mi);
            out[m * 128 + nn]       = v0;
            out[(m + 1) * 128 + nn] = v1;
        }
    }
}

// ============================================================================
// Kernel E (epilogue): X2 + fts_cat -> phases F, G1 -> g_DW
// ============================================================================
__global__ void __launch_bounds__(256, 2) epi_kernel(
    const float* __restrict__ dwW, const float* __restrict__ dwb)
{
    extern __shared__ float sm[];
    float* XA = sm + 384;    // [8][256]  X2
    float* FC = sm + 4480;   // [8][16][FCS]

    const int t   = threadIdx.x;
    const int gp0 = blockIdx.x * TILEP;

    {
        const float4* src = (const float4*)(g_X2 + (size_t)gp0 * 256);
        float4* dst = (float4*)XA;
        dst[t] = src[t];
        dst[t + 256] = src[t + 256];
    }
    for (int idx = t * 4; idx < 8 * 1536; idx += 1024) {
        int row = idx / 96, c = idx - row * 96;
        *(float4*)&FC[row * FCS + c] =
            *(const float4*)&g_FCg[(size_t)gp0 * 1536 + idx];
    }
    __syncthreads();

    // Phase F: fts_X = X2(16x16) @ FC(16x96), in place
    {
        const int i = t >> 5, lane = t & 31;
        const float* X2 = &XA[i * 256];
#pragma unroll
        for (int u = 0; u < 3; u++) {
            int c = lane + 32 * u;
            float f[16];
#pragma unroll
            for (int cc = 0; cc < 16; cc++) f[cc] = FC[(i * 16 + cc) * FCS + c];
#pragma unroll
            for (int r = 0; r < 16; r++) {
                float acc = 0.f;
                const float4* xr = (const float4*)&X2[r * 16];
#pragma unroll
                for (int c4 = 0; c4 < 4; c4++) {
                    float4 xv = xr[c4];
                    acc += xv.x * f[c4 * 4] + xv.y * f[c4 * 4 + 1]
                         + xv.z * f[c4 * 4 + 2] + xv.w * f[c4 * 4 + 3];
                }
                FC[(i * 16 + r) * FCS + c] = acc;
            }
        }
    }
    __syncthreads();

    // Phase G1: depthwise -> g_DW
    {
        const int i = t >> 5, lane = t & 31;
#pragma unroll
        for (int u = 0; u < 6; u++) {
            int cm = lane + 32 * u;
            int c = cm >> 1, m = cm & 1;
            float w[16];
            const float4* wp = (const float4*)(dwW + c * 32 + m * 16);
            *(float4*)&w[0]  = wp[0]; *(float4*)&w[4]  = wp[1];
            *(float4*)&w[8]  = wp[2]; *(float4*)&w[12] = wp[3];
            float acc = dwb[cm];
#pragma unroll
            for (int k = 0; k < 16; k++) acc += FC[(i * 16 + k) * FCS + c] * w[k];
            g_DW[(size_t)(gp0 + i) * 192 + cm] = acc;
        }
    }
}

// ============================================================================
extern "C" void kernel_launch(void* const* d_in, const int* in_sizes, int n_in,
                              void* d_out, int out_size)
{
    const float* rep_pts = (const float*)d_in[0];
    const float* pts     = (const float*)d_in[1];
    const float* fts     = (const float*)d_in[2];
    const int*   pts_idx = (const int*)d_in[3];
    const float* d0W  = (const float*)d_in[4];
    const float* d0b  = (const float*)d_in[5];
    const float* d0g  = (const float*)d_in[6];
    const float* d0be = (const float*)d_in[7];
    const float* d1W  = (const float*)d_in[8];
    const float* d1b  = (const float*)d_in[9];
    const float* d1g  = (const float*)d_in[10];
    const float* d1be = (const float*)d_in[11];
    const float* d2W  = (const float*)d_in[12];
    const float* d2b  = (const float*)d_in[13];
    const float* d2g  = (const float*)d_in[14];
    const float* d2be = (const float*)d_in[15];
    const float* xcW  = (const float*)d_in[16];
    const float* xcb  = (const float*)d_in[17];
    const float* xd1W = (const float*)d_in[18];
    const float* xd1b = (const float*)d_in[19];
    const float* xd2W = (const float*)d_in[20];
    const float* xd2b = (const float*)d_in[21];
    const float* dwW  = (const float*)d_in[22];
    const float* dwb  = (const float*)d_in[23];
    const float* pwW  = (const float*)d_in[24];
    const float* pwb  = (const float*)d_in[25];
    const float* endg = (const float*)d_in[26];
    const float* endbe= (const float*)d_in[27];
    float* out = (float*)d_out;

    float *pX0, *pX1, *pX2;
    cudaGetSymbolAddress((void**)&pX0, g_X0);
    cudaGetSymbolAddress((void**)&pX1, g_X1);
    cudaGetSymbolAddress((void**)&pX2, g_X2);

    dense0_kernel<<<4096, 256>>>(fts, d0W, d0b, d0g, d0be);

    cudaFuncSetAttribute(prep_kernel,
                         cudaFuncAttributeMaxDynamicSharedMemorySize, SMEM_B);
    prep_kernel<<<32768 / TILEP, 256, SMEM_B>>>(
        rep_pts, pts, pts_idx,
        d1W, d1b, d1g, d1be, d2W, d2b, d2g, d2be, xcW, xcb);

    dim3 ggrid(2, 256);
    gemm256<true><<<ggrid, 256>>>(pX0, xd1W, xd1b, pX1);
    gemm256<false><<<ggrid, 256>>>(pX1, xd2W, xd2b, pX2);

    cudaFuncSetAttribute(epi_kernel,
                         cudaFuncAttributeMaxDynamicSharedMemorySize, SMEM_B);
    epi_kernel<<<32768 / TILEP, 256, SMEM_B>>>(dwW, dwb);

    gemm_pw<<<256, 256>>>(pwW, pwb, endg, endbe, out);
}

// round 9
// speedup vs baseline: 1.4557x; 1.2728x over previous
#include <cuda_runtime.h>
#include <math.h>

typedef unsigned long long u64;
typedef unsigned int u32;

// ---- problem dims ----
#define NB      32
#define NUMPTS  2048
#define PN      1024
#define TILEP   8
#define FCS     100
#define BNI     0.9999950000374996f

// scratch
__device__ float g_ftsl[NB * NUMPTS * 64];
__device__ float g_X0 [32768 * 256];
__device__ float g_X1 [32768 * 256];
__device__ float g_X2 [32768 * 256];
__device__ float g_DW [(size_t)32768 * 192];
__device__ float g_FCg[(size_t)32768 * 1536];

__device__ __forceinline__ float eluf(float x) {
    return x > 0.0f ? x : expm1f(x);
}
__device__ __forceinline__ u64 fma2(u64 a, u64 b, u64 c) {
    u64 d; asm("fma.rn.f32x2 %0,%1,%2,%3;" : "=l"(d) : "l"(a), "l"(b), "l"(c)); return d;
}
__device__ __forceinline__ u64 dup2(float x) {
    u64 d; asm("mov.b64 %0,{%1,%1};" : "=l"(d) : "f"(x)); return d;
}
__device__ __forceinline__ float2 unpk(u64 v) {
    float2 r; asm("mov.b64 {%0,%1},%2;" : "=f"(r.x), "=f"(r.y) : "l"(v)); return r;
}
__device__ __forceinline__ u32 tf32(float f) {
    u32 o; asm("cvt.rna.tf32.f32 %0, %1;" : "=r"(o) : "f"(f)); return o;
}
__device__ __forceinline__ void mma8(float4& d, const u32* a, u32 b0, u32 b1) {
    asm("mma.sync.aligned.m16n8k8.row.col.f32.tf32.tf32.f32 "
        "{%0,%1,%2,%3}, {%4,%5,%6,%7}, {%8,%9}, {%0,%1,%2,%3};"
        : "+f"(d.x), "+f"(d.y), "+f"(d.z), "+f"(d.w)
        : "r"(a[0]), "r"(a[1]), "r"(a[2]), "r"(a[3]), "r"(b0), "r"(b1));
}

// ============================================================================
// Kernel A: dense0 -> g_ftsl
// ============================================================================
__global__ void __launch_bounds__(256) dense0_kernel(
    const float* __restrict__ fts, const float* __restrict__ W,
    const float* __restrict__ b,   const float* __restrict__ g,
    const float* __restrict__ be)
{
    __shared__ float Ws[64 * 64];
    __shared__ float xs[16 * 64];
    const int t = threadIdx.x;
    const size_t row0 = (size_t)blockIdx.x * 16;

#pragma unroll
    for (int u = 0; u < 16; u++) Ws[t + 256 * u] = W[t + 256 * u];
    ((float4*)xs)[t] = ((const float4*)(fts + row0 * 64))[t];
    __syncthreads();

    const int r  = t >> 4;
    const int cb = (t & 15) * 4;
    u64 a0 = 0ull, a1 = 0ull;
#pragma unroll 8
    for (int k = 0; k < 64; k++) {
        u64 xd = dup2(xs[r * 64 + k]);
        ulonglong2 w = *(const ulonglong2*)&Ws[k * 64 + cb];
        a0 = fma2(xd, w.x, a0);
        a1 = fma2(xd, w.y, a1);
    }
    float2 f0 = unpk(a0), f1 = unpk(a1);
    float4 b4 = *(const float4*)&b[cb];
    float4 g4 = *(const float4*)&g[cb];
    float4 e4 = *(const float4*)&be[cb];
    float4 o;
    o.x = g4.x * (eluf(f0.x + b4.x) * BNI) + e4.x;
    o.y = g4.y * (eluf(f0.y + b4.y) * BNI) + e4.y;
    o.z = g4.z * (eluf(f1.x + b4.z) * BNI) + e4.z;
    o.w = g4.w * (eluf(f1.y + b4.w) * BNI) + e4.w;
    *(float4*)&g_ftsl[(row0 + r) * 64 + cb] = o;
}

// ============================================================================
// Kernel B (prep): gather + lift MLP + X0 conv. Writes g_X0, g_FCg.
// ============================================================================
#define SM_FLOATS 19744
#define SMEM_B    (SM_FLOATS * 4)

__global__ void __launch_bounds__(256, 2) prep_kernel(
    const float* __restrict__ rep_pts, const float* __restrict__ pts,
    const int*   __restrict__ pts_idx,
    const float* __restrict__ d1W, const float* __restrict__ d1b,
    const float* __restrict__ d1g, const float* __restrict__ d1be,
    const float* __restrict__ d2W, const float* __restrict__ d2b,
    const float* __restrict__ d2g, const float* __restrict__ d2be,
    const float* __restrict__ xcW, const float* __restrict__ xcb)
{
    extern __shared__ float sm[];
    float* PT    = sm;
    float* H     = sm + 384;     // [32][128] (E phase)
    float* FC    = sm + 4480;
    int*   SIDX  = (int*)(sm + 17280);
    float* SD1W  = sm + 17408; float* SD1B  = sm + 17504;
    float* SD1G  = sm + 17536; float* SD1BE = sm + 17568;
    float* SD2Wd = sm + 17600;                      // duplicated [c][64]
    float* SD2B  = sm + 19648; float* SD2G = sm + 19680;
    float* SD2BE = sm + 19712;

    const int t   = threadIdx.x;
    const int gp0 = blockIdx.x * TILEP;
    const int n   = gp0 >> 10;

    for (int u = t; u < 96; u += 256) SD1W[u] = d1W[u];
    for (int u = t; u < 1024; u += 256) {
        float w = d2W[u];
        SD2Wd[2 * u] = w; SD2Wd[2 * u + 1] = w;
    }
    if (t < 32) {
        SD1B[t] = d1b[t]; SD1G[t] = d1g[t]; SD1BE[t] = d1be[t];
        SD2B[t] = d2b[t]; SD2G[t] = d2g[t]; SD2BE[t] = d2be[t];
    }
    if (t < 128) SIDX[t] = pts_idx[(size_t)gp0 * 16 + t];
    __syncthreads();

    if (t < 128) {
        int i = t >> 4, k = t & 15;
        int gi = SIDX[t];
        const float* pp = pts + ((size_t)n * NUMPTS + gi) * 3;
        const float* rp = rep_pts + (size_t)(gp0 + i) * 3;
        PT[( 0 + k) * 8 + i] = pp[0] - rp[0];
        PT[(16 + k) * 8 + i] = pp[1] - rp[1];
        PT[(32 + k) * 8 + i] = pp[2] - rp[2];
    }
    {
        int row = t >> 1, half = t & 1;
        int gi = SIDX[row];
        const float4* src = (const float4*)(g_ftsl + ((size_t)n * NUMPTS + gi) * 64 + half * 32);
        float4* dst = (float4*)&FC[row * FCS + 32 + half * 32];
#pragma unroll
        for (int u = 0; u < 8; u++) dst[u] = src[u];
    }
    __syncthreads();

    // E1: dense1 (3 -> 32) into H[c][row]
    {
        const int row = t & 127, hc = t >> 7;
        const int i = row >> 4, k = row & 15;
        float px = PT[k * 8 + i];
        float py = PT[(16 + k) * 8 + i];
        float pz = PT[(32 + k) * 8 + i];
#pragma unroll
        for (int u = 0; u < 16; u++) {
            int c = hc * 16 + u;
            float v = fmaf(px, SD1W[c], fmaf(py, SD1W[32 + c],
                      fmaf(pz, SD1W[64 + c], SD1B[c])));
            H[c * 128 + row] = SD1G[c] * (eluf(v) * BNI) + SD1BE[c];
        }
    }
    __syncthreads();

    // E2: dense2 (32 -> 32), row-pair packed fma2 -> FC[:,0:32]
    {
        const int rp = t & 63, cg = t >> 6;
        const int row0 = 2 * rp, c0 = cg * 8;
        u64 acc[8];
#pragma unroll
        for (int u = 0; u < 8; u++) acc[u] = dup2(SD2B[c0 + u]);
#pragma unroll 4
        for (int c = 0; c < 32; c++) {
            u64 hv = *(const u64*)&H[c * 128 + row0];
            const ulonglong2* wd = (const ulonglong2*)&SD2Wd[c * 64 + 2 * c0];
            ulonglong2 w0 = wd[0], w1 = wd[1], w2 = wd[2], w3 = wd[3];
            acc[0] = fma2(hv, w0.x, acc[0]); acc[1] = fma2(hv, w0.y, acc[1]);
            acc[2] = fma2(hv, w1.x, acc[2]); acc[3] = fma2(hv, w1.y, acc[3]);
            acc[4] = fma2(hv, w2.x, acc[4]); acc[5] = fma2(hv, w2.y, acc[5]);
            acc[6] = fma2(hv, w3.x, acc[6]); acc[7] = fma2(hv, w3.y, acc[7]);
        }
#pragma unroll
        for (int u = 0; u < 8; u++) {
            int c = c0 + u;
            float2 f = unpk(acc[u]);
            FC[row0 * FCS + c]       = SD2G[c] * (eluf(f.x) * BNI) + SD2BE[c];
            FC[(row0 + 1) * FCS + c] = SD2G[c] * (eluf(f.y) * BNI) + SD2BE[c];
        }
    }
    __syncthreads();

    // Phase B: X0[q] = elu(sum_48 pls*xcW[q])
    {
        const int q = t;
        u64 acc[4] = {0ull, 0ull, 0ull, 0ull};
        const float4* w4p = (const float4*)(xcW + q * 48);
#pragma unroll 4
        for (int k4 = 0; k4 < 12; k4++) {
            float4 w = w4p[k4];
            float wv[4] = {w.x, w.y, w.z, w.w};
#pragma unroll
            for (int u = 0; u < 4; u++) {
                u64 wd = dup2(wv[u]);
                int k = k4 * 4 + u;
                ulonglong2 a0 = *(const ulonglong2*)&PT[k * 8];
                ulonglong2 a1 = *(const ulonglong2*)&PT[k * 8 + 4];
                acc[0] = fma2(a0.x, wd, acc[0]);
                acc[1] = fma2(a0.y, wd, acc[1]);
                acc[2] = fma2(a1.x, wd, acc[2]);
                acc[3] = fma2(a1.y, wd, acc[3]);
            }
        }
        float b = xcb[q];
        float2 f0 = unpk(acc[0]), f1 = unpk(acc[1]);
        float2 f2 = unpk(acc[2]), f3 = unpk(acc[3]);
        float x0v[8];
        x0v[0] = eluf(f0.x + b); x0v[1] = eluf(f0.y + b);
        x0v[2] = eluf(f1.x + b); x0v[3] = eluf(f1.y + b);
        x0v[4] = eluf(f2.x + b); x0v[5] = eluf(f2.y + b);
        x0v[6] = eluf(f3.x + b); x0v[7] = eluf(f3.y + b);
#pragma unroll
        for (int i = 0; i < 8; i++)
            g_X0[(size_t)(gp0 + i) * 256 + q] = x0v[i];
    }

    for (int idx = t; idx < 8 * 1536; idx += 256) {
        int row = idx / 96, c = idx - row * 96;
        g_FCg[(size_t)gp0 * 1536 + idx] = FC[row * FCS + c];
    }
}

// ============================================================================
// GEMM (TF32 tensor): C[M,256] = act(A[M,256] @ W[256,256] + bias)
// 128x128 block, 8 warps (4m x 2n), warp tile 32x64 = 2x8 m16n8k8 frags,
// K-chunk 16 double-buffered, single sync per chunk.
// A smem stride 20, B stride 136 -> conflict-free fragment loads.
// ============================================================================
template<bool ELU>
__global__ void __launch_bounds__(256, 2) gemm256_tf32(
    const float* __restrict__ A, const float* __restrict__ W,
    const float* __restrict__ bias, float* __restrict__ C)
{
    __shared__ u32 As[2][128][20];
    __shared__ u32 Bs[2][16][136];
    const int t  = threadIdx.x;
    const int m0 = blockIdx.y << 7;
    const int n0 = blockIdx.x << 7;
    const int wid = t >> 5, lane = t & 31;
    const int wm = wid >> 1, wn = wid & 1;
    const int g = lane >> 2, tg = lane & 3;

    float4 acc[2][8];
#pragma unroll
    for (int i = 0; i < 2; i++)
#pragma unroll
        for (int j = 0; j < 8; j++) acc[i][j] = make_float4(0.f, 0.f, 0.f, 0.f);

    const int ar = t >> 1, ak = (t & 1) * 8;
    const int bk = t >> 4, bn = (t & 15) * 8;
    const float* Arow = A + (size_t)(m0 + ar) * 256;

    float4 a0 = *(const float4*)&Arow[ak];
    float4 a1 = *(const float4*)&Arow[ak + 4];
    float4 b0 = *(const float4*)&W[(size_t)bk * 256 + n0 + bn];
    float4 b1 = *(const float4*)&W[(size_t)bk * 256 + n0 + bn + 4];

#pragma unroll 1
    for (int k0 = 0; k0 < 16; k0++) {
        const int buf = k0 & 1;
        {
            u32* ap = &As[buf][ar][ak];
            ap[0] = tf32(a0.x); ap[1] = tf32(a0.y);
            ap[2] = tf32(a0.z); ap[3] = tf32(a0.w);
            ap[4] = tf32(a1.x); ap[5] = tf32(a1.y);
            ap[6] = tf32(a1.z); ap[7] = tf32(a1.w);
            u32* bp = &Bs[buf][bk][bn];
            bp[0] = tf32(b0.x); bp[1] = tf32(b0.y);
            bp[2] = tf32(b0.z); bp[3] = tf32(b0.w);
            bp[4] = tf32(b1.x); bp[5] = tf32(b1.y);
            bp[6] = tf32(b1.z); bp[7] = tf32(b1.w);
        }
        __syncthreads();
        if (k0 < 15) {
            int kn = (k0 + 1) * 16;
            a0 = *(const float4*)&Arow[kn + ak];
            a1 = *(const float4*)&Arow[kn + ak + 4];
            b0 = *(const float4*)&W[(size_t)(kn + bk) * 256 + n0 + bn];
            b1 = *(const float4*)&W[(size_t)(kn + bk) * 256 + n0 + bn + 4];
        }
#pragma unroll
        for (int kk = 0; kk < 2; kk++) {
            const int kb = kk * 8;
            u32 af[2][4];
#pragma unroll
            for (int mi = 0; mi < 2; mi++) {
                int r = wm * 32 + mi * 16;
                af[mi][0] = As[buf][r + g][kb + tg];
                af[mi][1] = As[buf][r + g + 8][kb + tg];
                af[mi][2] = As[buf][r + g][kb + tg + 4];
                af[mi][3] = As[buf][r + g + 8][kb + tg + 4];
            }
#pragma unroll
            for (int nj = 0; nj < 8; nj++) {
                int cn = wn * 64 + nj * 8 + g;
                u32 bf0 = Bs[buf][kb + tg][cn];
                u32 bf1 = Bs[buf][kb + tg + 4][cn];
                mma8(acc[0][nj], af[0], bf0, bf1);
                mma8(acc[1][nj], af[1], bf0, bf1);
            }
        }
    }

    // epilogue
#pragma unroll
    for (int nj = 0; nj < 8; nj++) {
        int col = n0 + wn * 64 + nj * 8 + tg * 2;
        float bv0 = __ldg(&bias[col]);
        float bv1 = __ldg(&bias[col + 1]);
#pragma unroll
        for (int mi = 0; mi < 2; mi++) {
            int row = m0 + wm * 32 + mi * 16 + g;
            float4 d = acc[mi][nj];
            float v0 = d.x + bv0, v1 = d.y + bv1;
            float v2 = d.z + bv0, v3 = d.w + bv1;
            if (ELU) { v0 = eluf(v0); v1 = eluf(v1); v2 = eluf(v2); v3 = eluf(v3); }
            float2 s0; s0.x = v0; s0.y = v1;
            float2 s1; s1.x = v2; s1.y = v3;
            *(float2*)&C[(size_t)row * 256 + col]       = s0;
            *(float2*)&C[(size_t)(row + 8) * 256 + col] = s1;
        }
    }
}

// ============================================================================
// GEMM-PW: out[M,128] = endg*(elu(DW[M,192] @ pwW[192,128] + pwb)*BNI)+endbe
// ============================================================================
__global__ void __launch_bounds__(256, 2) gemm_pw(
    const float* __restrict__ pwW, const float* __restrict__ pwb,
    const float* __restrict__ endg, const float* __restrict__ endbe,
    float* __restrict__ out)
{
    __shared__ float As[2][16][132];
    __shared__ float Bs[2][16][128];
    const int t  = threadIdx.x;
    const int m0 = blockIdx.x << 7;
    const int tx = t & 15, ty = t >> 4;

    u64 acc[4][8];
#pragma unroll
    for (int i = 0; i < 4; i++)
#pragma unroll
        for (int j = 0; j < 8; j++) acc[i][j] = 0ull;

    const int ar = t >> 1, ak = (t & 1) * 8;
    const int bk = t >> 4, bn = (t & 15) * 8;
    const float* Arow = g_DW + (size_t)(m0 + ar) * 192;

    float4 a0 = *(const float4*)&Arow[ak];
    float4 a1 = *(const float4*)&Arow[ak + 4];
    float4 b0 = *(const float4*)&pwW[(size_t)bk * 128 + bn];
    float4 b1 = *(const float4*)&pwW[(size_t)bk * 128 + bn + 4];

#pragma unroll 1
    for (int k0 = 0; k0 < 12; k0++) {
        const int buf = k0 & 1;
        As[buf][ak + 0][ar] = a0.x; As[buf][ak + 1][ar] = a0.y;
        As[buf][ak + 2][ar] = a0.z; As[buf][ak + 3][ar] = a0.w;
        As[buf][ak + 4][ar] = a1.x; As[buf][ak + 5][ar] = a1.y;
        As[buf][ak + 6][ar] = a1.z; As[buf][ak + 7][ar] = a1.w;
        *(float4*)&Bs[buf][bk][bn]     = b0;
        *(float4*)&Bs[buf][bk][bn + 4] = b1;
        __syncthreads();
        if (k0 < 11) {
            int kn = (k0 + 1) * 16;
            a0 = *(const float4*)&Arow[kn + ak];
            a1 = *(const float4*)&Arow[kn + ak + 4];
            b0 = *(const float4*)&pwW[(size_t)(kn + bk) * 128 + bn];
            b1 = *(const float4*)&pwW[(size_t)(kn + bk) * 128 + bn + 4];
        }
#pragma unroll
        for (int kk = 0; kk < 16; kk++) {
            ulonglong2 aa0 = *(const ulonglong2*)&As[buf][kk][ty * 8];
            ulonglong2 aa1 = *(const ulonglong2*)&As[buf][kk][ty * 8 + 4];
            u64 am[4] = {aa0.x, aa0.y, aa1.x, aa1.y};
            float4 bb0 = *(const float4*)&Bs[buf][kk][tx * 8];
            float4 bb1 = *(const float4*)&Bs[buf][kk][tx * 8 + 4];
            float bs[8] = {bb0.x, bb0.y, bb0.z, bb0.w,
                           bb1.x, bb1.y, bb1.z, bb1.w};
#pragma unroll
            for (int nj = 0; nj < 8; nj++) {
                u64 bd = dup2(bs[nj]);
#pragma unroll
                for (int mi = 0; mi < 4; mi++)
                    acc[mi][nj] = fma2(am[mi], bd, acc[mi][nj]);
            }
        }
    }

#pragma unroll
    for (int nj = 0; nj < 8; nj++) {
        int nn = tx * 8 + nj;
        float bv = __ldg(&pwb[nn]);
        float gv = __ldg(&endg[nn]);
        float ev = __ldg(&endbe[nn]);
#pragma unroll
        for (int mi = 0; mi < 4; mi++) {
            float2 f = unpk(acc[mi][nj]);
            float v0 = gv * (eluf(f.x + bv) * BNI) + ev;
            float v1 = gv * (eluf(f.y + bv) * BNI) + ev;
            size_t m = (size_t)(m0 + ty * 8 + 2 * mi);
            out[m * 128 + nn]       = v0;
            out[(m + 1) * 128 + nn] = v1;
        }
    }
}

// ============================================================================
// Kernel E (epilogue): X2 + fts_cat -> phases F, G1 -> g_DW
// ============================================================================
__global__ void __launch_bounds__(256, 2) epi_kernel(
    const float* __restrict__ dwW, const float* __restrict__ dwb)
{
    extern __shared__ float sm[];
    float* XA = sm + 384;    // [8][256]  X2
    float* FC = sm + 4480;   // [8][16][FCS]

    const int t   = threadIdx.x;
    const int gp0 = blockIdx.x * TILEP;

    {
        const float4* src = (const float4*)(g_X2 + (size_t)gp0 * 256);
        float4* dst = (float4*)XA;
        dst[t] = src[t];
        dst[t + 256] = src[t + 256];
    }
    for (int idx = t * 4; idx < 8 * 1536; idx += 1024) {
        int row = idx / 96, c = idx - row * 96;
        *(float4*)&FC[row * FCS + c] =
            *(const float4*)&g_FCg[(size_t)gp0 * 1536 + idx];
    }
    __syncthreads();

    // Phase F: fts_X = X2(16x16) @ FC(16x96), in place
    {
        const int i = t >> 5, lane = t & 31;
        const float* X2 = &XA[i * 256];
#pragma unroll
        for (int u = 0; u < 3; u++) {
            int c = lane + 32 * u;
            float f[16];
#pragma unroll
            for (int cc = 0; cc < 16; cc++) f[cc] = FC[(i * 16 + cc) * FCS + c];
#pragma unroll
            for (int r = 0; r < 16; r++) {
                float acc = 0.f;
                const float4* xr = (const float4*)&X2[r * 16];
#pragma unroll
                for (int c4 = 0; c4 < 4; c4++) {
                    float4 xv = xr[c4];
                    acc += xv.x * f[c4 * 4] + xv.y * f[c4 * 4 + 1]
                         + xv.z * f[c4 * 4 + 2] + xv.w * f[c4 * 4 + 3];
                }
                FC[(i * 16 + r) * FCS + c] = acc;
            }
        }
    }
    __syncthreads();

    // Phase G1: depthwise -> g_DW
    {
        const int i = t >> 5, lane = t & 31;
#pragma unroll
        for (int u = 0; u < 6; u++) {
            int cm = lane + 32 * u;
            int c = cm >> 1, m = cm & 1;
            float w[16];
            const float4* wp = (const float4*)(dwW + c * 32 + m * 16);
            *(float4*)&w[0]  = wp[0]; *(float4*)&w[4]  = wp[1];
            *(float4*)&w[8]  = wp[2]; *(float4*)&w[12] = wp[3];
            float acc = dwb[cm];
#pragma unroll
            for (int k = 0; k < 16; k++) acc += FC[(i * 16 + k) * FCS + c] * w[k];
            g_DW[(size_t)(gp0 + i) * 192 + cm] = acc;
        }
    }
}

// ============================================================================
extern "C" void kernel_launch(void* const* d_in, const int* in_sizes, int n_in,
                              void* d_out, int out_size)
{
    const float* rep_pts = (const float*)d_in[0];
    const float* pts     = (const float*)d_in[1];
    const float* fts     = (const float*)d_in[2];
    const int*   pts_idx = (const int*)d_in[3];
    const float* d0W  = (const float*)d_in[4];
    const float* d0b  = (const float*)d_in[5];
    const float* d0g  = (const float*)d_in[6];
    const float* d0be = (const float*)d_in[7];
    const float* d1W  = (const float*)d_in[8];
    const float* d1b  = (const float*)d_in[9];
    const float* d1g  = (const float*)d_in[10];
    const float* d1be = (const float*)d_in[11];
    const float* d2W  = (const float*)d_in[12];
    const float* d2b  = (const float*)d_in[13];
    const float* d2g  = (const float*)d_in[14];
    const float* d2be = (const float*)d_in[15];
    const float* xcW  = (const float*)d_in[16];
    const float* xcb  = (const float*)d_in[17];
    const float* xd1W = (const float*)d_in[18];
    const float* xd1b = (const float*)d_in[19];
    const float* xd2W = (const float*)d_in[20];
    const float* xd2b = (const float*)d_in[21];
    const float* dwW  = (const float*)d_in[22];
    const float* dwb  = (const float*)d_in[23];
    const float* pwW  = (const float*)d_in[24];
    const float* pwb  = (const float*)d_in[25];
    const float* endg = (const float*)d_in[26];
    const float* endbe= (const float*)d_in[27];
    float* out = (float*)d_out;

    float *pX0, *pX1, *pX2;
    cudaGetSymbolAddress((void**)&pX0, g_X0);
    cudaGetSymbolAddress((void**)&pX1, g_X1);
    cudaGetSymbolAddress((void**)&pX2, g_X2);

    dense0_kernel<<<4096, 256>>>(fts, d0W, d0b, d0g, d0be);

    cudaFuncSetAttribute(prep_kernel,
                         cudaFuncAttributeMaxDynamicSharedMemorySize, SMEM_B);
    prep_kernel<<<32768 / TILEP, 256, SMEM_B>>>(
        rep_pts, pts, pts_idx,
        d1W, d1b, d1g, d1be, d2W, d2b, d2g, d2be, xcW, xcb);

    dim3 ggrid(2, 256);
    gemm256_tf32<true><<<ggrid, 256>>>(pX0, xd1W, xd1b, pX1);
    gemm256_tf32<false><<<ggrid, 256>>>(pX1, xd2W, xd2b, pX2);

    cudaFuncSetAttribute(epi_kernel,
                         cudaFuncAttributeMaxDynamicSharedMemorySize, SMEM_B);
    epi_kernel<<<32768 / TILEP, 256, SMEM_B>>>(dwW, dwb);

    gemm_pw<<<256, 256>>>(pwW, pwb, endg, endbe, out);
}

// round 10
// speedup vs baseline: 1.4583x; 1.0018x over previous
#include <cuda_runtime.h>
#include <math.h>

typedef unsigned long long u64;
typedef unsigned int u32;

// ---- problem dims ----
#define NB      32
#define NUMPTS  2048
#define PN      1024
#define TILEP   8
#define FCS     100
#define BNI     0.9999950000374996f

// scratch
__device__ float g_ftsl[NB * NUMPTS * 64];
__device__ float g_X0 [32768 * 256];
__device__ float g_X1 [32768 * 256];
__device__ float g_X2 [32768 * 256];
__device__ float g_DW [(size_t)32768 * 192];
__device__ float g_FCg[(size_t)32768 * 1536];

__device__ __forceinline__ float eluf(float x) {
    return x > 0.0f ? x : expm1f(x);
}
__device__ __forceinline__ u64 fma2(u64 a, u64 b, u64 c) {
    u64 d; asm("fma.rn.f32x2 %0,%1,%2,%3;" : "=l"(d) : "l"(a), "l"(b), "l"(c)); return d;
}
__device__ __forceinline__ u64 dup2(float x) {
    u64 d; asm("mov.b64 %0,{%1,%1};" : "=l"(d) : "f"(x)); return d;
}
__device__ __forceinline__ u64 pk2(float lo, float hi) {
    u64 d; asm("mov.b64 %0,{%1,%2};" : "=l"(d) : "f"(lo), "f"(hi)); return d;
}
__device__ __forceinline__ float2 unpk(u64 v) {
    float2 r; asm("mov.b64 {%0,%1},%2;" : "=f"(r.x), "=f"(r.y) : "l"(v)); return r;
}
__device__ __forceinline__ u32 tf32(float f) {
    u32 o; asm("cvt.rna.tf32.f32 %0, %1;" : "=r"(o) : "f"(f)); return o;
}
__device__ __forceinline__ void mma8(float4& d, const u32* a, u32 b0, u32 b1) {
    asm("mma.sync.aligned.m16n8k8.row.col.f32.tf32.tf32.f32 "
        "{%0,%1,%2,%3}, {%4,%5,%6,%7}, {%8,%9}, {%0,%1,%2,%3};"
        : "+f"(d.x), "+f"(d.y), "+f"(d.z), "+f"(d.w)
        : "r"(a[0]), "r"(a[1]), "r"(a[2]), "r"(a[3]), "r"(b0), "r"(b1));
}

// ============================================================================
// Kernel A: dense0 -> g_ftsl
// ============================================================================
__global__ void __launch_bounds__(256) dense0_kernel(
    const float* __restrict__ fts, const float* __restrict__ W,
    const float* __restrict__ b,   const float* __restrict__ g,
    const float* __restrict__ be)
{
    __shared__ float Ws[64 * 64];
    __shared__ float xs[16 * 64];
    const int t = threadIdx.x;
    const size_t row0 = (size_t)blockIdx.x * 16;

#pragma unroll
    for (int u = 0; u < 16; u++) Ws[t + 256 * u] = W[t + 256 * u];
    ((float4*)xs)[t] = ((const float4*)(fts + row0 * 64))[t];
    __syncthreads();

    const int r  = t >> 4;
    const int cb = (t & 15) * 4;
    u64 a0 = 0ull, a1 = 0ull;
#pragma unroll 8
    for (int k = 0; k < 64; k++) {
        u64 xd = dup2(xs[r * 64 + k]);
        ulonglong2 w = *(const ulonglong2*)&Ws[k * 64 + cb];
        a0 = fma2(xd, w.x, a0);
        a1 = fma2(xd, w.y, a1);
    }
    float2 f0 = unpk(a0), f1 = unpk(a1);
    float4 b4 = *(const float4*)&b[cb];
    float4 g4 = *(const float4*)&g[cb];
    float4 e4 = *(const float4*)&be[cb];
    float4 o;
    o.x = g4.x * (eluf(f0.x + b4.x) * BNI) + e4.x;
    o.y = g4.y * (eluf(f0.y + b4.y) * BNI) + e4.y;
    o.z = g4.z * (eluf(f1.x + b4.z) * BNI) + e4.z;
    o.w = g4.w * (eluf(f1.y + b4.w) * BNI) + e4.w;
    *(float4*)&g_ftsl[(row0 + r) * 64 + cb] = o;
}

// ============================================================================
// Kernel B (prep): gather + lift MLP + X0 conv. Writes g_X0, g_FCg.
// ============================================================================
#define SM_FLOATS 19744
#define SMEM_B    (SM_FLOATS * 4)

__global__ void __launch_bounds__(256, 2) prep_kernel(
    const float* __restrict__ rep_pts, const float* __restrict__ pts,
    const int*   __restrict__ pts_idx,
    const float* __restrict__ d1W, const float* __restrict__ d1b,
    const float* __restrict__ d1g, const float* __restrict__ d1be,
    const float* __restrict__ d2W, const float* __restrict__ d2b,
    const float* __restrict__ d2g, const float* __restrict__ d2be,
    const float* __restrict__ xcW, const float* __restrict__ xcb)
{
    extern __shared__ float sm[];
    float* PT    = sm;
    float* H     = sm + 384;     // [32][128] (E phase)
    float* FC    = sm + 4480;
    int*   SIDX  = (int*)(sm + 17280);
    float* SD1W  = sm + 17408; float* SD1B  = sm + 17504;
    float* SD1G  = sm + 17536; float* SD1BE = sm + 17568;
    float* SD2Wd = sm + 17600;                      // duplicated [c][64]
    float* SD2B  = sm + 19648; float* SD2G = sm + 19680;
    float* SD2BE = sm + 19712;

    const int t   = threadIdx.x;
    const int gp0 = blockIdx.x * TILEP;
    const int n   = gp0 >> 10;

    for (int u = t; u < 96; u += 256) SD1W[u] = d1W[u];
    for (int u = t; u < 1024; u += 256) {
        float w = d2W[u];
        SD2Wd[2 * u] = w; SD2Wd[2 * u + 1] = w;
    }
    if (t < 32) {
        SD1B[t] = d1b[t]; SD1G[t] = d1g[t]; SD1BE[t] = d1be[t];
        SD2B[t] = d2b[t]; SD2G[t] = d2g[t]; SD2BE[t] = d2be[t];
    }
    if (t < 128) SIDX[t] = pts_idx[(size_t)gp0 * 16 + t];
    __syncthreads();

    if (t < 128) {
        int i = t >> 4, k = t & 15;
        int gi = SIDX[t];
        const float* pp = pts + ((size_t)n * NUMPTS + gi) * 3;
        const float* rp = rep_pts + (size_t)(gp0 + i) * 3;
        PT[( 0 + k) * 8 + i] = pp[0] - rp[0];
        PT[(16 + k) * 8 + i] = pp[1] - rp[1];
        PT[(32 + k) * 8 + i] = pp[2] - rp[2];
    }
    {
        int row = t >> 1, half = t & 1;
        int gi = SIDX[row];
        const float4* src = (const float4*)(g_ftsl + ((size_t)n * NUMPTS + gi) * 64 + half * 32);
        float4* dst = (float4*)&FC[row * FCS + 32 + half * 32];
#pragma unroll
        for (int u = 0; u < 8; u++) dst[u] = src[u];
    }
    __syncthreads();

    // E1: dense1 (3 -> 32) into H[c][row]
    {
        const int row = t & 127, hc = t >> 7;
        const int i = row >> 4, k = row & 15;
        float px = PT[k * 8 + i];
        float py = PT[(16 + k) * 8 + i];
        float pz = PT[(32 + k) * 8 + i];
#pragma unroll
        for (int u = 0; u < 16; u++) {
            int c = hc * 16 + u;
            float v = fmaf(px, SD1W[c], fmaf(py, SD1W[32 + c],
                      fmaf(pz, SD1W[64 + c], SD1B[c])));
            H[c * 128 + row] = SD1G[c] * (eluf(v) * BNI) + SD1BE[c];
        }
    }
    __syncthreads();

    // E2: dense2 (32 -> 32), row-pair packed fma2 -> FC[:,0:32]
    {
        const int rp = t & 63, cg = t >> 6;
        const int row0 = 2 * rp, c0 = cg * 8;
        u64 acc[8];
#pragma unroll
        for (int u = 0; u < 8; u++) acc[u] = dup2(SD2B[c0 + u]);
#pragma unroll 4
        for (int c = 0; c < 32; c++) {
            u64 hv = *(const u64*)&H[c * 128 + row0];
            const ulonglong2* wd = (const ulonglong2*)&SD2Wd[c * 64 + 2 * c0];
            ulonglong2 w0 = wd[0], w1 = wd[1], w2 = wd[2], w3 = wd[3];
            acc[0] = fma2(hv, w0.x, acc[0]); acc[1] = fma2(hv, w0.y, acc[1]);
            acc[2] = fma2(hv, w1.x, acc[2]); acc[3] = fma2(hv, w1.y, acc[3]);
            acc[4] = fma2(hv, w2.x, acc[4]); acc[5] = fma2(hv, w2.y, acc[5]);
            acc[6] = fma2(hv, w3.x, acc[6]); acc[7] = fma2(hv, w3.y, acc[7]);
        }
#pragma unroll
        for (int u = 0; u < 8; u++) {
            int c = c0 + u;
            float2 f = unpk(acc[u]);
            FC[row0 * FCS + c]       = SD2G[c] * (eluf(f.x) * BNI) + SD2BE[c];
            FC[(row0 + 1) * FCS + c] = SD2G[c] * (eluf(f.y) * BNI) + SD2BE[c];
        }
    }
    __syncthreads();

    // Phase B: X0[q] = elu(sum_48 pls*xcW[q])
    {
        const int q = t;
        u64 acc[4] = {0ull, 0ull, 0ull, 0ull};
        const float4* w4p = (const float4*)(xcW + q * 48);
#pragma unroll 4
        for (int k4 = 0; k4 < 12; k4++) {
            float4 w = w4p[k4];
            float wv[4] = {w.x, w.y, w.z, w.w};
#pragma unroll
            for (int u = 0; u < 4; u++) {
                u64 wd = dup2(wv[u]);
                int k = k4 * 4 + u;
                ulonglong2 a0 = *(const ulonglong2*)&PT[k * 8];
                ulonglong2 a1 = *(const ulonglong2*)&PT[k * 8 + 4];
                acc[0] = fma2(a0.x, wd, acc[0]);
                acc[1] = fma2(a0.y, wd, acc[1]);
                acc[2] = fma2(a1.x, wd, acc[2]);
                acc[3] = fma2(a1.y, wd, acc[3]);
            }
        }
        float b = xcb[q];
        float2 f0 = unpk(acc[0]), f1 = unpk(acc[1]);
        float2 f2 = unpk(acc[2]), f3 = unpk(acc[3]);
        float x0v[8];
        x0v[0] = eluf(f0.x + b); x0v[1] = eluf(f0.y + b);
        x0v[2] = eluf(f1.x + b); x0v[3] = eluf(f1.y + b);
        x0v[4] = eluf(f2.x + b); x0v[5] = eluf(f2.y + b);
        x0v[6] = eluf(f3.x + b); x0v[7] = eluf(f3.y + b);
#pragma unroll
        for (int i = 0; i < 8; i++)
            g_X0[(size_t)(gp0 + i) * 256 + q] = x0v[i];
    }

    // store fts_cat compact [pt][16][96], vectorized
    for (int idx = t * 4; idx < 8 * 1536; idx += 1024) {
        int row = idx / 96, c = idx - row * 96;
        *(float4*)&g_FCg[(size_t)gp0 * 1536 + idx] =
            *(const float4*)&FC[row * FCS + c];
    }
}

// ============================================================================
// GEMM (TF32 tensor): C[M,256] = act(A[M,256] @ W[256,256] + bias)
// ============================================================================
template<bool ELU>
__global__ void __launch_bounds__(256, 2) gemm256_tf32(
    const float* __restrict__ A, const float* __restrict__ W,
    const float* __restrict__ bias, float* __restrict__ C)
{
    __shared__ u32 As[2][128][20];
    __shared__ u32 Bs[2][16][136];
    const int t  = threadIdx.x;
    const int m0 = blockIdx.y << 7;
    const int n0 = blockIdx.x << 7;
    const int wid = t >> 5, lane = t & 31;
    const int wm = wid >> 1, wn = wid & 1;
    const int g = lane >> 2, tg = lane & 3;

    float4 acc[2][8];
#pragma unroll
    for (int i = 0; i < 2; i++)
#pragma unroll
        for (int j = 0; j < 8; j++) acc[i][j] = make_float4(0.f, 0.f, 0.f, 0.f);

    const int ar = t >> 1, ak = (t & 1) * 8;
    const int bk = t >> 4, bn = (t & 15) * 8;
    const float* Arow = A + (size_t)(m0 + ar) * 256;

    float4 a0 = *(const float4*)&Arow[ak];
    float4 a1 = *(const float4*)&Arow[ak + 4];
    float4 b0 = *(const float4*)&W[(size_t)bk * 256 + n0 + bn];
    float4 b1 = *(const float4*)&W[(size_t)bk * 256 + n0 + bn + 4];

#pragma unroll 1
    for (int k0 = 0; k0 < 16; k0++) {
        const int buf = k0 & 1;
        {
            u32 av[8], bv[8];
            av[0] = tf32(a0.x); av[1] = tf32(a0.y);
            av[2] = tf32(a0.z); av[3] = tf32(a0.w);
            av[4] = tf32(a1.x); av[5] = tf32(a1.y);
            av[6] = tf32(a1.z); av[7] = tf32(a1.w);
            bv[0] = tf32(b0.x); bv[1] = tf32(b0.y);
            bv[2] = tf32(b0.z); bv[3] = tf32(b0.w);
            bv[4] = tf32(b1.x); bv[5] = tf32(b1.y);
            bv[6] = tf32(b1.z); bv[7] = tf32(b1.w);
            *(uint4*)&As[buf][ar][ak]     = *(uint4*)&av[0];
            *(uint4*)&As[buf][ar][ak + 4] = *(uint4*)&av[4];
            *(uint4*)&Bs[buf][bk][bn]     = *(uint4*)&bv[0];
            *(uint4*)&Bs[buf][bk][bn + 4] = *(uint4*)&bv[4];
        }
        __syncthreads();
        if (k0 < 15) {
            int kn = (k0 + 1) * 16;
            a0 = *(const float4*)&Arow[kn + ak];
            a1 = *(const float4*)&Arow[kn + ak + 4];
            b0 = *(const float4*)&W[(size_t)(kn + bk) * 256 + n0 + bn];
            b1 = *(const float4*)&W[(size_t)(kn + bk) * 256 + n0 + bn + 4];
        }
#pragma unroll
        for (int kk = 0; kk < 2; kk++) {
            const int kb = kk * 8;
            u32 af[2][4];
#pragma unroll
            for (int mi = 0; mi < 2; mi++) {
                int r = wm * 32 + mi * 16;
                af[mi][0] = As[buf][r + g][kb + tg];
                af[mi][1] = As[buf][r + g + 8][kb + tg];
                af[mi][2] = As[buf][r + g][kb + tg + 4];
                af[mi][3] = As[buf][r + g + 8][kb + tg + 4];
            }
#pragma unroll
            for (int nj = 0; nj < 8; nj++) {
                int cn = wn * 64 + nj * 8 + g;
                u32 bf0 = Bs[buf][kb + tg][cn];
                u32 bf1 = Bs[buf][kb + tg + 4][cn];
                mma8(acc[0][nj], af[0], bf0, bf1);
                mma8(acc[1][nj], af[1], bf0, bf1);
            }
        }
    }

#pragma unroll
    for (int nj = 0; nj < 8; nj++) {
        int col = n0 + wn * 64 + nj * 8 + tg * 2;
        float bv0 = __ldg(&bias[col]);
        float bv1 = __ldg(&bias[col + 1]);
#pragma unroll
        for (int mi = 0; mi < 2; mi++) {
            int row = m0 + wm * 32 + mi * 16 + g;
            float4 d = acc[mi][nj];
            float v0 = d.x + bv0, v1 = d.y + bv1;
            float v2 = d.z + bv0, v3 = d.w + bv1;
            if (ELU) { v0 = eluf(v0); v1 = eluf(v1); v2 = eluf(v2); v3 = eluf(v3); }
            float2 s0; s0.x = v0; s0.y = v1;
            float2 s1; s1.x = v2; s1.y = v3;
            *(float2*)&C[(size_t)row * 256 + col]       = s0;
            *(float2*)&C[(size_t)(row + 8) * 256 + col] = s1;
        }
    }
}

// ============================================================================
// GEMM-PW: out[M,128] = endg*(elu(DW[M,192] @ pwW[192,128] + pwb)*BNI)+endbe
// ============================================================================
__global__ void __launch_bounds__(256, 2) gemm_pw(
    const float* __restrict__ pwW, const float* __restrict__ pwb,
    const float* __restrict__ endg, const float* __restrict__ endbe,
    float* __restrict__ out)
{
    __shared__ float As[2][16][132];
    __shared__ float Bs[2][16][128];
    const int t  = threadIdx.x;
    const int m0 = blockIdx.x << 7;
    const int tx = t & 15, ty = t >> 4;

    u64 acc[4][8];
#pragma unroll
    for (int i = 0; i < 4; i++)
#pragma unroll
        for (int j = 0; j < 8; j++) acc[i][j] = 0ull;

    const int ar = t >> 1, ak = (t & 1) * 8;
    const int bk = t >> 4, bn = (t & 15) * 8;
    const float* Arow = g_DW + (size_t)(m0 + ar) * 192;

    float4 a0 = *(const float4*)&Arow[ak];
    float4 a1 = *(const float4*)&Arow[ak + 4];
    float4 b0 = *(const float4*)&pwW[(size_t)bk * 128 + bn];
    float4 b1 = *(const float4*)&pwW[(size_t)bk * 128 + bn + 4];

#pragma unroll 1
    for (int k0 = 0; k0 < 12; k0++) {
        const int buf = k0 & 1;
        As[buf][ak + 0][ar] = a0.x; As[buf][ak + 1][ar] = a0.y;
        As[buf][ak + 2][ar] = a0.z; As[buf][ak + 3][ar] = a0.w;
        As[buf][ak + 4][ar] = a1.x; As[buf][ak + 5][ar] = a1.y;
        As[buf][ak + 6][ar] = a1.z; As[buf][ak + 7][ar] = a1.w;
        *(float4*)&Bs[buf][bk][bn]     = b0;
        *(float4*)&Bs[buf][bk][bn + 4] = b1;
        __syncthreads();
        if (k0 < 11) {
            int kn = (k0 + 1) * 16;
            a0 = *(const float4*)&Arow[kn + ak];
            a1 = *(const float4*)&Arow[kn + ak + 4];
            b0 = *(const float4*)&pwW[(size_t)(kn + bk) * 128 + bn];
            b1 = *(const float4*)&pwW[(size_t)(kn + bk) * 128 + bn + 4];
        }
#pragma unroll
        for (int kk = 0; kk < 16; kk++) {
            ulonglong2 aa0 = *(const ulonglong2*)&As[buf][kk][ty * 8];
            ulonglong2 aa1 = *(const ulonglong2*)&As[buf][kk][ty * 8 + 4];
            u64 am[4] = {aa0.x, aa0.y, aa1.x, aa1.y};
            float4 bb0 = *(const float4*)&Bs[buf][kk][tx * 8];
            float4 bb1 = *(const float4*)&Bs[buf][kk][tx * 8 + 4];
            float bs[8] = {bb0.x, bb0.y, bb0.z, bb0.w,
                           bb1.x, bb1.y, bb1.z, bb1.w};
#pragma unroll
            for (int nj = 0; nj < 8; nj++) {
                u64 bd = dup2(bs[nj]);
#pragma unroll
                for (int mi = 0; mi < 4; mi++)
                    acc[mi][nj] = fma2(am[mi], bd, acc[mi][nj]);
            }
        }
    }

#pragma unroll
    for (int nj = 0; nj < 8; nj++) {
        int nn = tx * 8 + nj;
        float bv = __ldg(&pwb[nn]);
        float gv = __ldg(&endg[nn]);
        float ev = __ldg(&endbe[nn]);
#pragma unroll
        for (int mi = 0; mi < 4; mi++) {
            float2 f = unpk(acc[mi][nj]);
            float v0 = gv * (eluf(f.x + bv) * BNI) + ev;
            float v1 = gv * (eluf(f.y + bv) * BNI) + ev;
            size_t m = (size_t)(m0 + ty * 8 + 2 * mi);
            out[m * 128 + nn]       = v0;
            out[(m + 1) * 128 + nn] = v1;
        }
    }
}

// ============================================================================
// Kernel E (epilogue): X2 + fts_cat -> F (k-paired fma2), G1 (paired dw) -> g_DW
// smem: XA [8][256] @0 | FC [8][16][FCS] @2048 | SDW [16][96] u64 pairs @14848
// total 17920 floats = 71680 B
// ============================================================================
#define EPI_SM (17920 * 4)

__global__ void __launch_bounds__(256, 2) epi_kernel(
    const float* __restrict__ dwW, const float* __restrict__ dwb)
{
    extern __shared__ float sm[];
    float* XA  = sm;           // [8][256]  X2
    float* FC  = sm + 2048;    // [8][16][FCS]
    float* SDW = sm + 14848;   // [k][c] interleaved (m0,m1) pairs: 3072 floats

    const int t   = threadIdx.x;
    const int gp0 = blockIdx.x * TILEP;

    {
        const float4* src = (const float4*)(g_X2 + (size_t)gp0 * 256);
        float4* dst = (float4*)XA;
        dst[t] = src[t];
        dst[t + 256] = src[t + 256];
    }
    for (int idx = t * 4; idx < 8 * 1536; idx += 1024) {
        int row = idx / 96, c = idx - row * 96;
        *(float4*)&FC[row * FCS + c] =
            *(const float4*)&g_FCg[(size_t)gp0 * 1536 + idx];
    }
    // dwW staged interleaved: SDW[(k*96+c)*2 + m] = dwW[c*32 + m*16 + k]
    for (int idx = t; idx < 1536; idx += 256) {
        int k = idx / 96, c = idx - k * 96;
        float2 w;
        w.x = dwW[c * 32 + k];
        w.y = dwW[c * 32 + 16 + k];
        *(float2*)&SDW[idx * 2] = w;
    }
    __syncthreads();

    const int i = t >> 5, lane = t & 31;

    // Phase F: fts_X = X2(16x16) @ FC(16x96), k-paired fma2, in place
    {
        u64 fp[3][8];
#pragma unroll
        for (int u = 0; u < 3; u++) {
            int c = lane + 32 * u;
#pragma unroll
            for (int kk = 0; kk < 8; kk++) {
                float lo = FC[(i * 16 + 2 * kk) * FCS + c];
                float hi = FC[(i * 16 + 2 * kk + 1) * FCS + c];
                fp[u][kk] = pk2(lo, hi);
            }
        }
#pragma unroll
        for (int r = 0; r < 16; r++) {
            const ulonglong2* xr = (const ulonglong2*)&XA[i * 256 + r * 16];
            ulonglong2 x0 = xr[0], x1 = xr[1], x2 = xr[2], x3 = xr[3];
            u64 xp[8] = {x0.x, x0.y, x1.x, x1.y, x2.x, x2.y, x3.x, x3.y};
#pragma unroll
            for (int u = 0; u < 3; u++) {
                u64 acc = 0ull;
#pragma unroll
                for (int kk = 0; kk < 8; kk++)
                    acc = fma2(xp[kk], fp[u][kk], acc);
                float2 h = unpk(acc);
                FC[(i * 16 + r) * FCS + lane + 32 * u] = h.x + h.y;
            }
        }
    }
    __syncthreads();

    // Phase G1: depthwise, m-paired fma2 -> g_DW
    {
#pragma unroll
        for (int u = 0; u < 3; u++) {
            int c = lane + 32 * u;
            u64 acc = *(const u64*)&dwb[2 * c];
#pragma unroll
            for (int k = 0; k < 16; k++) {
                u64 fd = dup2(FC[(i * 16 + k) * FCS + c]);
                u64 wd = *(const u64*)&SDW[(k * 96 + c) * 2];
                acc = fma2(fd, wd, acc);
            }
            *(u64*)&g_DW[(size_t)(gp0 + i) * 192 + 2 * c] = acc;
        }
    }
}

// ============================================================================
extern "C" void kernel_launch(void* const* d_in, const int* in_sizes, int n_in,
                              void* d_out, int out_size)
{
    const float* rep_pts = (const float*)d_in[0];
    const float* pts     = (const float*)d_in[1];
    const float* fts     = (const float*)d_in[2];
    const int*   pts_idx = (const int*)d_in[3];
    const float* d0W  = (const float*)d_in[4];
    const float* d0b  = (const float*)d_in[5];
    const float* d0g  = (const float*)d_in[6];
    const float* d0be = (const float*)d_in[7];
    const float* d1W  = (const float*)d_in[8];
    const float* d1b  = (const float*)d_in[9];
    const float* d1g  = (const float*)d_in[10];
    const float* d1be = (const float*)d_in[11];
    const float* d2W  = (const float*)d_in[12];
    const float* d2b  = (const float*)d_in[13];
    const float* d2g  = (const float*)d_in[14];
    const float* d2be = (const float*)d_in[15];
    const float* xcW  = (const float*)d_in[16];
    const float* xcb  = (const float*)d_in[17];
    const float* xd1W = (const float*)d_in[18];
    const float* xd1b = (const float*)d_in[19];
    const float* xd2W = (const float*)d_in[20];
    const float* xd2b = (const float*)d_in[21];
    const float* dwW  = (const float*)d_in[22];
    const float* dwb  = (const float*)d_in[23];
    const float* pwW  = (const float*)d_in[24];
    const float* pwb  = (const float*)d_in[25];
    const float* endg = (const float*)d_in[26];
    const float* endbe= (const float*)d_in[27];
    float* out = (float*)d_out;

    float *pX0, *pX1, *pX2;
    cudaGetSymbolAddress((void**)&pX0, g_X0);
    cudaGetSymbolAddress((void**)&pX1, g_X1);
    cudaGetSymbolAddress((void**)&pX2, g_X2);

    dense0_kernel<<<4096, 256>>>(fts, d0W, d0b, d0g, d0be);

    cudaFuncSetAttribute(prep_kernel,
                         cudaFuncAttributeMaxDynamicSharedMemorySize, SMEM_B);
    prep_kernel<<<32768 / TILEP, 256, SMEM_B>>>(
        rep_pts, pts, pts_idx,
        d1W, d1b, d1g, d1be, d2W, d2b, d2g, d2be, xcW, xcb);

    dim3 ggrid(2, 256);
    gemm256_tf32<true><<<ggrid, 256>>>(pX0, xd1W, xd1b, pX1);
    gemm256_tf32<false><<<ggrid, 256>>>(pX1, xd2W, xd2b, pX2);

    cudaFuncSetAttribute(epi_kernel,
                         cudaFuncAttributeMaxDynamicSharedMemorySize, EPI_SM);
    epi_kernel<<<32768 / TILEP, 256, EPI_SM>>>(dwW, dwb);

    gemm_pw<<<256, 256>>>(pwW, pwb, endg, endbe, out);
}

// round 11
// speedup vs baseline: 1.6535x; 1.1338x over previous
#include <cuda_runtime.h>
#include <math.h>

typedef unsigned long long u64;
typedef unsigned int u32;

// ---- problem dims ----
#define NB      32
#define NUMPTS  2048
#define PN      1024
#define TILEP   8
#define FCS     100
#define BNI     0.9999950000374996f

// scratch
__device__ float g_ftsl[NB * NUMPTS * 64];
__device__ float g_PLS[(size_t)32768 * 48];
__device__ float g_X0 [32768 * 256];
__device__ float g_X1 [32768 * 256];
__device__ float g_X2 [32768 * 256];
__device__ float g_DW [(size_t)32768 * 192];
__device__ float g_FCg[(size_t)32768 * 1536];

__device__ __forceinline__ float eluf(float x) {
    return x > 0.0f ? x : expm1f(x);
}
__device__ __forceinline__ u64 fma2(u64 a, u64 b, u64 c) {
    u64 d; asm("fma.rn.f32x2 %0,%1,%2,%3;" : "=l"(d) : "l"(a), "l"(b), "l"(c)); return d;
}
__device__ __forceinline__ u64 dup2(float x) {
    u64 d; asm("mov.b64 %0,{%1,%1};" : "=l"(d) : "f"(x)); return d;
}
__device__ __forceinline__ u64 pk2(float lo, float hi) {
    u64 d; asm("mov.b64 %0,{%1,%2};" : "=l"(d) : "f"(lo), "f"(hi)); return d;
}
__device__ __forceinline__ float2 unpk(u64 v) {
    float2 r; asm("mov.b64 {%0,%1},%2;" : "=f"(r.x), "=f"(r.y) : "l"(v)); return r;
}
__device__ __forceinline__ u32 tf32(float f) {
    u32 o; asm("cvt.rna.tf32.f32 %0, %1;" : "=r"(o) : "f"(f)); return o;
}
__device__ __forceinline__ void mma8(float4& d, const u32* a, u32 b0, u32 b1) {
    asm("mma.sync.aligned.m16n8k8.row.col.f32.tf32.tf32.f32 "
        "{%0,%1,%2,%3}, {%4,%5,%6,%7}, {%8,%9}, {%0,%1,%2,%3};"
        : "+f"(d.x), "+f"(d.y), "+f"(d.z), "+f"(d.w)
        : "r"(a[0]), "r"(a[1]), "r"(a[2]), "r"(a[3]), "r"(b0), "r"(b1));
}

// ============================================================================
// Kernel A: dense0 -> g_ftsl
// ============================================================================
__global__ void __launch_bounds__(256) dense0_kernel(
    const float* __restrict__ fts, const float* __restrict__ W,
    const float* __restrict__ b,   const float* __restrict__ g,
    const float* __restrict__ be)
{
    __shared__ float Ws[64 * 64];
    __shared__ float xs[16 * 64];
    const int t = threadIdx.x;
    const size_t row0 = (size_t)blockIdx.x * 16;

#pragma unroll
    for (int u = 0; u < 16; u++) Ws[t + 256 * u] = W[t + 256 * u];
    ((float4*)xs)[t] = ((const float4*)(fts + row0 * 64))[t];
    __syncthreads();

    const int r  = t >> 4;
    const int cb = (t & 15) * 4;
    u64 a0 = 0ull, a1 = 0ull;
#pragma unroll 8
    for (int k = 0; k < 64; k++) {
        u64 xd = dup2(xs[r * 64 + k]);
        ulonglong2 w = *(const ulonglong2*)&Ws[k * 64 + cb];
        a0 = fma2(xd, w.x, a0);
        a1 = fma2(xd, w.y, a1);
    }
    float2 f0 = unpk(a0), f1 = unpk(a1);
    float4 b4 = *(const float4*)&b[cb];
    float4 g4 = *(const float4*)&g[cb];
    float4 e4 = *(const float4*)&be[cb];
    float4 o;
    o.x = g4.x * (eluf(f0.x + b4.x) * BNI) + e4.x;
    o.y = g4.y * (eluf(f0.y + b4.y) * BNI) + e4.y;
    o.z = g4.z * (eluf(f1.x + b4.z) * BNI) + e4.z;
    o.w = g4.w * (eluf(f1.y + b4.w) * BNI) + e4.w;
    *(float4*)&g_ftsl[(row0 + r) * 64 + cb] = o;
}

// ============================================================================
// Kernel B (prep): gather + lift MLP. Writes g_PLS, g_FCg.
// ============================================================================
#define SM_FLOATS 19744
#define SMEM_B    (SM_FLOATS * 4)

__global__ void __launch_bounds__(256, 2) prep_kernel(
    const float* __restrict__ rep_pts, const float* __restrict__ pts,
    const int*   __restrict__ pts_idx,
    const float* __restrict__ d1W, const float* __restrict__ d1b,
    const float* __restrict__ d1g, const float* __restrict__ d1be,
    const float* __restrict__ d2W, const float* __restrict__ d2b,
    const float* __restrict__ d2g, const float* __restrict__ d2be)
{
    extern __shared__ float sm[];
    float* PT    = sm;           // [48][8]
    float* H     = sm + 384;     // [32][128] (E phase)
    float* FC    = sm + 4480;
    int*   SIDX  = (int*)(sm + 17280);
    float* SD1W  = sm + 17408; float* SD1B  = sm + 17504;
    float* SD1G  = sm + 17536; float* SD1BE = sm + 17568;
    float* SD2Wd = sm + 17600;                      // duplicated [c][64]
    float* SD2B  = sm + 19648; float* SD2G = sm + 19680;
    float* SD2BE = sm + 19712;

    const int t   = threadIdx.x;
    const int gp0 = blockIdx.x * TILEP;
    const int n   = gp0 >> 10;

    for (int u = t; u < 96; u += 256) SD1W[u] = d1W[u];
    for (int u = t; u < 1024; u += 256) {
        float w = d2W[u];
        SD2Wd[2 * u] = w; SD2Wd[2 * u + 1] = w;
    }
    if (t < 32) {
        SD1B[t] = d1b[t]; SD1G[t] = d1g[t]; SD1BE[t] = d1be[t];
        SD2B[t] = d2b[t]; SD2G[t] = d2g[t]; SD2BE[t] = d2be[t];
    }
    if (t < 128) SIDX[t] = pts_idx[(size_t)gp0 * 16 + t];
    __syncthreads();

    if (t < 128) {
        int i = t >> 4, k = t & 15;
        int gi = SIDX[t];
        const float* pp = pts + ((size_t)n * NUMPTS + gi) * 3;
        const float* rp = rep_pts + (size_t)(gp0 + i) * 3;
        PT[( 0 + k) * 8 + i] = pp[0] - rp[0];
        PT[(16 + k) * 8 + i] = pp[1] - rp[1];
        PT[(32 + k) * 8 + i] = pp[2] - rp[2];
    }
    {
        int row = t >> 1, half = t & 1;
        int gi = SIDX[row];
        const float4* src = (const float4*)(g_ftsl + ((size_t)n * NUMPTS + gi) * 64 + half * 32);
        float4* dst = (float4*)&FC[row * FCS + 32 + half * 32];
#pragma unroll
        for (int u = 0; u < 8; u++) dst[u] = src[u];
    }
    __syncthreads();

    // E1: dense1 (3 -> 32) into H[c][row]
    {
        const int row = t & 127, hc = t >> 7;
        const int i = row >> 4, k = row & 15;
        float px = PT[k * 8 + i];
        float py = PT[(16 + k) * 8 + i];
        float pz = PT[(32 + k) * 8 + i];
#pragma unroll
        for (int u = 0; u < 16; u++) {
            int c = hc * 16 + u;
            float v = fmaf(px, SD1W[c], fmaf(py, SD1W[32 + c],
                      fmaf(pz, SD1W[64 + c], SD1B[c])));
            H[c * 128 + row] = SD1G[c] * (eluf(v) * BNI) + SD1BE[c];
        }
    }
    __syncthreads();

    // E2: dense2 (32 -> 32), row-pair packed fma2 -> FC[:,0:32]
    {
        const int rp = t & 63, cg = t >> 6;
        const int row0 = 2 * rp, c0 = cg * 8;
        u64 acc[8];
#pragma unroll
        for (int u = 0; u < 8; u++) acc[u] = dup2(SD2B[c0 + u]);
#pragma unroll 4
        for (int c = 0; c < 32; c++) {
            u64 hv = *(const u64*)&H[c * 128 + row0];
            const ulonglong2* wd = (const ulonglong2*)&SD2Wd[c * 64 + 2 * c0];
            ulonglong2 w0 = wd[0], w1 = wd[1], w2 = wd[2], w3 = wd[3];
            acc[0] = fma2(hv, w0.x, acc[0]); acc[1] = fma2(hv, w0.y, acc[1]);
            acc[2] = fma2(hv, w1.x, acc[2]); acc[3] = fma2(hv, w1.y, acc[3]);
            acc[4] = fma2(hv, w2.x, acc[4]); acc[5] = fma2(hv, w2.y, acc[5]);
            acc[6] = fma2(hv, w3.x, acc[6]); acc[7] = fma2(hv, w3.y, acc[7]);
        }
#pragma unroll
        for (int u = 0; u < 8; u++) {
            int c = c0 + u;
            float2 f = unpk(acc[u]);
            FC[row0 * FCS + c]       = SD2G[c] * (eluf(f.x) * BNI) + SD2BE[c];
            FC[(row0 + 1) * FCS + c] = SD2G[c] * (eluf(f.y) * BNI) + SD2BE[c];
        }
    }
    __syncthreads();

    // store local coords [pt][48] (layout j = d*16+k matches xcW rows)
    for (int idx = t; idx < 8 * 48; idx += 256) {
        int i = idx / 48, j = idx - i * 48;
        g_PLS[(size_t)(gp0 + i) * 48 + j] = PT[j * 8 + i];
    }
    // store fts_cat compact [pt][16][96], vectorized
    for (int idx = t * 4; idx < 8 * 1536; idx += 1024) {
        int row = idx / 96, c = idx - row * 96;
        *(float4*)&g_FCg[(size_t)gp0 * 1536 + idx] =
            *(const float4*)&FC[row * FCS + c];
    }
}

// ============================================================================
// GEMM-X0 (TF32): X0[M,256] = elu(PLS[M,48] @ xcW^T[48,256] + xcb)
// single K pass (6 chunks of 8), 128x128 tile, same warp layout as gemm256.
// ============================================================================
#define X0_SMEM ((128 * 52 + 48 * 136) * 4)

__global__ void __launch_bounds__(256, 2) gemmX0_tf32(
    const float* __restrict__ xcW, const float* __restrict__ xcb,
    float* __restrict__ X0)
{
    extern __shared__ u32 smx[];
    u32 (*As)[52]  = (u32(*)[52])smx;               // [128][52]
    u32 (*Bs)[136] = (u32(*)[136])(smx + 128 * 52); // [48][136]

    const int t  = threadIdx.x;
    const int m0 = blockIdx.y << 7;
    const int n0 = blockIdx.x << 7;
    const int wid = t >> 5, lane = t & 31;
    const int wm = wid >> 1, wn = wid & 1;
    const int g = lane >> 2, tg = lane & 3;

    // load A: 128 rows x 48, each thread half a row (24 floats)
    {
        const int ar = t >> 1, ah = (t & 1) * 24;
        const float* Ar = g_PLS + (size_t)(m0 + ar) * 48 + ah;
#pragma unroll
        for (int v = 0; v < 6; v++) {
            float4 a = *(const float4*)&Ar[v * 4];
            u32* ap = &As[ar][ah + v * 4];
            ap[0] = tf32(a.x); ap[1] = tf32(a.y);
            ap[2] = tf32(a.z); ap[3] = tf32(a.w);
        }
    }
    // load B transposed: Bs[k][n] = xcW[(n0+n)*48 + k]
    {
        const int q = t >> 1, kh = (t & 1) * 24;
        const float* Wr = xcW + (size_t)(n0 + q) * 48 + kh;
#pragma unroll
        for (int v = 0; v < 6; v++) {
            float4 w = *(const float4*)&Wr[v * 4];
            Bs[kh + v * 4 + 0][q] = tf32(w.x);
            Bs[kh + v * 4 + 1][q] = tf32(w.y);
            Bs[kh + v * 4 + 2][q] = tf32(w.z);
            Bs[kh + v * 4 + 3][q] = tf32(w.w);
        }
    }
    __syncthreads();

    float4 acc[2][8];
#pragma unroll
    for (int i = 0; i < 2; i++)
#pragma unroll
        for (int j = 0; j < 8; j++) acc[i][j] = make_float4(0.f, 0.f, 0.f, 0.f);

#pragma unroll
    for (int kc = 0; kc < 6; kc++) {
        const int kb = kc * 8;
        u32 af[2][4];
#pragma unroll
        for (int mi = 0; mi < 2; mi++) {
            int r = wm * 32 + mi * 16;
            af[mi][0] = As[r + g][kb + tg];
            af[mi][1] = As[r + g + 8][kb + tg];
            af[mi][2] = As[r + g][kb + tg + 4];
            af[mi][3] = As[r + g + 8][kb + tg + 4];
        }
#pragma unroll
        for (int nj = 0; nj < 8; nj++) {
            int cn = wn * 64 + nj * 8 + g;
            u32 bf0 = Bs[kb + tg][cn];
            u32 bf1 = Bs[kb + tg + 4][cn];
            mma8(acc[0][nj], af[0], bf0, bf1);
            mma8(acc[1][nj], af[1], bf0, bf1);
        }
    }

#pragma unroll
    for (int nj = 0; nj < 8; nj++) {
        int col = n0 + wn * 64 + nj * 8 + tg * 2;
        float bv0 = __ldg(&xcb[col]);
        float bv1 = __ldg(&xcb[col + 1]);
#pragma unroll
        for (int mi = 0; mi < 2; mi++) {
            int row = m0 + wm * 32 + mi * 16 + g;
            float4 d = acc[mi][nj];
            float2 s0, s1;
            s0.x = eluf(d.x + bv0); s0.y = eluf(d.y + bv1);
            s1.x = eluf(d.z + bv0); s1.y = eluf(d.w + bv1);
            *(float2*)&X0[(size_t)row * 256 + col]       = s0;
            *(float2*)&X0[(size_t)(row + 8) * 256 + col] = s1;
        }
    }
}

// ============================================================================
// GEMM (TF32 tensor): C[M,256] = act(A[M,256] @ W[256,256] + bias)
// ============================================================================
template<bool ELU>
__global__ void __launch_bounds__(256, 2) gemm256_tf32(
    const float* __restrict__ A, const float* __restrict__ W,
    const float* __restrict__ bias, float* __restrict__ C)
{
    __shared__ u32 As[2][128][20];
    __shared__ u32 Bs[2][16][136];
    const int t  = threadIdx.x;
    const int m0 = blockIdx.y << 7;
    const int n0 = blockIdx.x << 7;
    const int wid = t >> 5, lane = t & 31;
    const int wm = wid >> 1, wn = wid & 1;
    const int g = lane >> 2, tg = lane & 3;

    float4 acc[2][8];
#pragma unroll
    for (int i = 0; i < 2; i++)
#pragma unroll
        for (int j = 0; j < 8; j++) acc[i][j] = make_float4(0.f, 0.f, 0.f, 0.f);

    const int ar = t >> 1, ak = (t & 1) * 8;
    const int bk = t >> 4, bn = (t & 15) * 8;
    const float* Arow = A + (size_t)(m0 + ar) * 256;

    float4 a0 = *(const float4*)&Arow[ak];
    float4 a1 = *(const float4*)&Arow[ak + 4];
    float4 b0 = *(const float4*)&W[(size_t)bk * 256 + n0 + bn];
    float4 b1 = *(const float4*)&W[(size_t)bk * 256 + n0 + bn + 4];

#pragma unroll 1
    for (int k0 = 0; k0 < 16; k0++) {
        const int buf = k0 & 1;
        {
            u32 av[8], bv[8];
            av[0] = tf32(a0.x); av[1] = tf32(a0.y);
            av[2] = tf32(a0.z); av[3] = tf32(a0.w);
            av[4] = tf32(a1.x); av[5] = tf32(a1.y);
            av[6] = tf32(a1.z); av[7] = tf32(a1.w);
            bv[0] = tf32(b0.x); bv[1] = tf32(b0.y);
            bv[2] = tf32(b0.z); bv[3] = tf32(b0.w);
            bv[4] = tf32(b1.x); bv[5] = tf32(b1.y);
            bv[6] = tf32(b1.z); bv[7] = tf32(b1.w);
            *(uint4*)&As[buf][ar][ak]     = *(uint4*)&av[0];
            *(uint4*)&As[buf][ar][ak + 4] = *(uint4*)&av[4];
            *(uint4*)&Bs[buf][bk][bn]     = *(uint4*)&bv[0];
            *(uint4*)&Bs[buf][bk][bn + 4] = *(uint4*)&bv[4];
        }
        __syncthreads();
        if (k0 < 15) {
            int kn = (k0 + 1) * 16;
            a0 = *(const float4*)&Arow[kn + ak];
            a1 = *(const float4*)&Arow[kn + ak + 4];
            b0 = *(const float4*)&W[(size_t)(kn + bk) * 256 + n0 + bn];
            b1 = *(const float4*)&W[(size_t)(kn + bk) * 256 + n0 + bn + 4];
        }
#pragma unroll
        for (int kk = 0; kk < 2; kk++) {
            const int kb = kk * 8;
            u32 af[2][4];
#pragma unroll
            for (int mi = 0; mi < 2; mi++) {
                int r = wm * 32 + mi * 16;
                af[mi][0] = As[buf][r + g][kb + tg];
                af[mi][1] = As[buf][r + g + 8][kb + tg];
                af[mi][2] = As[buf][r + g][kb + tg + 4];
                af[mi][3] = As[buf][r + g + 8][kb + tg + 4];
            }
#pragma unroll
            for (int nj = 0; nj < 8; nj++) {
                int cn = wn * 64 + nj * 8 + g;
                u32 bf0 = Bs[buf][kb + tg][cn];
                u32 bf1 = Bs[buf][kb + tg + 4][cn];
                mma8(acc[0][nj], af[0], bf0, bf1);
                mma8(acc[1][nj], af[1], bf0, bf1);
            }
        }
    }

#pragma unroll
    for (int nj = 0; nj < 8; nj++) {
        int col = n0 + wn * 64 + nj * 8 + tg * 2;
        float bv0 = __ldg(&bias[col]);
        float bv1 = __ldg(&bias[col + 1]);
#pragma unroll
        for (int mi = 0; mi < 2; mi++) {
            int row = m0 + wm * 32 + mi * 16 + g;
            float4 d = acc[mi][nj];
            float v0 = d.x + bv0, v1 = d.y + bv1;
            float v2 = d.z + bv0, v3 = d.w + bv1;
            if (ELU) { v0 = eluf(v0); v1 = eluf(v1); v2 = eluf(v2); v3 = eluf(v3); }
            float2 s0; s0.x = v0; s0.y = v1;
            float2 s1; s1.x = v2; s1.y = v3;
            *(float2*)&C[(size_t)row * 256 + col]       = s0;
            *(float2*)&C[(size_t)(row + 8) * 256 + col] = s1;
        }
    }
}

// ============================================================================
// GEMM-PW (TF32): out[M,128] = endg*(elu(DW[M,192]@pwW[192,128]+pwb)*BNI)+endbe
// ============================================================================
__global__ void __launch_bounds__(256, 2) gemm_pw_tf32(
    const float* __restrict__ pwW, const float* __restrict__ pwb,
    const float* __restrict__ endg, const float* __restrict__ endbe,
    float* __restrict__ out)
{
    __shared__ u32 As[2][128][20];
    __shared__ u32 Bs[2][16][136];
    const int t  = threadIdx.x;
    const int m0 = blockIdx.x << 7;
    const int wid = t >> 5, lane = t & 31;
    const int wm = wid >> 1, wn = wid & 1;
    const int g = lane >> 2, tg = lane & 3;

    float4 acc[2][8];
#pragma unroll
    for (int i = 0; i < 2; i++)
#pragma unroll
        for (int j = 0; j < 8; j++) acc[i][j] = make_float4(0.f, 0.f, 0.f, 0.f);

    const int ar = t >> 1, ak = (t & 1) * 8;
    const int bk = t >> 4, bn = (t & 15) * 8;
    const float* Arow = g_DW + (size_t)(m0 + ar) * 192;

    float4 a0 = *(const float4*)&Arow[ak];
    float4 a1 = *(const float4*)&Arow[ak + 4];
    float4 b0 = *(const float4*)&pwW[(size_t)bk * 128 + bn];
    float4 b1 = *(const float4*)&pwW[(size_t)bk * 128 + bn + 4];

#pragma unroll 1
    for (int k0 = 0; k0 < 12; k0++) {
        const int buf = k0 & 1;
        {
            u32 av[8], bv[8];
            av[0] = tf32(a0.x); av[1] = tf32(a0.y);
            av[2] = tf32(a0.z); av[3] = tf32(a0.w);
            av[4] = tf32(a1.x); av[5] = tf32(a1.y);
            av[6] = tf32(a1.z); av[7] = tf32(a1.w);
            bv[0] = tf32(b0.x); bv[1] = tf32(b0.y);
            bv[2] = tf32(b0.z); bv[3] = tf32(b0.w);
            bv[4] = tf32(b1.x); bv[5] = tf32(b1.y);
            bv[6] = tf32(b1.z); bv[7] = tf32(b1.w);
            *(uint4*)&As[buf][ar][ak]     = *(uint4*)&av[0];
            *(uint4*)&As[buf][ar][ak + 4] = *(uint4*)&av[4];
            *(uint4*)&Bs[buf][bk][bn]     = *(uint4*)&bv[0];
            *(uint4*)&Bs[buf][bk][bn + 4] = *(uint4*)&bv[4];
        }
        __syncthreads();
        if (k0 < 11) {
            int kn = (k0 + 1) * 16;
            a0 = *(const float4*)&Arow[kn + ak];
            a1 = *(const float4*)&Arow[kn + ak + 4];
            b0 = *(const float4*)&pwW[(size_t)(kn + bk) * 128 + bn];
            b1 = *(const float4*)&pwW[(size_t)(kn + bk) * 128 + bn + 4];
        }
#pragma unroll
        for (int kk = 0; kk < 2; kk++) {
            const int kb = kk * 8;
            u32 af[2][4];
#pragma unroll
            for (int mi = 0; mi < 2; mi++) {
                int r = wm * 32 + mi * 16;
                af[mi][0] = As[buf][r + g][kb + tg];
                af[mi][1] = As[buf][r + g + 8][kb + tg];
                af[mi][2] = As[buf][r + g][kb + tg + 4];
                af[mi][3] = As[buf][r + g + 8][kb + tg + 4];
            }
#pragma unroll
            for (int nj = 0; nj < 8; nj++) {
                int cn = wn * 64 + nj * 8 + g;
                u32 bf0 = Bs[buf][kb + tg][cn];
                u32 bf1 = Bs[buf][kb + tg + 4][cn];
                mma8(acc[0][nj], af[0], bf0, bf1);
                mma8(acc[1][nj], af[1], bf0, bf1);
            }
        }
    }

#pragma unroll
    for (int nj = 0; nj < 8; nj++) {
        int col = wn * 64 + nj * 8 + tg * 2;
        float bv0 = __ldg(&pwb[col]),   bv1 = __ldg(&pwb[col + 1]);
        float gv0 = __ldg(&endg[col]),  gv1 = __ldg(&endg[col + 1]);
        float ev0 = __ldg(&endbe[col]), ev1 = __ldg(&endbe[col + 1]);
#pragma unroll
        for (int mi = 0; mi < 2; mi++) {
            int row = m0 + wm * 32 + mi * 16 + g;
            float4 d = acc[mi][nj];
            float2 s0, s1;
            s0.x = gv0 * (eluf(d.x + bv0) * BNI) + ev0;
            s0.y = gv1 * (eluf(d.y + bv1) * BNI) + ev1;
            s1.x = gv0 * (eluf(d.z + bv0) * BNI) + ev0;
            s1.y = gv1 * (eluf(d.w + bv1) * BNI) + ev1;
            *(float2*)&out[(size_t)row * 128 + col]       = s0;
            *(float2*)&out[(size_t)(row + 8) * 128 + col] = s1;
        }
    }
}

// ============================================================================
// Kernel E (epilogue): X2 + fts_cat -> F, G1 -> g_DW
// ============================================================================
#define EPI_SM (17920 * 4)

__global__ void __launch_bounds__(256, 2) epi_kernel(
    const float* __restrict__ dwW, const float* __restrict__ dwb)
{
    extern __shared__ float sm[];
    float* XA  = sm;           // [8][256]  X2
    float* FC  = sm + 2048;    // [8][16][FCS]
    float* SDW = sm + 14848;   // [k][c] interleaved (m0,m1) pairs

    const int t   = threadIdx.x;
    const int gp0 = blockIdx.x * TILEP;

    {
        const float4* src = (const float4*)(g_X2 + (size_t)gp0 * 256);
        float4* dst = (float4*)XA;
        dst[t] = src[t];
        dst[t + 256] = src[t + 256];
    }
    for (int idx = t * 4; idx < 8 * 1536; idx += 1024) {
        int row = idx / 96, c = idx - row * 96;
        *(float4*)&FC[row * FCS + c] =
            *(const float4*)&g_FCg[(size_t)gp0 * 1536 + idx];
    }
    for (int idx = t; idx < 1536; idx += 256) {
        int k = idx / 96, c = idx - k * 96;
        float2 w;
        w.x = dwW[c * 32 + k];
        w.y = dwW[c * 32 + 16 + k];
        *(float2*)&SDW[idx * 2] = w;
    }
    __syncthreads();

    const int i = t >> 5, lane = t & 31;

    // Phase F: fts_X = X2(16x16) @ FC(16x96), k-paired fma2, in place
    {
        u64 fp[3][8];
#pragma unroll
        for (int u = 0; u < 3; u++) {
            int c = lane + 32 * u;
#pragma unroll
            for (int kk = 0; kk < 8; kk++) {
                float lo = FC[(i * 16 + 2 * kk) * FCS + c];
                float hi = FC[(i * 16 + 2 * kk + 1) * FCS + c];
                fp[u][kk] = pk2(lo, hi);
            }
        }
#pragma unroll
        for (int r = 0; r < 16; r++) {
            const ulonglong2* xr = (const ulonglong2*)&XA[i * 256 + r * 16];
            ulonglong2 x0 = xr[0], x1 = xr[1], x2 = xr[2], x3 = xr[3];
            u64 xp[8] = {x0.x, x0.y, x1.x, x1.y, x2.x, x2.y, x3.x, x3.y};
#pragma unroll
            for (int u = 0; u < 3; u++) {
                u64 acc = 0ull;
#pragma unroll
                for (int kk = 0; kk < 8; kk++)
                    acc = fma2(xp[kk], fp[u][kk], acc);
                float2 h = unpk(acc);
                FC[(i * 16 + r) * FCS + lane + 32 * u] = h.x + h.y;
            }
        }
    }
    __syncthreads();

    // Phase G1: depthwise, m-paired fma2 -> g_DW
    {
#pragma unroll
        for (int u = 0; u < 3; u++) {
            int c = lane + 32 * u;
            u64 acc = *(const u64*)&dwb[2 * c];
#pragma unroll
            for (int k = 0; k < 16; k++) {
                u64 fd = dup2(FC[(i * 16 + k) * FCS + c]);
                u64 wd = *(const u64*)&SDW[(k * 96 + c) * 2];
                acc = fma2(fd, wd, acc);
            }
            *(u64*)&g_DW[(size_t)(gp0 + i) * 192 + 2 * c] = acc;
        }
    }
}

// ============================================================================
extern "C" void kernel_launch(void* const* d_in, const int* in_sizes, int n_in,
                              void* d_out, int out_size)
{
    const float* rep_pts = (const float*)d_in[0];
    const float* pts     = (const float*)d_in[1];
    const float* fts     = (const float*)d_in[2];
    const int*   pts_idx = (const int*)d_in[3];
    const float* d0W  = (const float*)d_in[4];
    const float* d0b  = (const float*)d_in[5];
    const float* d0g  = (const float*)d_in[6];
    const float* d0be = (const float*)d_in[7];
    const float* d1W  = (const float*)d_in[8];
    const float* d1b  = (const float*)d_in[9];
    const float* d1g  = (const float*)d_in[10];
    const float* d1be = (const float*)d_in[11];
    const float* d2W  = (const float*)d_in[12];
    const float* d2b  = (const float*)d_in[13];
    const float* d2g  = (const float*)d_in[14];
    const float* d2be = (const float*)d_in[15];
    const float* xcW  = (const float*)d_in[16];
    const float* xcb  = (const float*)d_in[17];
    const float* xd1W = (const float*)d_in[18];
    const float* xd1b = (const float*)d_in[19];
    const float* xd2W = (const float*)d_in[20];
    const float* xd2b = (const float*)d_in[21];
    const float* dwW  = (const float*)d_in[22];
    const float* dwb  = (const float*)d_in[23];
    const float* pwW  = (const float*)d_in[24];
    const float* pwb  = (const float*)d_in[25];
    const float* endg = (const float*)d_in[26];
    const float* endbe= (const float*)d_in[27];
    float* out = (float*)d_out;

    float *pX0, *pX1, *pX2;
    cudaGetSymbolAddress((void**)&pX0, g_X0);
    cudaGetSymbolAddress((void**)&pX1, g_X1);
    cudaGetSymbolAddress((void**)&pX2, g_X2);

    dense0_kernel<<<4096, 256>>>(fts, d0W, d0b, d0g, d0be);

    cudaFuncSetAttribute(prep_kernel,
                         cudaFuncAttributeMaxDynamicSharedMemorySize, SMEM_B);
    prep_kernel<<<32768 / TILEP, 256, SMEM_B>>>(
        rep_pts, pts, pts_idx,
        d1W, d1b, d1g, d1be, d2W, d2b, d2g, d2be);

    cudaFuncSetAttribute(gemmX0_tf32,
                         cudaFuncAttributeMaxDynamicSharedMemorySize, X0_SMEM);
    dim3 xgrid(2, 256);
    gemmX0_tf32<<<xgrid, 256, X0_SMEM>>>(xcW, xcb, pX0);

    dim3 ggrid(2, 256);
    gemm256_tf32<true><<<ggrid, 256>>>(pX0, xd1W, xd1b, pX1);
    gemm256_tf32<false><<<ggrid, 256>>>(pX1, xd2W, xd2b, pX2);

    cudaFuncSetAttribute(epi_kernel,
                         cudaFuncAttributeMaxDynamicSharedMemorySize, EPI_SM);
    epi_kernel<<<32768 / TILEP, 256, EPI_SM>>>(dwW, dwb);

    gemm_pw_tf32<<<256, 256>>>(pwW, pwb, endg, endbe, out);
}

// round 12
// speedup vs baseline: 2.0288x; 1.2270x over previous
#include <cuda_runtime.h>
#include <math.h>

typedef unsigned long long u64;
typedef unsigned int u32;

// ---- problem dims ----
#define NB      32
#define NUMPTS  2048
#define PN      1024
#define TILEP   8
#define FCS     100
#define BNI     0.9999950000374996f

// scratch
__device__ float g_ftsl[NB * NUMPTS * 64];
__device__ float g_PLS[(size_t)32768 * 48];
__device__ float g_X0 [32768 * 256];
__device__ float g_X1 [32768 * 256];
__device__ float g_X2 [32768 * 256];
__device__ float g_DW [(size_t)32768 * 192];

__device__ __forceinline__ float eluf(float x) {
    return x > 0.0f ? x : expm1f(x);
}
__device__ __forceinline__ u64 fma2(u64 a, u64 b, u64 c) {
    u64 d; asm("fma.rn.f32x2 %0,%1,%2,%3;" : "=l"(d) : "l"(a), "l"(b), "l"(c)); return d;
}
__device__ __forceinline__ u64 dup2(float x) {
    u64 d; asm("mov.b64 %0,{%1,%1};" : "=l"(d) : "f"(x)); return d;
}
__device__ __forceinline__ u64 pk2(float lo, float hi) {
    u64 d; asm("mov.b64 %0,{%1,%2};" : "=l"(d) : "f"(lo), "f"(hi)); return d;
}
__device__ __forceinline__ float2 unpk(u64 v) {
    float2 r; asm("mov.b64 {%0,%1},%2;" : "=f"(r.x), "=f"(r.y) : "l"(v)); return r;
}
__device__ __forceinline__ u32 tf32(float f) {
    u32 o; asm("cvt.rna.tf32.f32 %0, %1;" : "=r"(o) : "f"(f)); return o;
}
__device__ __forceinline__ void mma8(float4& d, const u32* a, u32 b0, u32 b1) {
    asm("mma.sync.aligned.m16n8k8.row.col.f32.tf32.tf32.f32 "
        "{%0,%1,%2,%3}, {%4,%5,%6,%7}, {%8,%9}, {%0,%1,%2,%3};"
        : "+f"(d.x), "+f"(d.y), "+f"(d.z), "+f"(d.w)
        : "r"(a[0]), "r"(a[1]), "r"(a[2]), "r"(a[3]), "r"(b0), "r"(b1));
}

// ============================================================================
// Kernel A: dense0 -> g_ftsl (16 MB, stays L2-resident for the epi gather)
// ============================================================================
__global__ void __launch_bounds__(256) dense0_kernel(
    const float* __restrict__ fts, const float* __restrict__ W,
    const float* __restrict__ b,   const float* __restrict__ g,
    const float* __restrict__ be)
{
    __shared__ float Ws[64 * 64];
    __shared__ float xs[16 * 64];
    const int t = threadIdx.x;
    const size_t row0 = (size_t)blockIdx.x * 16;

#pragma unroll
    for (int u = 0; u < 16; u++) Ws[t + 256 * u] = W[t + 256 * u];
    ((float4*)xs)[t] = ((const float4*)(fts + row0 * 64))[t];
    __syncthreads();

    const int r  = t >> 4;
    const int cb = (t & 15) * 4;
    u64 a0 = 0ull, a1 = 0ull;
#pragma unroll 8
    for (int k = 0; k < 64; k++) {
        u64 xd = dup2(xs[r * 64 + k]);
        ulonglong2 w = *(const ulonglong2*)&Ws[k * 64 + cb];
        a0 = fma2(xd, w.x, a0);
        a1 = fma2(xd, w.y, a1);
    }
    float2 f0 = unpk(a0), f1 = unpk(a1);
    float4 b4 = *(const float4*)&b[cb];
    float4 g4 = *(const float4*)&g[cb];
    float4 e4 = *(const float4*)&be[cb];
    float4 o;
    o.x = g4.x * (eluf(f0.x + b4.x) * BNI) + e4.x;
    o.y = g4.y * (eluf(f0.y + b4.y) * BNI) + e4.y;
    o.z = g4.z * (eluf(f1.x + b4.z) * BNI) + e4.z;
    o.w = g4.w * (eluf(f1.y + b4.w) * BNI) + e4.w;
    *(float4*)&g_ftsl[(row0 + r) * 64 + cb] = o;
}

// ============================================================================
// Kernel C (coords): gather neighbor coords, center on rep point -> g_PLS
// one thread per (point, k) pair
// ============================================================================
__global__ void __launch_bounds__(256) coords_kernel(
    const float* __restrict__ rep_pts, const float* __restrict__ pts,
    const int* __restrict__ pts_idx)
{
    int idx = blockIdx.x * 256 + threadIdx.x;   // 0 .. 524287
    int pt = idx >> 4, k = idx & 15;
    int n = pt >> 10;
    int gi = pts_idx[idx];
    const float* pp = pts + ((size_t)n * NUMPTS + gi) * 3;
    const float* rp = rep_pts + (size_t)pt * 3;
    float* dst = g_PLS + (size_t)pt * 48;
    dst[k]      = pp[0] - rp[0];
    dst[16 + k] = pp[1] - rp[1];
    dst[32 + k] = pp[2] - rp[2];
}

// ============================================================================
// GEMM-X0 (TF32): X0[M,256] = elu(PLS[M,48] @ xcW^T[48,256] + xcb)
// ============================================================================
#define X0_SMEM ((128 * 52 + 48 * 136) * 4)

__global__ void __launch_bounds__(256, 2) gemmX0_tf32(
    const float* __restrict__ xcW, const float* __restrict__ xcb,
    float* __restrict__ X0)
{
    extern __shared__ u32 smx[];
    u32 (*As)[52]  = (u32(*)[52])smx;
    u32 (*Bs)[136] = (u32(*)[136])(smx + 128 * 52);

    const int t  = threadIdx.x;
    const int m0 = blockIdx.y << 7;
    const int n0 = blockIdx.x << 7;
    const int wid = t >> 5, lane = t & 31;
    const int wm = wid >> 1, wn = wid & 1;
    const int g = lane >> 2, tg = lane & 3;

    {
        const int ar = t >> 1, ah = (t & 1) * 24;
        const float* Ar = g_PLS + (size_t)(m0 + ar) * 48 + ah;
#pragma unroll
        for (int v = 0; v < 6; v++) {
            float4 a = *(const float4*)&Ar[v * 4];
            u32* ap = &As[ar][ah + v * 4];
            ap[0] = tf32(a.x); ap[1] = tf32(a.y);
            ap[2] = tf32(a.z); ap[3] = tf32(a.w);
        }
    }
    {
        const int q = t >> 1, kh = (t & 1) * 24;
        const float* Wr = xcW + (size_t)(n0 + q) * 48 + kh;
#pragma unroll
        for (int v = 0; v < 6; v++) {
            float4 w = *(const float4*)&Wr[v * 4];
            Bs[kh + v * 4 + 0][q] = tf32(w.x);
            Bs[kh + v * 4 + 1][q] = tf32(w.y);
            Bs[kh + v * 4 + 2][q] = tf32(w.z);
            Bs[kh + v * 4 + 3][q] = tf32(w.w);
        }
    }
    __syncthreads();

    float4 acc[2][8];
#pragma unroll
    for (int i = 0; i < 2; i++)
#pragma unroll
        for (int j = 0; j < 8; j++) acc[i][j] = make_float4(0.f, 0.f, 0.f, 0.f);

#pragma unroll
    for (int kc = 0; kc < 6; kc++) {
        const int kb = kc * 8;
        u32 af[2][4];
#pragma unroll
        for (int mi = 0; mi < 2; mi++) {
            int r = wm * 32 + mi * 16;
            af[mi][0] = As[r + g][kb + tg];
            af[mi][1] = As[r + g + 8][kb + tg];
            af[mi][2] = As[r + g][kb + tg + 4];
            af[mi][3] = As[r + g + 8][kb + tg + 4];
        }
#pragma unroll
        for (int nj = 0; nj < 8; nj++) {
            int cn = wn * 64 + nj * 8 + g;
            u32 bf0 = Bs[kb + tg][cn];
            u32 bf1 = Bs[kb + tg + 4][cn];
            mma8(acc[0][nj], af[0], bf0, bf1);
            mma8(acc[1][nj], af[1], bf0, bf1);
        }
    }

#pragma unroll
    for (int nj = 0; nj < 8; nj++) {
        int col = n0 + wn * 64 + nj * 8 + tg * 2;
        float bv0 = __ldg(&xcb[col]);
        float bv1 = __ldg(&xcb[col + 1]);
#pragma unroll
        for (int mi = 0; mi < 2; mi++) {
            int row = m0 + wm * 32 + mi * 16 + g;
            float4 d = acc[mi][nj];
            float2 s0, s1;
            s0.x = eluf(d.x + bv0); s0.y = eluf(d.y + bv1);
            s1.x = eluf(d.z + bv0); s1.y = eluf(d.w + bv1);
            *(float2*)&X0[(size_t)row * 256 + col]       = s0;
            *(float2*)&X0[(size_t)(row + 8) * 256 + col] = s1;
        }
    }
}

// ============================================================================
// GEMM (TF32 tensor): C[M,256] = act(A[M,256] @ W[256,256] + bias)
// ============================================================================
template<bool ELU>
__global__ void __launch_bounds__(256, 2) gemm256_tf32(
    const float* __restrict__ A, const float* __restrict__ W,
    const float* __restrict__ bias, float* __restrict__ C)
{
    __shared__ u32 As[2][128][20];
    __shared__ u32 Bs[2][16][136];
    const int t  = threadIdx.x;
    const int m0 = blockIdx.y << 7;
    const int n0 = blockIdx.x << 7;
    const int wid = t >> 5, lane = t & 31;
    const int wm = wid >> 1, wn = wid & 1;
    const int g = lane >> 2, tg = lane & 3;

    float4 acc[2][8];
#pragma unroll
    for (int i = 0; i < 2; i++)
#pragma unroll
        for (int j = 0; j < 8; j++) acc[i][j] = make_float4(0.f, 0.f, 0.f, 0.f);

    const int ar = t >> 1, ak = (t & 1) * 8;
    const int bk = t >> 4, bn = (t & 15) * 8;
    const float* Arow = A + (size_t)(m0 + ar) * 256;

    float4 a0 = *(const float4*)&Arow[ak];
    float4 a1 = *(const float4*)&Arow[ak + 4];
    float4 b0 = *(const float4*)&W[(size_t)bk * 256 + n0 + bn];
    float4 b1 = *(const float4*)&W[(size_t)bk * 256 + n0 + bn + 4];

#pragma unroll 1
    for (int k0 = 0; k0 < 16; k0++) {
        const int buf = k0 & 1;
        {
            u32 av[8], bv[8];
            av[0] = tf32(a0.x); av[1] = tf32(a0.y);
            av[2] = tf32(a0.z); av[3] = tf32(a0.w);
            av[4] = tf32(a1.x); av[5] = tf32(a1.y);
            av[6] = tf32(a1.z); av[7] = tf32(a1.w);
            bv[0] = tf32(b0.x); bv[1] = tf32(b0.y);
            bv[2] = tf32(b0.z); bv[3] = tf32(b0.w);
            bv[4] = tf32(b1.x); bv[5] = tf32(b1.y);
            bv[6] = tf32(b1.z); bv[7] = tf32(b1.w);
            *(uint4*)&As[buf][ar][ak]     = *(uint4*)&av[0];
            *(uint4*)&As[buf][ar][ak + 4] = *(uint4*)&av[4];
            *(uint4*)&Bs[buf][bk][bn]     = *(uint4*)&bv[0];
            *(uint4*)&Bs[buf][bk][bn + 4] = *(uint4*)&bv[4];
        }
        __syncthreads();
        if (k0 < 15) {
            int kn = (k0 + 1) * 16;
            a0 = *(const float4*)&Arow[kn + ak];
            a1 = *(const float4*)&Arow[kn + ak + 4];
            b0 = *(const float4*)&W[(size_t)(kn + bk) * 256 + n0 + bn];
            b1 = *(const float4*)&W[(size_t)(kn + bk) * 256 + n0 + bn + 4];
        }
#pragma unroll
        for (int kk = 0; kk < 2; kk++) {
            const int kb = kk * 8;
            u32 af[2][4];
#pragma unroll
            for (int mi = 0; mi < 2; mi++) {
                int r = wm * 32 + mi * 16;
                af[mi][0] = As[buf][r + g][kb + tg];
                af[mi][1] = As[buf][r + g + 8][kb + tg];
                af[mi][2] = As[buf][r + g][kb + tg + 4];
                af[mi][3] = As[buf][r + g + 8][kb + tg + 4];
            }
#pragma unroll
            for (int nj = 0; nj < 8; nj++) {
                int cn = wn * 64 + nj * 8 + g;
                u32 bf0 = Bs[buf][kb + tg][cn];
                u32 bf1 = Bs[buf][kb + tg + 4][cn];
                mma8(acc[0][nj], af[0], bf0, bf1);
                mma8(acc[1][nj], af[1], bf0, bf1);
            }
        }
    }

#pragma unroll
    for (int nj = 0; nj < 8; nj++) {
        int col = n0 + wn * 64 + nj * 8 + tg * 2;
        float bv0 = __ldg(&bias[col]);
        float bv1 = __ldg(&bias[col + 1]);
#pragma unroll
        for (int mi = 0; mi < 2; mi++) {
            int row = m0 + wm * 32 + mi * 16 + g;
            float4 d = acc[mi][nj];
            float v0 = d.x + bv0, v1 = d.y + bv1;
            float v2 = d.z + bv0, v3 = d.w + bv1;
            if (ELU) { v0 = eluf(v0); v1 = eluf(v1); v2 = eluf(v2); v3 = eluf(v3); }
            float2 s0; s0.x = v0; s0.y = v1;
            float2 s1; s1.x = v2; s1.y = v3;
            *(float2*)&C[(size_t)row * 256 + col]       = s0;
            *(float2*)&C[(size_t)(row + 8) * 256 + col] = s1;
        }
    }
}

// ============================================================================
// GEMM-PW (TF32): out[M,128] = endg*(elu(DW[M,192]@pwW[192,128]+pwb)*BNI)+endbe
// ============================================================================
__global__ void __launch_bounds__(256, 2) gemm_pw_tf32(
    const float* __restrict__ pwW, const float* __restrict__ pwb,
    const float* __restrict__ endg, const float* __restrict__ endbe,
    float* __restrict__ out)
{
    __shared__ u32 As[2][128][20];
    __shared__ u32 Bs[2][16][136];
    const int t  = threadIdx.x;
    const int m0 = blockIdx.x << 7;
    const int wid = t >> 5, lane = t & 31;
    const int wm = wid >> 1, wn = wid & 1;
    const int g = lane >> 2, tg = lane & 3;

    float4 acc[2][8];
#pragma unroll
    for (int i = 0; i < 2; i++)
#pragma unroll
        for (int j = 0; j < 8; j++) acc[i][j] = make_float4(0.f, 0.f, 0.f, 0.f);

    const int ar = t >> 1, ak = (t & 1) * 8;
    const int bk = t >> 4, bn = (t & 15) * 8;
    const float* Arow = g_DW + (size_t)(m0 + ar) * 192;

    float4 a0 = *(const float4*)&Arow[ak];
    float4 a1 = *(const float4*)&Arow[ak + 4];
    float4 b0 = *(const float4*)&pwW[(size_t)bk * 128 + bn];
    float4 b1 = *(const float4*)&pwW[(size_t)bk * 128 + bn + 4];

#pragma unroll 1
    for (int k0 = 0; k0 < 12; k0++) {
        const int buf = k0 & 1;
        {
            u32 av[8], bv[8];
            av[0] = tf32(a0.x); av[1] = tf32(a0.y);
            av[2] = tf32(a0.z); av[3] = tf32(a0.w);
            av[4] = tf32(a1.x); av[5] = tf32(a1.y);
            av[6] = tf32(a1.z); av[7] = tf32(a1.w);
            bv[0] = tf32(b0.x); bv[1] = tf32(b0.y);
            bv[2] = tf32(b0.z); bv[3] = tf32(b0.w);
            bv[4] = tf32(b1.x); bv[5] = tf32(b1.y);
            bv[6] = tf32(b1.z); bv[7] = tf32(b1.w);
            *(uint4*)&As[buf][ar][ak]     = *(uint4*)&av[0];
            *(uint4*)&As[buf][ar][ak + 4] = *(uint4*)&av[4];
            *(uint4*)&Bs[buf][bk][bn]     = *(uint4*)&bv[0];
            *(uint4*)&Bs[buf][bk][bn + 4] = *(uint4*)&bv[4];
        }
        __syncthreads();
        if (k0 < 11) {
            int kn = (k0 + 1) * 16;
            a0 = *(const float4*)&Arow[kn + ak];
            a1 = *(const float4*)&Arow[kn + ak + 4];
            b0 = *(const float4*)&pwW[(size_t)(kn + bk) * 128 + bn];
            b1 = *(const float4*)&pwW[(size_t)(kn + bk) * 128 + bn + 4];
        }
#pragma unroll
        for (int kk = 0; kk < 2; kk++) {
            const int kb = kk * 8;
            u32 af[2][4];
#pragma unroll
            for (int mi = 0; mi < 2; mi++) {
                int r = wm * 32 + mi * 16;
                af[mi][0] = As[buf][r + g][kb + tg];
                af[mi][1] = As[buf][r + g + 8][kb + tg];
                af[mi][2] = As[buf][r + g][kb + tg + 4];
                af[mi][3] = As[buf][r + g + 8][kb + tg + 4];
            }
#pragma unroll
            for (int nj = 0; nj < 8; nj++) {
                int cn = wn * 64 + nj * 8 + g;
                u32 bf0 = Bs[buf][kb + tg][cn];
                u32 bf1 = Bs[buf][kb + tg + 4][cn];
                mma8(acc[0][nj], af[0], bf0, bf1);
                mma8(acc[1][nj], af[1], bf0, bf1);
            }
        }
    }

#pragma unroll
    for (int nj = 0; nj < 8; nj++) {
        int col = wn * 64 + nj * 8 + tg * 2;
        float bv0 = __ldg(&pwb[col]),   bv1 = __ldg(&pwb[col + 1]);
        float gv0 = __ldg(&endg[col]),  gv1 = __ldg(&endg[col + 1]);
        float ev0 = __ldg(&endbe[col]), ev1 = __ldg(&endbe[col + 1]);
#pragma unroll
        for (int mi = 0; mi < 2; mi++) {
            int row = m0 + wm * 32 + mi * 16 + g;
            float4 d = acc[mi][nj];
            float2 s0, s1;
            s0.x = gv0 * (eluf(d.x + bv0) * BNI) + ev0;
            s0.y = gv1 * (eluf(d.y + bv1) * BNI) + ev1;
            s1.x = gv0 * (eluf(d.z + bv0) * BNI) + ev0;
            s1.y = gv1 * (eluf(d.w + bv1) * BNI) + ev1;
            *(float2*)&out[(size_t)row * 128 + col]       = s0;
            *(float2*)&out[(size_t)(row + 8) * 128 + col] = s1;
        }
    }
}

// ============================================================================
// Kernel E (mega-epilogue): gather ftsl (L2-resident) + lift MLP + F + G1
// smem (floats):
//   XA [8][256] @0 | FC [8][16][FCS] @2048 | H [32][128] @14848
//   SDW @18944 (3072) | SD1W @22016(96) SD1B @22112 SD1G @22144 SD1BE @22176
//   SD2Wd @22208 (2048) | SD2B @24256 SD2G @24288 SD2BE @24320 | SIDX @24352
// total 24480 floats = 97920 B
// ============================================================================
#define EPI_SM (24480 * 4)

__global__ void __launch_bounds__(256, 2) epi_kernel(
    const int* __restrict__ pts_idx,
    const float* __restrict__ d1W, const float* __restrict__ d1b,
    const float* __restrict__ d1g, const float* __restrict__ d1be,
    const float* __restrict__ d2W, const float* __restrict__ d2b,
    const float* __restrict__ d2g, const float* __restrict__ d2be,
    const float* __restrict__ dwW, const float* __restrict__ dwb)
{
    extern __shared__ float sm[];
    float* XA    = sm;            // [8][256]  X2
    float* FC    = sm + 2048;     // [8][16][FCS]
    float* H     = sm + 14848;    // [32][128]
    float* SDW   = sm + 18944;    // dw pairs
    float* SD1W  = sm + 22016; float* SD1B  = sm + 22112;
    float* SD1G  = sm + 22144; float* SD1BE = sm + 22176;
    float* SD2Wd = sm + 22208;
    float* SD2B  = sm + 24256; float* SD2G  = sm + 24288;
    float* SD2BE = sm + 24320;
    int*   SIDX  = (int*)(sm + 24352);

    const int t   = threadIdx.x;
    const int gp0 = blockIdx.x * TILEP;
    const int n   = gp0 >> 10;

    // ---- phase 0: indices, weights, X2 ----
    if (t < 128) SIDX[t] = pts_idx[(size_t)gp0 * 16 + t];
    for (int u = t; u < 96; u += 256) SD1W[u] = d1W[u];
    for (int u = t; u < 1024; u += 256) {
        float w = d2W[u];
        SD2Wd[2 * u] = w; SD2Wd[2 * u + 1] = w;
    }
    if (t < 32) {
        SD1B[t] = d1b[t]; SD1G[t] = d1g[t]; SD1BE[t] = d1be[t];
        SD2B[t] = d2b[t]; SD2G[t] = d2g[t]; SD2BE[t] = d2be[t];
    }
    for (int idx = t; idx < 1536; idx += 256) {
        int k = idx / 96, c = idx - k * 96;
        float2 w;
        w.x = dwW[c * 32 + k];
        w.y = dwW[c * 32 + 16 + k];
        *(float2*)&SDW[idx * 2] = w;
    }
    {
        const float4* src = (const float4*)(g_X2 + (size_t)gp0 * 256);
        float4* dst = (float4*)XA;
        dst[t] = src[t];
        dst[t + 256] = src[t + 256];
    }
    __syncthreads();

    // ---- phase 1: gather ftsl -> FC[:,32:96]; E1 -> H ----
    {
        int row = t >> 1, half = t & 1;
        int gi = SIDX[row];
        const float4* src = (const float4*)(g_ftsl + ((size_t)n * NUMPTS + gi) * 64 + half * 32);
        float4* dst = (float4*)&FC[row * FCS + 32 + half * 32];
#pragma unroll
        for (int u = 0; u < 8; u++) dst[u] = src[u];
    }
    {
        const int row = t & 127, hc = t >> 7;
        const int i = row >> 4, k = row & 15;
        const float* pl = g_PLS + (size_t)(gp0 + i) * 48;
        float px = __ldg(&pl[k]);
        float py = __ldg(&pl[16 + k]);
        float pz = __ldg(&pl[32 + k]);
#pragma unroll
        for (int u = 0; u < 16; u++) {
            int c = hc * 16 + u;
            float v = fmaf(px, SD1W[c], fmaf(py, SD1W[32 + c],
                      fmaf(pz, SD1W[64 + c], SD1B[c])));
            H[c * 128 + row] = SD1G[c] * (eluf(v) * BNI) + SD1BE[c];
        }
    }
    __syncthreads();

    // ---- E2: dense2 (32 -> 32), row-pair packed fma2 -> FC[:,0:32] ----
    {
        const int rp = t & 63, cg = t >> 6;
        const int row0 = 2 * rp, c0 = cg * 8;
        u64 acc[8];
#pragma unroll
        for (int u = 0; u < 8; u++) acc[u] = dup2(SD2B[c0 + u]);
#pragma unroll 4
        for (int c = 0; c < 32; c++) {
            u64 hv = *(const u64*)&H[c * 128 + row0];
            const ulonglong2* wd = (const ulonglong2*)&SD2Wd[c * 64 + 2 * c0];
            ulonglong2 w0 = wd[0], w1 = wd[1], w2 = wd[2], w3 = wd[3];
            acc[0] = fma2(hv, w0.x, acc[0]); acc[1] = fma2(hv, w0.y, acc[1]);
            acc[2] = fma2(hv, w1.x, acc[2]); acc[3] = fma2(hv, w1.y, acc[3]);
            acc[4] = fma2(hv, w2.x, acc[4]); acc[5] = fma2(hv, w2.y, acc[5]);
            acc[6] = fma2(hv, w3.x, acc[6]); acc[7] = fma2(hv, w3.y, acc[7]);
        }
#pragma unroll
        for (int u = 0; u < 8; u++) {
            int c = c0 + u;
            float2 f = unpk(acc[u]);
            FC[row0 * FCS + c]       = SD2G[c] * (eluf(f.x) * BNI) + SD2BE[c];
            FC[(row0 + 1) * FCS + c] = SD2G[c] * (eluf(f.y) * BNI) + SD2BE[c];
        }
    }
    __syncthreads();

    const int i = t >> 5, lane = t & 31;

    // ---- Phase F: fts_X = X2(16x16) @ FC(16x96), k-paired fma2, in place ----
    {
        u64 fp[3][8];
#pragma unroll
        for (int u = 0; u < 3; u++) {
            int c = lane + 32 * u;
#pragma unroll
            for (int kk = 0; kk < 8; kk++) {
                float lo = FC[(i * 16 + 2 * kk) * FCS + c];
                float hi = FC[(i * 16 + 2 * kk + 1) * FCS + c];
                fp[u][kk] = pk2(lo, hi);
            }
        }
#pragma unroll
        for (int r = 0; r < 16; r++) {
            const ulonglong2* xr = (const ulonglong2*)&XA[i * 256 + r * 16];
            ulonglong2 x0 = xr[0], x1 = xr[1], x2 = xr[2], x3 = xr[3];
            u64 xp[8] = {x0.x, x0.y, x1.x, x1.y, x2.x, x2.y, x3.x, x3.y};
#pragma unroll
            for (int u = 0; u < 3; u++) {
                u64 acc = 0ull;
#pragma unroll
                for (int kk = 0; kk < 8; kk++)
                    acc = fma2(xp[kk], fp[u][kk], acc);
                float2 h = unpk(acc);
                FC[(i * 16 + r) * FCS + lane + 32 * u] = h.x + h.y;
            }
        }
    }
    __syncthreads();

    // ---- Phase G1: depthwise, m-paired fma2 -> g_DW ----
    {
#pragma unroll
        for (int u = 0; u < 3; u++) {
            int c = lane + 32 * u;
            u64 acc = *(const u64*)&dwb[2 * c];
#pragma unroll
            for (int k = 0; k < 16; k++) {
                u64 fd = dup2(FC[(i * 16 + k) * FCS + c]);
                u64 wd = *(const u64*)&SDW[(k * 96 + c) * 2];
                acc = fma2(fd, wd, acc);
            }
            *(u64*)&g_DW[(size_t)(gp0 + i) * 192 + 2 * c] = acc;
        }
    }
}

// ============================================================================
extern "C" void kernel_launch(void* const* d_in, const int* in_sizes, int n_in,
                              void* d_out, int out_size)
{
    const float* rep_pts = (const float*)d_in[0];
    const float* pts     = (const float*)d_in[1];
    const float* fts     = (const float*)d_in[2];
    const int*   pts_idx = (const int*)d_in[3];
    const float* d0W  = (const float*)d_in[4];
    const float* d0b  = (const float*)d_in[5];
    const float* d0g  = (const float*)d_in[6];
    const float* d0be = (const float*)d_in[7];
    const float* d1W  = (const float*)d_in[8];
    const float* d1b  = (const float*)d_in[9];
    const float* d1g  = (const float*)d_in[10];
    const float* d1be = (const float*)d_in[11];
    const float* d2W  = (const float*)d_in[12];
    const float* d2b  = (const float*)d_in[13];
    const float* d2g  = (const float*)d_in[14];
    const float* d2be = (const float*)d_in[15];
    const float* xcW  = (const float*)d_in[16];
    const float* xcb  = (const float*)d_in[17];
    const float* xd1W = (const float*)d_in[18];
    const float* xd1b = (const float*)d_in[19];
    const float* xd2W = (const float*)d_in[20];
    const float* xd2b = (const float*)d_in[21];
    const float* dwW  = (const float*)d_in[22];
    const float* dwb  = (const float*)d_in[23];
    const float* pwW  = (const float*)d_in[24];
    const float* pwb  = (const float*)d_in[25];
    const float* endg = (const float*)d_in[26];
    const float* endbe= (const float*)d_in[27];
    float* out = (float*)d_out;

    float *pX0, *pX1, *pX2;
    cudaGetSymbolAddress((void**)&pX0, g_X0);
    cudaGetSymbolAddress((void**)&pX1, g_X1);
    cudaGetSymbolAddress((void**)&pX2, g_X2);

    dense0_kernel<<<4096, 256>>>(fts, d0W, d0b, d0g, d0be);
    coords_kernel<<<2048, 256>>>(rep_pts, pts, pts_idx);

    cudaFuncSetAttribute(gemmX0_tf32,
                         cudaFuncAttributeMaxDynamicSharedMemorySize, X0_SMEM);
    dim3 xgrid(2, 256);
    gemmX0_tf32<<<xgrid, 256, X0_SMEM>>>(xcW, xcb, pX0);

    dim3 ggrid(2, 256);
    gemm256_tf32<true><<<ggrid, 256>>>(pX0, xd1W, xd1b, pX1);
    gemm256_tf32<false><<<ggrid, 256>>>(pX1, xd2W, xd2b, pX2);

    cudaFuncSetAttribute(epi_kernel,
                         cudaFuncAttributeMaxDynamicSharedMemorySize, EPI_SM);
    epi_kernel<<<32768 / TILEP, 256, EPI_SM>>>(
        pts_idx, d1W, d1b, d1g, d1be, d2W, d2b, d2g, d2be, dwW, dwb);

    gemm_pw_tf32<<<256, 256>>>(pwW, pwb, endg, endbe, out);
}

// round 13
// speedup vs baseline: 2.0485x; 1.0097x over previous
#include <cuda_runtime.h>
#include <math.h>

typedef unsigned long long u64;
typedef unsigned int u32;

// ---- problem dims ----
#define NB      32
#define NUMPTS  2048
#define PN      1024
#define TILEP   8
#define FCS     100
#define BNI     0.9999950000374996f

// scratch
__device__ float g_ftsl[NB * NUMPTS * 64];
__device__ float g_PLS[(size_t)32768 * 48];
__device__ float g_X0 [32768 * 256];
__device__ float g_X1 [32768 * 256];
__device__ float g_X2 [32768 * 256];
__device__ float g_DW [(size_t)32768 * 192];

__device__ __forceinline__ float eluf(float x) {
    return x > 0.0f ? x : expm1f(x);
}
__device__ __forceinline__ u64 fma2(u64 a, u64 b, u64 c) {
    u64 d; asm("fma.rn.f32x2 %0,%1,%2,%3;" : "=l"(d) : "l"(a), "l"(b), "l"(c)); return d;
}
__device__ __forceinline__ u64 dup2(float x) {
    u64 d; asm("mov.b64 %0,{%1,%1};" : "=l"(d) : "f"(x)); return d;
}
__device__ __forceinline__ float2 unpk(u64 v) {
    float2 r; asm("mov.b64 {%0,%1},%2;" : "=f"(r.x), "=f"(r.y) : "l"(v)); return r;
}
__device__ __forceinline__ u32 tf32(float f) {
    u32 o; asm("cvt.rna.tf32.f32 %0, %1;" : "=r"(o) : "f"(f)); return o;
}
__device__ __forceinline__ void mma8(float4& d, const u32* a, u32 b0, u32 b1) {
    asm("mma.sync.aligned.m16n8k8.row.col.f32.tf32.tf32.f32 "
        "{%0,%1,%2,%3}, {%4,%5,%6,%7}, {%8,%9}, {%0,%1,%2,%3};"
        : "+f"(d.x), "+f"(d.y), "+f"(d.z), "+f"(d.w)
        : "r"(a[0]), "r"(a[1]), "r"(a[2]), "r"(a[3]), "r"(b0), "r"(b1));
}

// ============================================================================
// Kernel A: dense0 -> g_ftsl (16 MB, stays L2-resident for the epi gather)
// ============================================================================
__global__ void __launch_bounds__(256) dense0_kernel(
    const float* __restrict__ fts, const float* __restrict__ W,
    const float* __restrict__ b,   const float* __restrict__ g,
    const float* __restrict__ be)
{
    __shared__ float Ws[64 * 64];
    __shared__ float xs[16 * 64];
    const int t = threadIdx.x;
    const size_t row0 = (size_t)blockIdx.x * 16;

#pragma unroll
    for (int u = 0; u < 16; u++) Ws[t + 256 * u] = W[t + 256 * u];
    ((float4*)xs)[t] = ((const float4*)(fts + row0 * 64))[t];
    __syncthreads();

    const int r  = t >> 4;
    const int cb = (t & 15) * 4;
    u64 a0 = 0ull, a1 = 0ull;
#pragma unroll 8
    for (int k = 0; k < 64; k++) {
        u64 xd = dup2(xs[r * 64 + k]);
        ulonglong2 w = *(const ulonglong2*)&Ws[k * 64 + cb];
        a0 = fma2(xd, w.x, a0);
        a1 = fma2(xd, w.y, a1);
    }
    float2 f0 = unpk(a0), f1 = unpk(a1);
    float4 b4 = *(const float4*)&b[cb];
    float4 g4 = *(const float4*)&g[cb];
    float4 e4 = *(const float4*)&be[cb];
    float4 o;
    o.x = g4.x * (eluf(f0.x + b4.x) * BNI) + e4.x;
    o.y = g4.y * (eluf(f0.y + b4.y) * BNI) + e4.y;
    o.z = g4.z * (eluf(f1.x + b4.z) * BNI) + e4.z;
    o.w = g4.w * (eluf(f1.y + b4.w) * BNI) + e4.w;
    *(float4*)&g_ftsl[(row0 + r) * 64 + cb] = o;
}

// ============================================================================
// Kernel C (coords): gather neighbor coords, center on rep point -> g_PLS
// ============================================================================
__global__ void __launch_bounds__(256) coords_kernel(
    const float* __restrict__ rep_pts, const float* __restrict__ pts,
    const int* __restrict__ pts_idx)
{
    int idx = blockIdx.x * 256 + threadIdx.x;
    int pt = idx >> 4, k = idx & 15;
    int n = pt >> 10;
    int gi = pts_idx[idx];
    const float* pp = pts + ((size_t)n * NUMPTS + gi) * 3;
    const float* rp = rep_pts + (size_t)pt * 3;
    float* dst = g_PLS + (size_t)pt * 48;
    dst[k]      = pp[0] - rp[0];
    dst[16 + k] = pp[1] - rp[1];
    dst[32 + k] = pp[2] - rp[2];
}

// ============================================================================
// GEMM-X0 (TF32): X0[M,256] = elu(PLS[M,48] @ xcW^T[48,256] + xcb)
// ============================================================================
#define X0_SMEM ((128 * 52 + 48 * 136) * 4)

__global__ void __launch_bounds__(256, 2) gemmX0_tf32(
    const float* __restrict__ xcW, const float* __restrict__ xcb,
    float* __restrict__ X0)
{
    extern __shared__ u32 smx[];
    u32 (*As)[52]  = (u32(*)[52])smx;
    u32 (*Bs)[136] = (u32(*)[136])(smx + 128 * 52);

    const int t  = threadIdx.x;
    const int m0 = blockIdx.y << 7;
    const int n0 = blockIdx.x << 7;
    const int wid = t >> 5, lane = t & 31;
    const int wm = wid >> 1, wn = wid & 1;
    const int g = lane >> 2, tg = lane & 3;

    {
        const int ar = t >> 1, ah = (t & 1) * 24;
        const float* Ar = g_PLS + (size_t)(m0 + ar) * 48 + ah;
#pragma unroll
        for (int v = 0; v < 6; v++) {
            float4 a = *(const float4*)&Ar[v * 4];
            u32* ap = &As[ar][ah + v * 4];
            ap[0] = tf32(a.x); ap[1] = tf32(a.y);
            ap[2] = tf32(a.z); ap[3] = tf32(a.w);
        }
    }
    {
        const int q = t >> 1, kh = (t & 1) * 24;
        const float* Wr = xcW + (size_t)(n0 + q) * 48 + kh;
#pragma unroll
        for (int v = 0; v < 6; v++) {
            float4 w = *(const float4*)&Wr[v * 4];
            Bs[kh + v * 4 + 0][q] = tf32(w.x);
            Bs[kh + v * 4 + 1][q] = tf32(w.y);
            Bs[kh + v * 4 + 2][q] = tf32(w.z);
            Bs[kh + v * 4 + 3][q] = tf32(w.w);
        }
    }
    __syncthreads();

    float4 acc[2][8];
#pragma unroll
    for (int i = 0; i < 2; i++)
#pragma unroll
        for (int j = 0; j < 8; j++) acc[i][j] = make_float4(0.f, 0.f, 0.f, 0.f);

#pragma unroll
    for (int kc = 0; kc < 6; kc++) {
        const int kb = kc * 8;
        u32 af[2][4];
#pragma unroll
        for (int mi = 0; mi < 2; mi++) {
            int r = wm * 32 + mi * 16;
            af[mi][0] = As[r + g][kb + tg];
            af[mi][1] = As[r + g + 8][kb + tg];
            af[mi][2] = As[r + g][kb + tg + 4];
            af[mi][3] = As[r + g + 8][kb + tg + 4];
        }
#pragma unroll
        for (int nj = 0; nj < 8; nj++) {
            int cn = wn * 64 + nj * 8 + g;
            u32 bf0 = Bs[kb + tg][cn];
            u32 bf1 = Bs[kb + tg + 4][cn];
            mma8(acc[0][nj], af[0], bf0, bf1);
            mma8(acc[1][nj], af[1], bf0, bf1);
        }
    }

#pragma unroll
    for (int nj = 0; nj < 8; nj++) {
        int col = n0 + wn * 64 + nj * 8 + tg * 2;
        float bv0 = __ldg(&xcb[col]);
        float bv1 = __ldg(&xcb[col + 1]);
#pragma unroll
        for (int mi = 0; mi < 2; mi++) {
            int row = m0 + wm * 32 + mi * 16 + g;
            float4 d = acc[mi][nj];
            float2 s0, s1;
            s0.x = eluf(d.x + bv0); s0.y = eluf(d.y + bv1);
            s1.x = eluf(d.z + bv0); s1.y = eluf(d.w + bv1);
            *(float2*)&X0[(size_t)row * 256 + col]       = s0;
            *(float2*)&X0[(size_t)(row + 8) * 256 + col] = s1;
        }
    }
}

// ============================================================================
// GEMM (TF32): C[M,256] = act(A[M,256] @ W[256,256] + bias)
// double-buffered, unrolled x2 so the buffer index is compile-time.
// ============================================================================
#define G_STAGE(BUF) do {                                                     \
    u32 av[8], bv[8];                                                         \
    av[0] = tf32(a0.x); av[1] = tf32(a0.y);                                   \
    av[2] = tf32(a0.z); av[3] = tf32(a0.w);                                   \
    av[4] = tf32(a1.x); av[5] = tf32(a1.y);                                   \
    av[6] = tf32(a1.z); av[7] = tf32(a1.w);                                   \
    bv[0] = tf32(b0.x); bv[1] = tf32(b0.y);                                   \
    bv[2] = tf32(b0.z); bv[3] = tf32(b0.w);                                   \
    bv[4] = tf32(b1.x); bv[5] = tf32(b1.y);                                   \
    bv[6] = tf32(b1.z); bv[7] = tf32(b1.w);                                   \
    *(uint4*)&As[BUF][ar][ak]     = *(uint4*)&av[0];                          \
    *(uint4*)&As[BUF][ar][ak + 4] = *(uint4*)&av[4];                          \
    *(uint4*)&Bs[BUF][bk][bn]     = *(uint4*)&bv[0];                          \
    *(uint4*)&Bs[BUF][bk][bn + 4] = *(uint4*)&bv[4];                          \
} while (0)

#define G_MMA(BUF) do {                                                       \
    _Pragma("unroll")                                                         \
    for (int kk = 0; kk < 2; kk++) {                                          \
        const int kb = kk * 8;                                                \
        u32 af[2][4];                                                         \
        _Pragma("unroll")                                                     \
        for (int mi = 0; mi < 2; mi++) {                                      \
            int r = wm * 32 + mi * 16;                                        \
            af[mi][0] = As[BUF][r + g][kb + tg];                              \
            af[mi][1] = As[BUF][r + g + 8][kb + tg];                          \
            af[mi][2] = As[BUF][r + g][kb + tg + 4];                          \
            af[mi][3] = As[BUF][r + g + 8][kb + tg + 4];                      \
        }                                                                     \
        _Pragma("unroll")                                                     \
        for (int nj = 0; nj < 8; nj++) {                                      \
            int cn = wn * 64 + nj * 8 + g;                                    \
            u32 bf0 = Bs[BUF][kb + tg][cn];                                   \
            u32 bf1 = Bs[BUF][kb + tg + 4][cn];                               \
            mma8(acc[0][nj], af[0], bf0, bf1);                                \
            mma8(acc[1][nj], af[1], bf0, bf1);                                \
        }                                                                     \
    }                                                                         \
} while (0)

template<bool ELU>
__global__ void __launch_bounds__(256, 2) gemm256_tf32(
    const float* __restrict__ A, const float* __restrict__ W,
    const float* __restrict__ bias, float* __restrict__ C)
{
    __shared__ u32 As[2][128][20];
    __shared__ u32 Bs[2][16][136];
    const int t  = threadIdx.x;
    const int m0 = blockIdx.y << 7;
    const int n0 = blockIdx.x << 7;
    const int wid = t >> 5, lane = t & 31;
    const int wm = wid >> 1, wn = wid & 1;
    const int g = lane >> 2, tg = lane & 3;

    float4 acc[2][8];
#pragma unroll
    for (int i = 0; i < 2; i++)
#pragma unroll
        for (int j = 0; j < 8; j++) acc[i][j] = make_float4(0.f, 0.f, 0.f, 0.f);

    const int ar = t >> 1, ak = (t & 1) * 8;
    const int bk = t >> 4, bn = (t & 15) * 8;
    const float* Arow = A + (size_t)(m0 + ar) * 256;

    float4 a0 = *(const float4*)&Arow[ak];
    float4 a1 = *(const float4*)&Arow[ak + 4];
    float4 b0 = *(const float4*)&W[(size_t)bk * 256 + n0 + bn];
    float4 b1 = *(const float4*)&W[(size_t)bk * 256 + n0 + bn + 4];

#pragma unroll 1
    for (int k0 = 0; k0 < 16; k0 += 2) {
        G_STAGE(0);
        __syncthreads();
        {
            int kn = (k0 + 1) * 16;
            a0 = *(const float4*)&Arow[kn + ak];
            a1 = *(const float4*)&Arow[kn + ak + 4];
            b0 = *(const float4*)&W[(size_t)(kn + bk) * 256 + n0 + bn];
            b1 = *(const float4*)&W[(size_t)(kn + bk) * 256 + n0 + bn + 4];
        }
        G_MMA(0);
        G_STAGE(1);
        __syncthreads();
        if (k0 < 14) {
            int kn = (k0 + 2) * 16;
            a0 = *(const float4*)&Arow[kn + ak];
            a1 = *(const float4*)&Arow[kn + ak + 4];
            b0 = *(const float4*)&W[(size_t)(kn + bk) * 256 + n0 + bn];
            b1 = *(const float4*)&W[(size_t)(kn + bk) * 256 + n0 + bn + 4];
        }
        G_MMA(1);
    }

#pragma unroll
    for (int nj = 0; nj < 8; nj++) {
        int col = n0 + wn * 64 + nj * 8 + tg * 2;
        float bv0 = __ldg(&bias[col]);
        float bv1 = __ldg(&bias[col + 1]);
#pragma unroll
        for (int mi = 0; mi < 2; mi++) {
            int row = m0 + wm * 32 + mi * 16 + g;
            float4 d = acc[mi][nj];
            float v0 = d.x + bv0, v1 = d.y + bv1;
            float v2 = d.z + bv0, v3 = d.w + bv1;
            if (ELU) { v0 = eluf(v0); v1 = eluf(v1); v2 = eluf(v2); v3 = eluf(v3); }
            float2 s0; s0.x = v0; s0.y = v1;
            float2 s1; s1.x = v2; s1.y = v3;
            *(float2*)&C[(size_t)row * 256 + col]       = s0;
            *(float2*)&C[(size_t)(row + 8) * 256 + col] = s1;
        }
    }
}

// ============================================================================
// GEMM-PW (TF32): out[M,128] = endg*(elu(DW[M,192]@pwW[192,128]+pwb)*BNI)+endbe
// ============================================================================
__global__ void __launch_bounds__(256, 2) gemm_pw_tf32(
    const float* __restrict__ pwW, const float* __restrict__ pwb,
    const float* __restrict__ endg, const float* __restrict__ endbe,
    float* __restrict__ out)
{
    __shared__ u32 As[2][128][20];
    __shared__ u32 Bs[2][16][136];
    const int t  = threadIdx.x;
    const int m0 = blockIdx.x << 7;
    const int n0 = 0;
    const int wid = t >> 5, lane = t & 31;
    const int wm = wid >> 1, wn = wid & 1;
    const int g = lane >> 2, tg = lane & 3;

    float4 acc[2][8];
#pragma unroll
    for (int i = 0; i < 2; i++)
#pragma unroll
        for (int j = 0; j < 8; j++) acc[i][j] = make_float4(0.f, 0.f, 0.f, 0.f);

    const int ar = t >> 1, ak = (t & 1) * 8;
    const int bk = t >> 4, bn = (t & 15) * 8;
    const float* Arow = g_DW + (size_t)(m0 + ar) * 192;

    float4 a0 = *(const float4*)&Arow[ak];
    float4 a1 = *(const float4*)&Arow[ak + 4];
    float4 b0 = *(const float4*)&pwW[(size_t)bk * 128 + bn];
    float4 b1 = *(const float4*)&pwW[(size_t)bk * 128 + bn + 4];

#pragma unroll 1
    for (int k0 = 0; k0 < 12; k0 += 2) {
        G_STAGE(0);
        __syncthreads();
        {
            int kn = (k0 + 1) * 16;
            a0 = *(const float4*)&Arow[kn + ak];
            a1 = *(const float4*)&Arow[kn + ak + 4];
            b0 = *(const float4*)&pwW[(size_t)(kn + bk) * 128 + bn];
            b1 = *(const float4*)&pwW[(size_t)(kn + bk) * 128 + bn + 4];
        }
        G_MMA(0);
        G_STAGE(1);
        __syncthreads();
        if (k0 < 10) {
            int kn = (k0 + 2) * 16;
            a0 = *(const float4*)&Arow[kn + ak];
            a1 = *(const float4*)&Arow[kn + ak + 4];
            b0 = *(const float4*)&pwW[(size_t)(kn + bk) * 128 + bn];
            b1 = *(const float4*)&pwW[(size_t)(kn + bk) * 128 + bn + 4];
        }
        G_MMA(1);
    }

#pragma unroll
    for (int nj = 0; nj < 8; nj++) {
        int col = wn * 64 + nj * 8 + tg * 2;
        float bv0 = __ldg(&pwb[col]),   bv1 = __ldg(&pwb[col + 1]);
        float gv0 = __ldg(&endg[col]),  gv1 = __ldg(&endg[col + 1]);
        float ev0 = __ldg(&endbe[col]), ev1 = __ldg(&endbe[col + 1]);
#pragma unroll
        for (int mi = 0; mi < 2; mi++) {
            int row = m0 + wm * 32 + mi * 16 + g;
            float4 d = acc[mi][nj];
            float2 s0, s1;
            s0.x = gv0 * (eluf(d.x + bv0) * BNI) + ev0;
            s0.y = gv1 * (eluf(d.y + bv1) * BNI) + ev1;
            s1.x = gv0 * (eluf(d.z + bv0) * BNI) + ev0;
            s1.y = gv1 * (eluf(d.w + bv1) * BNI) + ev1;
            *(float2*)&out[(size_t)row * 128 + col]       = s0;
            *(float2*)&out[(size_t)(row + 8) * 128 + col] = s1;
        }
    }
}

// ============================================================================
// Kernel E (mega-epilogue): gather ftsl + lift MLP + F (tensor mma) + G1
// ============================================================================
#define EPI_SM (24480 * 4)

__global__ void __launch_bounds__(256, 2) epi_kernel(
    const int* __restrict__ pts_idx,
    const float* __restrict__ d1W, const float* __restrict__ d1b,
    const float* __restrict__ d1g, const float* __restrict__ d1be,
    const float* __restrict__ d2W, const float* __restrict__ d2b,
    const float* __restrict__ d2g, const float* __restrict__ d2be,
    const float* __restrict__ dwW, const float* __restrict__ dwb)
{
    extern __shared__ float sm[];
    float* XA    = sm;            // [8][256]  X2
    float* FC    = sm + 2048;     // [8][16][FCS]
    float* H     = sm + 14848;    // [32][128]
    float* SDW   = sm + 18944;    // dw pairs
    float* SD1W  = sm + 22016; float* SD1B  = sm + 22112;
    float* SD1G  = sm + 22144; float* SD1BE = sm + 22176;
    float* SD2Wd = sm + 22208;
    float* SD2B  = sm + 24256; float* SD2G  = sm + 24288;
    float* SD2BE = sm + 24320;
    int*   SIDX  = (int*)(sm + 24352);

    const int t   = threadIdx.x;
    const int gp0 = blockIdx.x * TILEP;
    const int n   = gp0 >> 10;

    // ---- phase 0: indices, weights, X2 ----
    if (t < 128) SIDX[t] = pts_idx[(size_t)gp0 * 16 + t];
    for (int u = t; u < 96; u += 256) SD1W[u] = d1W[u];
    for (int u = t; u < 1024; u += 256) {
        float w = d2W[u];
        SD2Wd[2 * u] = w; SD2Wd[2 * u + 1] = w;
    }
    if (t < 32) {
        SD1B[t] = d1b[t]; SD1G[t] = d1g[t]; SD1BE[t] = d1be[t];
        SD2B[t] = d2b[t]; SD2G[t] = d2g[t]; SD2BE[t] = d2be[t];
    }
    for (int idx = t; idx < 1536; idx += 256) {
        int k = idx / 96, c = idx - k * 96;
        float2 w;
        w.x = dwW[c * 32 + k];
        w.y = dwW[c * 32 + 16 + k];
        *(float2*)&SDW[idx * 2] = w;
    }
    {
        const float4* src = (const float4*)(g_X2 + (size_t)gp0 * 256);
        float4* dst = (float4*)XA;
        dst[t] = src[t];
        dst[t + 256] = src[t + 256];
    }
    __syncthreads();

    // ---- phase 1: gather ftsl -> FC[:,32:96]; E1 -> H ----
    {
        int row = t >> 1, half = t & 1;
        int gi = SIDX[row];
        const float4* src = (const float4*)(g_ftsl + ((size_t)n * NUMPTS + gi) * 64 + half * 32);
        float4* dst = (float4*)&FC[row * FCS + 32 + half * 32];
#pragma unroll
        for (int u = 0; u < 8; u++) dst[u] = src[u];
    }
    {
        const int row = t & 127, hc = t >> 7;
        const int i = row >> 4, k = row & 15;
        const float* pl = g_PLS + (size_t)(gp0 + i) * 48;
        float px = __ldg(&pl[k]);
        float py = __ldg(&pl[16 + k]);
        float pz = __ldg(&pl[32 + k]);
#pragma unroll
        for (int u = 0; u < 16; u++) {
            int c = hc * 16 + u;
            float v = fmaf(px, SD1W[c], fmaf(py, SD1W[32 + c],
                      fmaf(pz, SD1W[64 + c], SD1B[c])));
            H[c * 128 + row] = SD1G[c] * (eluf(v) * BNI) + SD1BE[c];
        }
    }
    __syncthreads();

    // ---- E2: dense2 (32 -> 32), row-pair packed fma2 -> FC[:,0:32] ----
    {
        const int rp = t & 63, cg = t >> 6;
        const int row0 = 2 * rp, c0 = cg * 8;
        u64 acc[8];
#pragma unroll
        for (int u = 0; u < 8; u++) acc[u] = dup2(SD2B[c0 + u]);
#pragma unroll 4
        for (int c = 0; c < 32; c++) {
            u64 hv = *(const u64*)&H[c * 128 + row0];
            const ulonglong2* wd = (const ulonglong2*)&SD2Wd[c * 64 + 2 * c0];
            ulonglong2 w0 = wd[0], w1 = wd[1], w2 = wd[2], w3 = wd[3];
            acc[0] = fma2(hv, w0.x, acc[0]); acc[1] = fma2(hv, w0.y, acc[1]);
            acc[2] = fma2(hv, w1.x, acc[2]); acc[3] = fma2(hv, w1.y, acc[3]);
            acc[4] = fma2(hv, w2.x, acc[4]); acc[5] = fma2(hv, w2.y, acc[5]);
            acc[6] = fma2(hv, w3.x, acc[6]); acc[7] = fma2(hv, w3.y, acc[7]);
        }
#pragma unroll
        for (int u = 0; u < 8; u++) {
            int c = c0 + u;
            float2 f = unpk(acc[u]);
            FC[row0 * FCS + c]       = SD2G[c] * (eluf(f.x) * BNI) + SD2BE[c];
            FC[(row0 + 1) * FCS + c] = SD2G[c] * (eluf(f.y) * BNI) + SD2BE[c];
        }
    }
    __syncthreads();

    const int i = t >> 5, lane = t & 31;
    const int g = lane >> 2, tg = lane & 3;

    // ---- Phase F (tensor): fts_X[16,96] = X2[16,16] @ FC[16,96] per point ----
    // warp i owns point i: reads + writes are warp-exclusive, results staged
    // in registers so the in-place update is safe without a barrier.
    {
        const float* X2 = &XA[i * 256];
        u32 af[2][4];
#pragma unroll
        for (int kc = 0; kc < 2; kc++) {
            int kb = kc * 8;
            af[kc][0] = tf32(X2[(g)     * 16 + kb + tg]);
            af[kc][1] = tf32(X2[(g + 8) * 16 + kb + tg]);
            af[kc][2] = tf32(X2[(g)     * 16 + kb + tg + 4]);
            af[kc][3] = tf32(X2[(g + 8) * 16 + kb + tg + 4]);
        }
        float4 dacc[12];
#pragma unroll
        for (int nj = 0; nj < 12; nj++) {
            dacc[nj] = make_float4(0.f, 0.f, 0.f, 0.f);
            int cn = nj * 8 + g;
#pragma unroll
            for (int kc = 0; kc < 2; kc++) {
                int kb = kc * 8;
                u32 bf0 = tf32(FC[(i * 16 + kb + tg)     * FCS + cn]);
                u32 bf1 = tf32(FC[(i * 16 + kb + tg + 4) * FCS + cn]);
                mma8(dacc[nj], af[kc], bf0, bf1);
            }
        }
        __syncwarp();
#pragma unroll
        for (int nj = 0; nj < 12; nj++) {
            int c = nj * 8 + tg * 2;
            float2 s0; s0.x = dacc[nj].x; s0.y = dacc[nj].y;
            float2 s1; s1.x = dacc[nj].z; s1.y = dacc[nj].w;
            *(float2*)&FC[(i * 16 + g)     * FCS + c] = s0;
            *(float2*)&FC[(i * 16 + g + 8) * FCS + c] = s1;
        }
        __syncwarp();
    }

    // ---- Phase G1: depthwise, m-paired fma2 -> g_DW (warp-local FC reads) ----
    {
#pragma unroll
        for (int u = 0; u < 3; u++) {
            int c = lane + 32 * u;
            u64 acc = *(const u64*)&dwb[2 * c];
#pragma unroll
            for (int k = 0; k < 16; k++) {
                u64 fd = dup2(FC[(i * 16 + k) * FCS + c]);
                u64 wd = *(const u64*)&SDW[(k * 96 + c) * 2];
                acc = fma2(fd, wd, acc);
            }
            *(u64*)&g_DW[(size_t)(gp0 + i) * 192 + 2 * c] = acc;
        }
    }
}

// ============================================================================
extern "C" void kernel_launch(void* const* d_in, const int* in_sizes, int n_in,
                              void* d_out, int out_size)
{
    const float* rep_pts = (const float*)d_in[0];
    const float* pts     = (const float*)d_in[1];
    const float* fts     = (const float*)d_in[2];
    const int*   pts_idx = (const int*)d_in[3];
    const float* d0W  = (const float*)d_in[4];
    const float* d0b  = (const float*)d_in[5];
    const float* d0g  = (const float*)d_in[6];
    const float* d0be = (const float*)d_in[7];
    const float* d1W  = (const float*)d_in[8];
    const float* d1b  = (const float*)d_in[9];
    const float* d1g  = (const float*)d_in[10];
    const float* d1be = (const float*)d_in[11];
    const float* d2W  = (const float*)d_in[12];
    const float* d2b  = (const float*)d_in[13];
    const float* d2g  = (const float*)d_in[14];
    const float* d2be = (const float*)d_in[15];
    const float* xcW  = (const float*)d_in[16];
    const float* xcb  = (const float*)d_in[17];
    const float* xd1W = (const float*)d_in[18];
    const float* xd1b = (const float*)d_in[19];
    const float* xd2W = (const float*)d_in[20];
    const float* xd2b = (const float*)d_in[21];
    const float* dwW  = (const float*)d_in[22];
    const float* dwb  = (const float*)d_in[23];
    const float* pwW  = (const float*)d_in[24];
    const float* pwb  = (const float*)d_in[25];
    const float* endg = (const float*)d_in[26];
    const float* endbe= (const float*)d_in[27];
    float* out = (float*)d_out;

    float *pX0, *pX1, *pX2;
    cudaGetSymbolAddress((void**)&pX0, g_X0);
    cudaGetSymbolAddress((void**)&pX1, g_X1);
    cudaGetSymbolAddress((void**)&pX2, g_X2);

    dense0_kernel<<<4096, 256>>>(fts, d0W, d0b, d0g, d0be);
    coords_kernel<<<2048, 256>>>(rep_pts, pts, pts_idx);

    cudaFuncSetAttribute(gemmX0_tf32,
                         cudaFuncAttributeMaxDynamicSharedMemorySize, X0_SMEM);
    dim3 xgrid(2, 256);
    gemmX0_tf32<<<xgrid, 256, X0_SMEM>>>(xcW, xcb, pX0);

    dim3 ggrid(2, 256);
    gemm256_tf32<true><<<ggrid, 256>>>(pX0, xd1W, xd1b, pX1);
    gemm256_tf32<false><<<ggrid, 256>>>(pX1, xd2W, xd2b, pX2);

    cudaFuncSetAttribute(epi_kernel,
                         cudaFuncAttributeMaxDynamicSharedMemorySize, EPI_SM);
    epi_kernel<<<32768 / TILEP, 256, EPI_SM>>>(
        pts_idx, d1W, d1b, d1g, d1be, d2W, d2b, d2g, d2be, dwW, dwb);

    gemm_pw_tf32<<<256, 256>>>(pwW, pwb, endg, endbe, out);
}

// round 14
// speedup vs baseline: 2.1000x; 1.0252x over previous
#include <cuda_runtime.h>
#include <math.h>

typedef unsigned long long u64;
typedef unsigned int u32;

// ---- problem dims ----
#define NB      32
#define NUMPTS  2048
#define PN      1024
#define TILEP   8
#define FCS     100
#define BNI     0.9999950000374996f

// scratch
__device__ float g_ftsl[NB * NUMPTS * 64];
__device__ float g_PLS[(size_t)32768 * 48];
__device__ float g_X0 [32768 * 256];
__device__ float g_X1 [32768 * 256];
__device__ float g_X2 [32768 * 256];
__device__ float g_DW [(size_t)32768 * 192];
__device__ float g_W1t[256 * 256];
__device__ float g_W2t[256 * 256];
__device__ float g_pWt[192 * 128];

__device__ __forceinline__ float eluf(float x) {
    return x > 0.0f ? x : expm1f(x);
}
__device__ __forceinline__ u64 fma2(u64 a, u64 b, u64 c) {
    u64 d; asm("fma.rn.f32x2 %0,%1,%2,%3;" : "=l"(d) : "l"(a), "l"(b), "l"(c)); return d;
}
__device__ __forceinline__ u64 dup2(float x) {
    u64 d; asm("mov.b64 %0,{%1,%1};" : "=l"(d) : "f"(x)); return d;
}
__device__ __forceinline__ float2 unpk(u64 v) {
    float2 r; asm("mov.b64 {%0,%1},%2;" : "=f"(r.x), "=f"(r.y) : "l"(v)); return r;
}
__device__ __forceinline__ u32 tf32(float f) {
    u32 o; asm("cvt.rna.tf32.f32 %0, %1;" : "=r"(o) : "f"(f)); return o;
}
__device__ __forceinline__ float tf32f(float f) {
    return __uint_as_float(tf32(f));
}
__device__ __forceinline__ void mma8(float4& d, const u32* a, u32 b0, u32 b1) {
    asm("mma.sync.aligned.m16n8k8.row.col.f32.tf32.tf32.f32 "
        "{%0,%1,%2,%3}, {%4,%5,%6,%7}, {%8,%9}, {%0,%1,%2,%3};"
        : "+f"(d.x), "+f"(d.y), "+f"(d.z), "+f"(d.w)
        : "r"(a[0]), "r"(a[1]), "r"(a[2]), "r"(a[3]), "r"(b0), "r"(b1));
}

// ============================================================================
// Kernel A: dense0 -> g_ftsl
// ============================================================================
__global__ void __launch_bounds__(256) dense0_kernel(
    const float* __restrict__ fts, const float* __restrict__ W,
    const float* __restrict__ b,   const float* __restrict__ g,
    const float* __restrict__ be)
{
    __shared__ float Ws[64 * 64];
    __shared__ float xs[16 * 64];
    const int t = threadIdx.x;
    const size_t row0 = (size_t)blockIdx.x * 16;

#pragma unroll
    for (int u = 0; u < 16; u++) Ws[t + 256 * u] = W[t + 256 * u];
    ((float4*)xs)[t] = ((const float4*)(fts + row0 * 64))[t];
    __syncthreads();

    const int r  = t >> 4;
    const int cb = (t & 15) * 4;
    u64 a0 = 0ull, a1 = 0ull;
#pragma unroll 8
    for (int k = 0; k < 64; k++) {
        u64 xd = dup2(xs[r * 64 + k]);
        ulonglong2 w = *(const ulonglong2*)&Ws[k * 64 + cb];
        a0 = fma2(xd, w.x, a0);
        a1 = fma2(xd, w.y, a1);
    }
    float2 f0 = unpk(a0), f1 = unpk(a1);
    float4 b4 = *(const float4*)&b[cb];
    float4 g4 = *(const float4*)&g[cb];
    float4 e4 = *(const float4*)&be[cb];
    float4 o;
    o.x = g4.x * (eluf(f0.x + b4.x) * BNI) + e4.x;
    o.y = g4.y * (eluf(f0.y + b4.y) * BNI) + e4.y;
    o.z = g4.z * (eluf(f1.x + b4.z) * BNI) + e4.z;
    o.w = g4.w * (eluf(f1.y + b4.w) * BNI) + e4.w;
    *(float4*)&g_ftsl[(row0 + r) * 64 + cb] = o;
}

// ============================================================================
// Kernel C (coords): gather neighbor coords -> g_PLS
// ============================================================================
__global__ void __launch_bounds__(256) coords_kernel(
    const float* __restrict__ rep_pts, const float* __restrict__ pts,
    const int* __restrict__ pts_idx)
{
    int idx = blockIdx.x * 256 + threadIdx.x;
    int pt = idx >> 4, k = idx & 15;
    int n = pt >> 10;
    int gi = pts_idx[idx];
    const float* pp = pts + ((size_t)n * NUMPTS + gi) * 3;
    const float* rp = rep_pts + (size_t)pt * 3;
    float* dst = g_PLS + (size_t)pt * 48;
    dst[k]      = pp[0] - rp[0];
    dst[16 + k] = pp[1] - rp[1];
    dst[32 + k] = pp[2] - rp[2];
}

// ============================================================================
// Kernel W: pre-round GEMM weights to tf32 bit patterns
// ============================================================================
__global__ void __launch_bounds__(256) cvt_weights(
    const float* __restrict__ xd1W, const float* __restrict__ xd2W,
    const float* __restrict__ pwW)
{
    int idx = blockIdx.x * 256 + threadIdx.x;       // 0..65535
    g_W1t[idx] = tf32f(xd1W[idx]);
    g_W2t[idx] = tf32f(xd2W[idx]);
    if (idx < 192 * 128) g_pWt[idx] = tf32f(pwW[idx]);
}

// ============================================================================
// GEMM-X0 (TF32): X0[M,256] = tf32(elu(PLS[M,48] @ xcW^T + xcb))
// ============================================================================
#define X0_SMEM ((128 * 52 + 48 * 136) * 4)

__global__ void __launch_bounds__(256, 2) gemmX0_tf32(
    const float* __restrict__ xcW, const float* __restrict__ xcb,
    float* __restrict__ X0)
{
    extern __shared__ u32 smx[];
    u32 (*As)[52]  = (u32(*)[52])smx;
    u32 (*Bs)[136] = (u32(*)[136])(smx + 128 * 52);

    const int t  = threadIdx.x;
    const int m0 = blockIdx.y << 7;
    const int n0 = blockIdx.x << 7;
    const int wid = t >> 5, lane = t & 31;
    const int wm = wid >> 1, wn = wid & 1;
    const int g = lane >> 2, tg = lane & 3;

    {
        const int ar = t >> 1, ah = (t & 1) * 24;
        const float* Ar = g_PLS + (size_t)(m0 + ar) * 48 + ah;
#pragma unroll
        for (int v = 0; v < 6; v++) {
            float4 a = *(const float4*)&Ar[v * 4];
            u32* ap = &As[ar][ah + v * 4];
            ap[0] = tf32(a.x); ap[1] = tf32(a.y);
            ap[2] = tf32(a.z); ap[3] = tf32(a.w);
        }
    }
    {
        const int q = t >> 1, kh = (t & 1) * 24;
        const float* Wr = xcW + (size_t)(n0 + q) * 48 + kh;
#pragma unroll
        for (int v = 0; v < 6; v++) {
            float4 w = *(const float4*)&Wr[v * 4];
            Bs[kh + v * 4 + 0][q] = tf32(w.x);
            Bs[kh + v * 4 + 1][q] = tf32(w.y);
            Bs[kh + v * 4 + 2][q] = tf32(w.z);
            Bs[kh + v * 4 + 3][q] = tf32(w.w);
        }
    }
    __syncthreads();

    float4 acc[2][8];
#pragma unroll
    for (int i = 0; i < 2; i++)
#pragma unroll
        for (int j = 0; j < 8; j++) acc[i][j] = make_float4(0.f, 0.f, 0.f, 0.f);

#pragma unroll
    for (int kc = 0; kc < 6; kc++) {
        const int kb = kc * 8;
        u32 af[2][4];
#pragma unroll
        for (int mi = 0; mi < 2; mi++) {
            int r = wm * 32 + mi * 16;
            af[mi][0] = As[r + g][kb + tg];
            af[mi][1] = As[r + g + 8][kb + tg];
            af[mi][2] = As[r + g][kb + tg + 4];
            af[mi][3] = As[r + g + 8][kb + tg + 4];
        }
#pragma unroll
        for (int nj = 0; nj < 8; nj++) {
            int cn = wn * 64 + nj * 8 + g;
            u32 bf0 = Bs[kb + tg][cn];
            u32 bf1 = Bs[kb + tg + 4][cn];
            mma8(acc[0][nj], af[0], bf0, bf1);
            mma8(acc[1][nj], af[1], bf0, bf1);
        }
    }

#pragma unroll
    for (int nj = 0; nj < 8; nj++) {
        int col = n0 + wn * 64 + nj * 8 + tg * 2;
        float bv0 = __ldg(&xcb[col]);
        float bv1 = __ldg(&xcb[col + 1]);
#pragma unroll
        for (int mi = 0; mi < 2; mi++) {
            int row = m0 + wm * 32 + mi * 16 + g;
            float4 d = acc[mi][nj];
            float2 s0, s1;
            s0.x = tf32f(eluf(d.x + bv0)); s0.y = tf32f(eluf(d.y + bv1));
            s1.x = tf32f(eluf(d.z + bv0)); s1.y = tf32f(eluf(d.w + bv1));
            *(float2*)&X0[(size_t)row * 256 + col]       = s0;
            *(float2*)&X0[(size_t)(row + 8) * 256 + col] = s1;
        }
    }
}

// ============================================================================
// GEMM mainloop macros. RAW: operands pre-rounded (pure copy).
// ACVT: round A only (B pre-rounded).
// ============================================================================
#define G_STAGE_RAW(BUF) do {                                                 \
    *(uint4*)&As[BUF][ar][ak]     = *(uint4*)&a0;                             \
    *(uint4*)&As[BUF][ar][ak + 4] = *(uint4*)&a1;                             \
    *(uint4*)&Bs[BUF][bk][bn]     = *(uint4*)&b0;                             \
    *(uint4*)&Bs[BUF][bk][bn + 4] = *(uint4*)&b1;                             \
} while (0)

#define G_STAGE_ACVT(BUF) do {                                                \
    u32 av[8];                                                                \
    av[0] = tf32(a0.x); av[1] = tf32(a0.y);                                   \
    av[2] = tf32(a0.z); av[3] = tf32(a0.w);                                   \
    av[4] = tf32(a1.x); av[5] = tf32(a1.y);                                   \
    av[6] = tf32(a1.z); av[7] = tf32(a1.w);                                   \
    *(uint4*)&As[BUF][ar][ak]     = *(uint4*)&av[0];                          \
    *(uint4*)&As[BUF][ar][ak + 4] = *(uint4*)&av[4];                          \
    *(uint4*)&Bs[BUF][bk][bn]     = *(uint4*)&b0;                             \
    *(uint4*)&Bs[BUF][bk][bn + 4] = *(uint4*)&b1;                             \
} while (0)

#define G_MMA(BUF) do {                                                       \
    _Pragma("unroll")                                                         \
    for (int kk = 0; kk < 2; kk++) {                                          \
        const int kb = kk * 8;                                                \
        u32 af[2][4];                                                         \
        _Pragma("unroll")                                                     \
        for (int mi = 0; mi < 2; mi++) {                                      \
            int r = wm * 32 + mi * 16;                                        \
            af[mi][0] = As[BUF][r + g][kb + tg];                              \
            af[mi][1] = As[BUF][r + g + 8][kb + tg];                          \
            af[mi][2] = As[BUF][r + g][kb + tg + 4];                          \
            af[mi][3] = As[BUF][r + g + 8][kb + tg + 4];                      \
        }                                                                     \
        _Pragma("unroll")                                                     \
        for (int nj = 0; nj < 8; nj++) {                                      \
            int cn = wn * 64 + nj * 8 + g;                                    \
            u32 bf0 = Bs[BUF][kb + tg][cn];                                   \
            u32 bf1 = Bs[BUF][kb + tg + 4][cn];                               \
            mma8(acc[0][nj], af[0], bf0, bf1);                                \
            mma8(acc[1][nj], af[1], bf0, bf1);                                \
        }                                                                     \
    }                                                                         \
} while (0)

// ============================================================================
// GEMM (TF32): C[M,256] = act(A[M,256] @ W[256,256] + bias); inputs pre-rounded
// ============================================================================
template<bool ELU>
__global__ void __launch_bounds__(256, 2) gemm256_tf32(
    const float* __restrict__ A, const float* __restrict__ W,
    const float* __restrict__ bias, float* __restrict__ C)
{
    __shared__ u32 As[2][128][20];
    __shared__ u32 Bs[2][16][136];
    const int t  = threadIdx.x;
    const int m0 = blockIdx.y << 7;
    const int n0 = blockIdx.x << 7;
    const int wid = t >> 5, lane = t & 31;
    const int wm = wid >> 1, wn = wid & 1;
    const int g = lane >> 2, tg = lane & 3;

    float4 acc[2][8];
#pragma unroll
    for (int i = 0; i < 2; i++)
#pragma unroll
        for (int j = 0; j < 8; j++) acc[i][j] = make_float4(0.f, 0.f, 0.f, 0.f);

    const int ar = t >> 1, ak = (t & 1) * 8;
    const int bk = t >> 4, bn = (t & 15) * 8;
    const float* Arow = A + (size_t)(m0 + ar) * 256;

    float4 a0 = *(const float4*)&Arow[ak];
    float4 a1 = *(const float4*)&Arow[ak + 4];
    float4 b0 = *(const float4*)&W[(size_t)bk * 256 + n0 + bn];
    float4 b1 = *(const float4*)&W[(size_t)bk * 256 + n0 + bn + 4];

#pragma unroll 1
    for (int k0 = 0; k0 < 16; k0 += 2) {
        G_STAGE_RAW(0);
        __syncthreads();
        {
            int kn = (k0 + 1) * 16;
            a0 = *(const float4*)&Arow[kn + ak];
            a1 = *(const float4*)&Arow[kn + ak + 4];
            b0 = *(const float4*)&W[(size_t)(kn + bk) * 256 + n0 + bn];
            b1 = *(const float4*)&W[(size_t)(kn + bk) * 256 + n0 + bn + 4];
        }
        G_MMA(0);
        G_STAGE_RAW(1);
        __syncthreads();
        if (k0 < 14) {
            int kn = (k0 + 2) * 16;
            a0 = *(const float4*)&Arow[kn + ak];
            a1 = *(const float4*)&Arow[kn + ak + 4];
            b0 = *(const float4*)&W[(size_t)(kn + bk) * 256 + n0 + bn];
            b1 = *(const float4*)&W[(size_t)(kn + bk) * 256 + n0 + bn + 4];
        }
        G_MMA(1);
    }

#pragma unroll
    for (int nj = 0; nj < 8; nj++) {
        int col = n0 + wn * 64 + nj * 8 + tg * 2;
        float bv0 = __ldg(&bias[col]);
        float bv1 = __ldg(&bias[col + 1]);
#pragma unroll
        for (int mi = 0; mi < 2; mi++) {
            int row = m0 + wm * 32 + mi * 16 + g;
            float4 d = acc[mi][nj];
            float v0 = d.x + bv0, v1 = d.y + bv1;
            float v2 = d.z + bv0, v3 = d.w + bv1;
            if (ELU) {
                v0 = tf32f(eluf(v0)); v1 = tf32f(eluf(v1));
                v2 = tf32f(eluf(v2)); v3 = tf32f(eluf(v3));
            }
            float2 s0; s0.x = v0; s0.y = v1;
            float2 s1; s1.x = v2; s1.y = v3;
            *(float2*)&C[(size_t)row * 256 + col]       = s0;
            *(float2*)&C[(size_t)(row + 8) * 256 + col] = s1;
        }
    }
}

// ============================================================================
// GEMM-PW (TF32): out = endg*(elu(DW[M,192]@pWt[192,128]+pwb)*BNI)+endbe
// ============================================================================
__global__ void __launch_bounds__(256, 2) gemm_pw_tf32(
    const float* __restrict__ pwb,
    const float* __restrict__ endg, const float* __restrict__ endbe,
    float* __restrict__ out)
{
    __shared__ u32 As[2][128][20];
    __shared__ u32 Bs[2][16][136];
    const int t  = threadIdx.x;
    const int m0 = blockIdx.x << 7;
    const int wid = t >> 5, lane = t & 31;
    const int wm = wid >> 1, wn = wid & 1;
    const int g = lane >> 2, tg = lane & 3;

    float4 acc[2][8];
#pragma unroll
    for (int i = 0; i < 2; i++)
#pragma unroll
        for (int j = 0; j < 8; j++) acc[i][j] = make_float4(0.f, 0.f, 0.f, 0.f);

    const int ar = t >> 1, ak = (t & 1) * 8;
    const int bk = t >> 4, bn = (t & 15) * 8;
    const float* Arow = g_DW + (size_t)(m0 + ar) * 192;

    float4 a0 = *(const float4*)&Arow[ak];
    float4 a1 = *(const float4*)&Arow[ak + 4];
    float4 b0 = *(const float4*)&g_pWt[(size_t)bk * 128 + bn];
    float4 b1 = *(const float4*)&g_pWt[(size_t)bk * 128 + bn + 4];

#pragma unroll 1
    for (int k0 = 0; k0 < 12; k0 += 2) {
        G_STAGE_ACVT(0);
        __syncthreads();
        {
            int kn = (k0 + 1) * 16;
            a0 = *(const float4*)&Arow[kn + ak];
            a1 = *(const float4*)&Arow[kn + ak + 4];
            b0 = *(const float4*)&g_pWt[(size_t)(kn + bk) * 128 + bn];
            b1 = *(const float4*)&g_pWt[(size_t)(kn + bk) * 128 + bn + 4];
        }
        G_MMA(0);
        G_STAGE_ACVT(1);
        __syncthreads();
        if (k0 < 10) {
            int kn = (k0 + 2) * 16;
            a0 = *(const float4*)&Arow[kn + ak];
            a1 = *(const float4*)&Arow[kn + ak + 4];
            b0 = *(const float4*)&g_pWt[(size_t)(kn + bk) * 128 + bn];
            b1 = *(const float4*)&g_pWt[(size_t)(kn + bk) * 128 + bn + 4];
        }
        G_MMA(1);
    }

#pragma unroll
    for (int nj = 0; nj < 8; nj++) {
        int col = wn * 64 + nj * 8 + tg * 2;
        float bv0 = __ldg(&pwb[col]),   bv1 = __ldg(&pwb[col + 1]);
        float gv0 = __ldg(&endg[col]),  gv1 = __ldg(&endg[col + 1]);
        float ev0 = __ldg(&endbe[col]), ev1 = __ldg(&endbe[col + 1]);
#pragma unroll
        for (int mi = 0; mi < 2; mi++) {
            int row = m0 + wm * 32 + mi * 16 + g;
            float4 d = acc[mi][nj];
            float2 s0, s1;
            s0.x = gv0 * (eluf(d.x + bv0) * BNI) + ev0;
            s0.y = gv1 * (eluf(d.y + bv1) * BNI) + ev1;
            s1.x = gv0 * (eluf(d.z + bv0) * BNI) + ev0;
            s1.y = gv1 * (eluf(d.w + bv1) * BNI) + ev1;
            *(float2*)&out[(size_t)row * 128 + col]       = s0;
            *(float2*)&out[(size_t)(row + 8) * 128 + col] = s1;
        }
    }
}

// ============================================================================
// Kernel E (mega-epilogue): gather ftsl + E1 + E2 (tensor) + F (tensor) + G1
// smem (floats):
//   XA [8][256] @0 | FC [8][16][FCS] @2048 | H [32][128] @14848
//   SDW @18944 (3072) | SD1W @22016(96) SD1B @22112 SD1G @22144 SD1BE @22176
//   SD2W @22208 (1024, tf32) | SD2B @23232 SD2G @23264 SD2BE @23296
//   SIDX @23328 (128)
// total 23456 floats = 93824 B
// ============================================================================
#define EPI_SM (23456 * 4)

__global__ void __launch_bounds__(256, 2) epi_kernel(
    const int* __restrict__ pts_idx,
    const float* __restrict__ d1W, const float* __restrict__ d1b,
    const float* __restrict__ d1g, const float* __restrict__ d1be,
    const float* __restrict__ d2W, const float* __restrict__ d2b,
    const float* __restrict__ d2g, const float* __restrict__ d2be,
    const float* __restrict__ dwW, const float* __restrict__ dwb)
{
    extern __shared__ float sm[];
    float* XA    = sm;            // [8][256]  X2
    float* FC    = sm + 2048;     // [8][16][FCS]
    float* H     = sm + 14848;    // [32][128] (tf32-rounded)
    float* SDW   = sm + 18944;    // dw pairs
    float* SD1W  = sm + 22016; float* SD1B  = sm + 22112;
    float* SD1G  = sm + 22144; float* SD1BE = sm + 22176;
    float* SD2W  = sm + 22208;    // [32][32] tf32-rounded
    float* SD2B  = sm + 23232; float* SD2G  = sm + 23264;
    float* SD2BE = sm + 23296;
    int*   SIDX  = (int*)(sm + 23328);

    const int t   = threadIdx.x;
    const int gp0 = blockIdx.x * TILEP;
    const int n   = gp0 >> 10;

    // ---- phase 0: indices, weights, X2 ----
    if (t < 128) SIDX[t] = pts_idx[(size_t)gp0 * 16 + t];
    for (int u = t; u < 96; u += 256) SD1W[u] = d1W[u];
    for (int u = t; u < 1024; u += 256) SD2W[u] = tf32f(d2W[u]);
    if (t < 32) {
        SD1B[t] = d1b[t]; SD1G[t] = d1g[t]; SD1BE[t] = d1be[t];
        SD2B[t] = d2b[t]; SD2G[t] = d2g[t]; SD2BE[t] = d2be[t];
    }
    for (int idx = t; idx < 1536; idx += 256) {
        int k = idx / 96, c = idx - k * 96;
        float2 w;
        w.x = dwW[c * 32 + k];
        w.y = dwW[c * 32 + 16 + k];
        *(float2*)&SDW[idx * 2] = w;
    }
    {
        const float4* src = (const float4*)(g_X2 + (size_t)gp0 * 256);
        float4* dst = (float4*)XA;
        dst[t] = src[t];
        dst[t + 256] = src[t + 256];
    }
    __syncthreads();

    // ---- phase 1: gather ftsl -> FC[:,32:96]; E1 -> H (tf32-rounded) ----
    {
        int row = t >> 1, half = t & 1;
        int gi = SIDX[row];
        const float4* src = (const float4*)(g_ftsl + ((size_t)n * NUMPTS + gi) * 64 + half * 32);
        float4* dst = (float4*)&FC[row * FCS + 32 + half * 32];
#pragma unroll
        for (int u = 0; u < 8; u++) dst[u] = src[u];
    }
    {
        const int row = t & 127, hc = t >> 7;
        const int i = row >> 4, k = row & 15;
        const float* pl = g_PLS + (size_t)(gp0 + i) * 48;
        float px = __ldg(&pl[k]);
        float py = __ldg(&pl[16 + k]);
        float pz = __ldg(&pl[32 + k]);
#pragma unroll
        for (int u = 0; u < 16; u++) {
            int c = hc * 16 + u;
            float v = fmaf(px, SD1W[c], fmaf(py, SD1W[32 + c],
                      fmaf(pz, SD1W[64 + c], SD1B[c])));
            H[c * 128 + row] = tf32f(SD1G[c] * (eluf(v) * BNI) + SD1BE[c]);
        }
    }
    __syncthreads();

    const int i = t >> 5, lane = t & 31;
    const int g = lane >> 2, tg = lane & 3;
    const int r0 = i * 16;

    // ---- E2 (tensor): FC[r,0:32] = act(H^T[128,32] @ d2W[32,32]) ----
    // warp i owns rows r0..r0+15 = point i's 16 neighbor rows (warp-local).
    {
        u32 af[4][4];
#pragma unroll
        for (int kc = 0; kc < 4; kc++) {
            int kb = kc * 8;
            af[kc][0] = __float_as_uint(H[(kb + tg)     * 128 + r0 + g]);
            af[kc][1] = __float_as_uint(H[(kb + tg)     * 128 + r0 + g + 8]);
            af[kc][2] = __float_as_uint(H[(kb + tg + 4) * 128 + r0 + g]);
            af[kc][3] = __float_as_uint(H[(kb + tg + 4) * 128 + r0 + g + 8]);
        }
        float4 dacc[4];
#pragma unroll
        for (int nj = 0; nj < 4; nj++) {
            dacc[nj] = make_float4(0.f, 0.f, 0.f, 0.f);
            int nb = nj * 8;
#pragma unroll
            for (int kc = 0; kc < 4; kc++) {
                int kb = kc * 8;
                u32 bf0 = __float_as_uint(SD2W[(kb + tg)     * 32 + nb + g]);
                u32 bf1 = __float_as_uint(SD2W[(kb + tg + 4) * 32 + nb + g]);
                mma8(dacc[nj], af[kc], bf0, bf1);
            }
        }
#pragma unroll
        for (int nj = 0; nj < 4; nj++) {
            int c0 = nj * 8 + tg * 2, c1 = c0 + 1;
            float4 d = dacc[nj];
            float2 s0, s1;
            s0.x = SD2G[c0] * (eluf(d.x + SD2B[c0]) * BNI) + SD2BE[c0];
            s0.y = SD2G[c1] * (eluf(d.y + SD2B[c1]) * BNI) + SD2BE[c1];
            s1.x = SD2G[c0] * (eluf(d.z + SD2B[c0]) * BNI) + SD2BE[c0];
            s1.y = SD2G[c1] * (eluf(d.w + SD2B[c1]) * BNI) + SD2BE[c1];
            *(float2*)&FC[(r0 + g)     * FCS + c0] = s0;
            *(float2*)&FC[(r0 + g + 8) * FCS + c0] = s1;
        }
        __syncwarp();
    }

    // ---- Phase F (tensor): fts_X[16,96] = X2[16,16] @ FC[16,96], warp-local ----
    {
        const float* X2 = &XA[i * 256];
        u32 af[2][4];
#pragma unroll
        for (int kc = 0; kc < 2; kc++) {
            int kb = kc * 8;
            af[kc][0] = tf32(X2[(g)     * 16 + kb + tg]);
            af[kc][1] = tf32(X2[(g + 8) * 16 + kb + tg]);
            af[kc][2] = tf32(X2[(g)     * 16 + kb + tg + 4]);
            af[kc][3] = tf32(X2[(g + 8) * 16 + kb + tg + 4]);
        }
        float4 dacc[12];
#pragma unroll
        for (int nj = 0; nj < 12; nj++) {
            dacc[nj] = make_float4(0.f, 0.f, 0.f, 0.f);
            int cn = nj * 8 + g;
#pragma unroll
            for (int kc = 0; kc < 2; kc++) {
                int kb = kc * 8;
                u32 bf0 = tf32(FC[(r0 + kb + tg)     * FCS + cn]);
                u32 bf1 = tf32(FC[(r0 + kb + tg + 4) * FCS + cn]);
                mma8(dacc[nj], af[kc], bf0, bf1);
            }
        }
        __syncwarp();
#pragma unroll
        for (int nj = 0; nj < 12; nj++) {
            int c = nj * 8 + tg * 2;
            float2 s0; s0.x = dacc[nj].x; s0.y = dacc[nj].y;
            float2 s1; s1.x = dacc[nj].z; s1.y = dacc[nj].w;
            *(float2*)&FC[(r0 + g)     * FCS + c] = s0;
            *(float2*)&FC[(r0 + g + 8) * FCS + c] = s1;
        }
        __syncwarp();
    }

    // ---- Phase G1: depthwise, m-paired fma2 -> g_DW (warp-local FC reads) ----
    {
#pragma unroll
        for (int u = 0; u < 3; u++) {
            int c = lane + 32 * u;
            u64 acc = *(const u64*)&dwb[2 * c];
#pragma unroll
            for (int k = 0; k < 16; k++) {
                u64 fd = dup2(FC[(r0 + k) * FCS + c]);
                u64 wd = *(const u64*)&SDW[(k * 96 + c) * 2];
                acc = fma2(fd, wd, acc);
            }
            *(u64*)&g_DW[(size_t)(gp0 + i) * 192 + 2 * c] = acc;
        }
    }
}

// ============================================================================
extern "C" void kernel_launch(void* const* d_in, const int* in_sizes, int n_in,
                              void* d_out, int out_size)
{
    const float* rep_pts = (const float*)d_in[0];
    const float* pts     = (const float*)d_in[1];
    const float* fts     = (const float*)d_in[2];
    const int*   pts_idx = (const int*)d_in[3];
    const float* d0W  = (const float*)d_in[4];
    const float* d0b  = (const float*)d_in[5];
    const float* d0g  = (const float*)d_in[6];
    const float* d0be = (const float*)d_in[7];
    const float* d1W  = (const float*)d_in[8];
    const float* d1b  = (const float*)d_in[9];
    const float* d1g  = (const float*)d_in[10];
    const float* d1be = (const float*)d_in[11];
    const float* d2W  = (const float*)d_in[12];
    const float* d2b  = (const float*)d_in[13];
    const float* d2g  = (const float*)d_in[14];
    const float* d2be = (const float*)d_in[15];
    const float* xcW  = (const float*)d_in[16];
    const float* xcb  = (const float*)d_in[17];
    const float* xd1W = (const float*)d_in[18];
    const float* xd1b = (const float*)d_in[19];
    const float* xd2W = (const float*)d_in[20];
    const float* xd2b = (const float*)d_in[21];
    const float* dwW  = (const float*)d_in[22];
    const float* dwb  = (const float*)d_in[23];
    const float* pwW  = (const float*)d_in[24];
    const float* pwb  = (const float*)d_in[25];
    const float* endg = (const float*)d_in[26];
    const float* endbe= (const float*)d_in[27];
    float* out = (float*)d_out;

    float *pX0, *pX1, *pX2, *pW1, *pW2;
    cudaGetSymbolAddress((void**)&pX0, g_X0);
    cudaGetSymbolAddress((void**)&pX1, g_X1);
    cudaGetSymbolAddress((void**)&pX2, g_X2);
    cudaGetSymbolAddress((void**)&pW1, g_W1t);
    cudaGetSymbolAddress((void**)&pW2, g_W2t);

    dense0_kernel<<<4096, 256>>>(fts, d0W, d0b, d0g, d0be);
    coords_kernel<<<2048, 256>>>(rep_pts, pts, pts_idx);
    cvt_weights<<<256, 256>>>(xd1W, xd2W, pwW);

    cudaFuncSetAttribute(gemmX0_tf32,
                         cudaFuncAttributeMaxDynamicSharedMemorySize, X0_SMEM);
    dim3 xgrid(2, 256);
    gemmX0_tf32<<<xgrid, 256, X0_SMEM>>>(xcW, xcb, pX0);

    dim3 ggrid(2, 256);
    gemm256_tf32<true><<<ggrid, 256>>>(pX0, pW1, xd1b, pX1);
    gemm256_tf32<false><<<ggrid, 256>>>(pX1, pW2, xd2b, pX2);

    cudaFuncSetAttribute(epi_kernel,
                         cudaFuncAttributeMaxDynamicSharedMemorySize, EPI_SM);
    epi_kernel<<<32768 / TILEP, 256, EPI_SM>>>(
        pts_idx, d1W, d1b, d1g, d1be, d2W, d2b, d2g, d2be, dwW, dwb);

    gemm_pw_tf32<<<256, 256>>>(pwb, endg, endbe, out);
}

// round 15
// speedup vs baseline: 2.3863x; 1.1364x over previous
#include <cuda_runtime.h>
#include <math.h>

typedef unsigned long long u64;
typedef unsigned int u32;

// ---- problem dims ----
#define NB      32
#define NUMPTS  2048
#define PN      1024
#define TILEP   8
#define FCS     100
#define BNI     0.9999950000374996f

// scratch
__device__ float g_ftsl[NB * NUMPTS * 64];
__device__ float g_PLS[(size_t)32768 * 48];
__device__ float g_X0 [32768 * 256];
__device__ float g_X1 [32768 * 256];
__device__ float g_X2 [32768 * 256];
__device__ float g_DW [(size_t)32768 * 192];
__device__ float g_W1t[256 * 256];
__device__ float g_W2t[256 * 256];
__device__ float g_pWt[192 * 128];

// Fast ELU: MUFU-based exp instead of libm expm1f. |err| ~1e-7 absolute,
// negligible vs the 1e-3 threshold and the existing ~6.7e-4 tf32 error.
__device__ __forceinline__ float eluf(float x) {
    float e = __expf(x) - 1.0f;
    return x > 0.0f ? x : e;
}
__device__ __forceinline__ u64 fma2(u64 a, u64 b, u64 c) {
    u64 d; asm("fma.rn.f32x2 %0,%1,%2,%3;" : "=l"(d) : "l"(a), "l"(b), "l"(c)); return d;
}
__device__ __forceinline__ u64 dup2(float x) {
    u64 d; asm("mov.b64 %0,{%1,%1};" : "=l"(d) : "f"(x)); return d;
}
__device__ __forceinline__ float2 unpk(u64 v) {
    float2 r; asm("mov.b64 {%0,%1},%2;" : "=f"(r.x), "=f"(r.y) : "l"(v)); return r;
}
__device__ __forceinline__ u32 tf32(float f) {
    u32 o; asm("cvt.rna.tf32.f32 %0, %1;" : "=r"(o) : "f"(f)); return o;
}
__device__ __forceinline__ float tf32f(float f) {
    return __uint_as_float(tf32(f));
}
__device__ __forceinline__ void mma8(float4& d, const u32* a, u32 b0, u32 b1) {
    asm("mma.sync.aligned.m16n8k8.row.col.f32.tf32.tf32.f32 "
        "{%0,%1,%2,%3}, {%4,%5,%6,%7}, {%8,%9}, {%0,%1,%2,%3};"
        : "+f"(d.x), "+f"(d.y), "+f"(d.z), "+f"(d.w)
        : "r"(a[0]), "r"(a[1]), "r"(a[2]), "r"(a[3]), "r"(b0), "r"(b1));
}

// ============================================================================
// Kernel A: dense0 -> g_ftsl
// ============================================================================
__global__ void __launch_bounds__(256) dense0_kernel(
    const float* __restrict__ fts, const float* __restrict__ W,
    const float* __restrict__ b,   const float* __restrict__ g,
    const float* __restrict__ be)
{
    __shared__ float Ws[64 * 64];
    __shared__ float xs[16 * 64];
    const int t = threadIdx.x;
    const size_t row0 = (size_t)blockIdx.x * 16;

#pragma unroll
    for (int u = 0; u < 16; u++) Ws[t + 256 * u] = W[t + 256 * u];
    ((float4*)xs)[t] = ((const float4*)(fts + row0 * 64))[t];
    __syncthreads();

    const int r  = t >> 4;
    const int cb = (t & 15) * 4;
    u64 a0 = 0ull, a1 = 0ull;
#pragma unroll 8
    for (int k = 0; k < 64; k++) {
        u64 xd = dup2(xs[r * 64 + k]);
        ulonglong2 w = *(const ulonglong2*)&Ws[k * 64 + cb];
        a0 = fma2(xd, w.x, a0);
        a1 = fma2(xd, w.y, a1);
    }
    float2 f0 = unpk(a0), f1 = unpk(a1);
    float4 b4 = *(const float4*)&b[cb];
    float4 g4 = *(const float4*)&g[cb];
    float4 e4 = *(const float4*)&be[cb];
    float4 o;
    o.x = g4.x * (eluf(f0.x + b4.x) * BNI) + e4.x;
    o.y = g4.y * (eluf(f0.y + b4.y) * BNI) + e4.y;
    o.z = g4.z * (eluf(f1.x + b4.z) * BNI) + e4.z;
    o.w = g4.w * (eluf(f1.y + b4.w) * BNI) + e4.w;
    *(float4*)&g_ftsl[(row0 + r) * 64 + cb] = o;
}

// ============================================================================
// Kernel C (coords): gather neighbor coords -> g_PLS
// ============================================================================
__global__ void __launch_bounds__(256) coords_kernel(
    const float* __restrict__ rep_pts, const float* __restrict__ pts,
    const int* __restrict__ pts_idx)
{
    int idx = blockIdx.x * 256 + threadIdx.x;
    int pt = idx >> 4, k = idx & 15;
    int n = pt >> 10;
    int gi = pts_idx[idx];
    const float* pp = pts + ((size_t)n * NUMPTS + gi) * 3;
    const float* rp = rep_pts + (size_t)pt * 3;
    float* dst = g_PLS + (size_t)pt * 48;
    dst[k]      = pp[0] - rp[0];
    dst[16 + k] = pp[1] - rp[1];
    dst[32 + k] = pp[2] - rp[2];
}

// ============================================================================
// Kernel W: pre-round GEMM weights to tf32 bit patterns
// ============================================================================
__global__ void __launch_bounds__(256) cvt_weights(
    const float* __restrict__ xd1W, const float* __restrict__ xd2W,
    const float* __restrict__ pwW)
{
    int idx = blockIdx.x * 256 + threadIdx.x;
    g_W1t[idx] = tf32f(xd1W[idx]);
    g_W2t[idx] = tf32f(xd2W[idx]);
    if (idx < 192 * 128) g_pWt[idx] = tf32f(pwW[idx]);
}

// ============================================================================
// GEMM-X0 (TF32): X0[M,256] = tf32(elu(PLS[M,48] @ xcW^T + xcb))
// ============================================================================
#define X0_SMEM ((128 * 52 + 48 * 136) * 4)

__global__ void __launch_bounds__(256, 2) gemmX0_tf32(
    const float* __restrict__ xcW, const float* __restrict__ xcb,
    float* __restrict__ X0)
{
    extern __shared__ u32 smx[];
    u32 (*As)[52]  = (u32(*)[52])smx;
    u32 (*Bs)[136] = (u32(*)[136])(smx + 128 * 52);

    const int t  = threadIdx.x;
    const int m0 = blockIdx.y << 7;
    const int n0 = blockIdx.x << 7;
    const int wid = t >> 5, lane = t & 31;
    const int wm = wid >> 1, wn = wid & 1;
    const int g = lane >> 2, tg = lane & 3;

    {
        const int ar = t >> 1, ah = (t & 1) * 24;
        const float* Ar = g_PLS + (size_t)(m0 + ar) * 48 + ah;
#pragma unroll
        for (int v = 0; v < 6; v++) {
            float4 a = *(const float4*)&Ar[v * 4];
            u32* ap = &As[ar][ah + v * 4];
            ap[0] = tf32(a.x); ap[1] = tf32(a.y);
            ap[2] = tf32(a.z); ap[3] = tf32(a.w);
        }
    }
    {
        const int q = t >> 1, kh = (t & 1) * 24;
        const float* Wr = xcW + (size_t)(n0 + q) * 48 + kh;
#pragma unroll
        for (int v = 0; v < 6; v++) {
            float4 w = *(const float4*)&Wr[v * 4];
            Bs[kh + v * 4 + 0][q] = tf32(w.x);
            Bs[kh + v * 4 + 1][q] = tf32(w.y);
            Bs[kh + v * 4 + 2][q] = tf32(w.z);
            Bs[kh + v * 4 + 3][q] = tf32(w.w);
        }
    }
    __syncthreads();

    float4 acc[2][8];
#pragma unroll
    for (int i = 0; i < 2; i++)
#pragma unroll
        for (int j = 0; j < 8; j++) acc[i][j] = make_float4(0.f, 0.f, 0.f, 0.f);

#pragma unroll
    for (int kc = 0; kc < 6; kc++) {
        const int kb = kc * 8;
        u32 af[2][4];
#pragma unroll
        for (int mi = 0; mi < 2; mi++) {
            int r = wm * 32 + mi * 16;
            af[mi][0] = As[r + g][kb + tg];
            af[mi][1] = As[r + g + 8][kb + tg];
            af[mi][2] = As[r + g][kb + tg + 4];
            af[mi][3] = As[r + g + 8][kb + tg + 4];
        }
#pragma unroll
        for (int nj = 0; nj < 8; nj++) {
            int cn = wn * 64 + nj * 8 + g;
            u32 bf0 = Bs[kb + tg][cn];
            u32 bf1 = Bs[kb + tg + 4][cn];
            mma8(acc[0][nj], af[0], bf0, bf1);
            mma8(acc[1][nj], af[1], bf0, bf1);
        }
    }

#pragma unroll
    for (int nj = 0; nj < 8; nj++) {
        int col = n0 + wn * 64 + nj * 8 + tg * 2;
        float bv0 = __ldg(&xcb[col]);
        float bv1 = __ldg(&xcb[col + 1]);
#pragma unroll
        for (int mi = 0; mi < 2; mi++) {
            int row = m0 + wm * 32 + mi * 16 + g;
            float4 d = acc[mi][nj];
            float2 s0, s1;
            s0.x = tf32f(eluf(d.x + bv0)); s0.y = tf32f(eluf(d.y + bv1));
            s1.x = tf32f(eluf(d.z + bv0)); s1.y = tf32f(eluf(d.w + bv1));
            *(float2*)&X0[(size_t)row * 256 + col]       = s0;
            *(float2*)&X0[(size_t)(row + 8) * 256 + col] = s1;
        }
    }
}

// ============================================================================
// GEMM mainloop macros
// ============================================================================
#define G_STAGE_RAW(BUF) do {                                                 \
    *(uint4*)&As[BUF][ar][ak]     = *(uint4*)&a0;                             \
    *(uint4*)&As[BUF][ar][ak + 4] = *(uint4*)&a1;                             \
    *(uint4*)&Bs[BUF][bk][bn]     = *(uint4*)&b0;                             \
    *(uint4*)&Bs[BUF][bk][bn + 4] = *(uint4*)&b1;                             \
} while (0)

#define G_STAGE_ACVT(BUF) do {                                                \
    u32 av[8];                                                                \
    av[0] = tf32(a0.x); av[1] = tf32(a0.y);                                   \
    av[2] = tf32(a0.z); av[3] = tf32(a0.w);                                   \
    av[4] = tf32(a1.x); av[5] = tf32(a1.y);                                   \
    av[6] = tf32(a1.z); av[7] = tf32(a1.w);                                   \
    *(uint4*)&As[BUF][ar][ak]     = *(uint4*)&av[0];                          \
    *(uint4*)&As[BUF][ar][ak + 4] = *(uint4*)&av[4];                          \
    *(uint4*)&Bs[BUF][bk][bn]     = *(uint4*)&b0;                             \
    *(uint4*)&Bs[BUF][bk][bn + 4] = *(uint4*)&b1;                             \
} while (0)

#define G_MMA(BUF) do {                                                       \
    _Pragma("unroll")                                                         \
    for (int kk = 0; kk < 2; kk++) {                                          \
        const int kb = kk * 8;                                                \
        u32 af[2][4];                                                         \
        _Pragma("unroll")                                                     \
        for (int mi = 0; mi < 2; mi++) {                                      \
            int r = wm * 32 + mi * 16;                                        \
            af[mi][0] = As[BUF][r + g][kb + tg];                              \
            af[mi][1] = As[BUF][r + g + 8][kb + tg];                          \
            af[mi][2] = As[BUF][r + g][kb + tg + 4];                          \
            af[mi][3] = As[BUF][r + g + 8][kb + tg + 4];                      \
        }                                                                     \
        _Pragma("unroll")                                                     \
        for (int nj = 0; nj < 8; nj++) {                                      \
            int cn = wn * 64 + nj * 8 + g;                                    \
            u32 bf0 = Bs[BUF][kb + tg][cn];                                   \
            u32 bf1 = Bs[BUF][kb + tg + 4][cn];                               \
            mma8(acc[0][nj], af[0], bf0, bf1);                                \
            mma8(acc[1][nj], af[1], bf0, bf1);                                \
        }                                                                     \
    }                                                                         \
} while (0)

// ============================================================================
// GEMM (TF32): C[M,256] = act(A[M,256] @ W[256,256] + bias); inputs pre-rounded
// ============================================================================
template<bool ELU>
__global__ void __launch_bounds__(256, 2) gemm256_tf32(
    const float* __restrict__ A, const float* __restrict__ W,
    const float* __restrict__ bias, float* __restrict__ C)
{
    __shared__ u32 As[2][128][20];
    __shared__ u32 Bs[2][16][136];
    const int t  = threadIdx.x;
    const int m0 = blockIdx.y << 7;
    const int n0 = blockIdx.x << 7;
    const int wid = t >> 5, lane = t & 31;
    const int wm = wid >> 1, wn = wid & 1;
    const int g = lane >> 2, tg = lane & 3;

    float4 acc[2][8];
#pragma unroll
    for (int i = 0; i < 2; i++)
#pragma unroll
        for (int j = 0; j < 8; j++) acc[i][j] = make_float4(0.f, 0.f, 0.f, 0.f);

    const int ar = t >> 1, ak = (t & 1) * 8;
    const int bk = t >> 4, bn = (t & 15) * 8;
    const float* Arow = A + (size_t)(m0 + ar) * 256;

    float4 a0 = *(const float4*)&Arow[ak];
    float4 a1 = *(const float4*)&Arow[ak + 4];
    float4 b0 = *(const float4*)&W[(size_t)bk * 256 + n0 + bn];
    float4 b1 = *(const float4*)&W[(size_t)bk * 256 + n0 + bn + 4];

#pragma unroll 1
    for (int k0 = 0; k0 < 16; k0 += 2) {
        G_STAGE_RAW(0);
        __syncthreads();
        {
            int kn = (k0 + 1) * 16;
            a0 = *(const float4*)&Arow[kn + ak];
            a1 = *(const float4*)&Arow[kn + ak + 4];
            b0 = *(const float4*)&W[(size_t)(kn + bk) * 256 + n0 + bn];
            b1 = *(const float4*)&W[(size_t)(kn + bk) * 256 + n0 + bn + 4];
        }
        G_MMA(0);
        G_STAGE_RAW(1);
        __syncthreads();
        if (k0 < 14) {
            int kn = (k0 + 2) * 16;
            a0 = *(const float4*)&Arow[kn + ak];
            a1 = *(const float4*)&Arow[kn + ak + 4];
            b0 = *(const float4*)&W[(size_t)(kn + bk) * 256 + n0 + bn];
            b1 = *(const float4*)&W[(size_t)(kn + bk) * 256 + n0 + bn + 4];
        }
        G_MMA(1);
    }

#pragma unroll
    for (int nj = 0; nj < 8; nj++) {
        int col = n0 + wn * 64 + nj * 8 + tg * 2;
        float bv0 = __ldg(&bias[col]);
        float bv1 = __ldg(&bias[col + 1]);
#pragma unroll
        for (int mi = 0; mi < 2; mi++) {
            int row = m0 + wm * 32 + mi * 16 + g;
            float4 d = acc[mi][nj];
            float v0 = d.x + bv0, v1 = d.y + bv1;
            float v2 = d.z + bv0, v3 = d.w + bv1;
            if (ELU) {
                v0 = tf32f(eluf(v0)); v1 = tf32f(eluf(v1));
                v2 = tf32f(eluf(v2)); v3 = tf32f(eluf(v3));
            }
            float2 s0; s0.x = v0; s0.y = v1;
            float2 s1; s1.x = v2; s1.y = v3;
            *(float2*)&C[(size_t)row * 256 + col]       = s0;
            *(float2*)&C[(size_t)(row + 8) * 256 + col] = s1;
        }
    }
}

// ============================================================================
// GEMM-PW (TF32): out = endg*(elu(DW[M,192]@pWt[192,128]+pwb)*BNI)+endbe
// ============================================================================
__global__ void __launch_bounds__(256, 2) gemm_pw_tf32(
    const float* __restrict__ pwb,
    const float* __restrict__ endg, const float* __restrict__ endbe,
    float* __restrict__ out)
{
    __shared__ u32 As[2][128][20];
    __shared__ u32 Bs[2][16][136];
    const int t  = threadIdx.x;
    const int m0 = blockIdx.x << 7;
    const int wid = t >> 5, lane = t & 31;
    const int wm = wid >> 1, wn = wid & 1;
    const int g = lane >> 2, tg = lane & 3;

    float4 acc[2][8];
#pragma unroll
    for (int i = 0; i < 2; i++)
#pragma unroll
        for (int j = 0; j < 8; j++) acc[i][j] = make_float4(0.f, 0.f, 0.f, 0.f);

    const int ar = t >> 1, ak = (t & 1) * 8;
    const int bk = t >> 4, bn = (t & 15) * 8;
    const float* Arow = g_DW + (size_t)(m0 + ar) * 192;

    float4 a0 = *(const float4*)&Arow[ak];
    float4 a1 = *(const float4*)&Arow[ak + 4];
    float4 b0 = *(const float4*)&g_pWt[(size_t)bk * 128 + bn];
    float4 b1 = *(const float4*)&g_pWt[(size_t)bk * 128 + bn + 4];

#pragma unroll 1
    for (int k0 = 0; k0 < 12; k0 += 2) {
        G_STAGE_ACVT(0);
        __syncthreads();
        {
            int kn = (k0 + 1) * 16;
            a0 = *(const float4*)&Arow[kn + ak];
            a1 = *(const float4*)&Arow[kn + ak + 4];
            b0 = *(const float4*)&g_pWt[(size_t)(kn + bk) * 128 + bn];
            b1 = *(const float4*)&g_pWt[(size_t)(kn + bk) * 128 + bn + 4];
        }
        G_MMA(0);
        G_STAGE_ACVT(1);
        __syncthreads();
        if (k0 < 10) {
            int kn = (k0 + 2) * 16;
            a0 = *(const float4*)&Arow[kn + ak];
            a1 = *(const float4*)&Arow[kn + ak + 4];
            b0 = *(const float4*)&g_pWt[(size_t)(kn + bk) * 128 + bn];
            b1 = *(const float4*)&g_pWt[(size_t)(kn + bk) * 128 + bn + 4];
        }
        G_MMA(1);
    }

#pragma unroll
    for (int nj = 0; nj < 8; nj++) {
        int col = wn * 64 + nj * 8 + tg * 2;
        float bv0 = __ldg(&pwb[col]),   bv1 = __ldg(&pwb[col + 1]);
        float gv0 = __ldg(&endg[col]),  gv1 = __ldg(&endg[col + 1]);
        float ev0 = __ldg(&endbe[col]), ev1 = __ldg(&endbe[col + 1]);
#pragma unroll
        for (int mi = 0; mi < 2; mi++) {
            int row = m0 + wm * 32 + mi * 16 + g;
            float4 d = acc[mi][nj];
            float2 s0, s1;
            s0.x = gv0 * (eluf(d.x + bv0) * BNI) + ev0;
            s0.y = gv1 * (eluf(d.y + bv1) * BNI) + ev1;
            s1.x = gv0 * (eluf(d.z + bv0) * BNI) + ev0;
            s1.y = gv1 * (eluf(d.w + bv1) * BNI) + ev1;
            *(float2*)&out[(size_t)row * 128 + col]       = s0;
            *(float2*)&out[(size_t)(row + 8) * 128 + col] = s1;
        }
    }
}

// ============================================================================
// Kernel E (mega-epilogue): gather ftsl + E1 + E2 (tensor) + F (tensor) + G1
// ============================================================================
#define EPI_SM (23456 * 4)

__global__ void __launch_bounds__(256, 2) epi_kernel(
    const int* __restrict__ pts_idx,
    const float* __restrict__ d1W, const float* __restrict__ d1b,
    const float* __restrict__ d1g, const float* __restrict__ d1be,
    const float* __restrict__ d2W, const float* __restrict__ d2b,
    const float* __restrict__ d2g, const float* __restrict__ d2be,
    const float* __restrict__ dwW, const float* __restrict__ dwb)
{
    extern __shared__ float sm[];
    float* XA    = sm;            // [8][256]  X2
    float* FC    = sm + 2048;     // [8][16][FCS]
    float* H     = sm + 14848;    // [32][128] (tf32-rounded)
    float* SDW   = sm + 18944;    // dw pairs
    float* SD1W  = sm + 22016; float* SD1B  = sm + 22112;
    float* SD1G  = sm + 22144; float* SD1BE = sm + 22176;
    float* SD2W  = sm + 22208;    // [32][32] tf32-rounded
    float* SD2B  = sm + 23232; float* SD2G  = sm + 23264;
    float* SD2BE = sm + 23296;
    int*   SIDX  = (int*)(sm + 23328);

    const int t   = threadIdx.x;
    const int gp0 = blockIdx.x * TILEP;
    const int n   = gp0 >> 10;

    // ---- phase 0: indices, weights, X2 ----
    if (t < 128) SIDX[t] = pts_idx[(size_t)gp0 * 16 + t];
    for (int u = t; u < 96; u += 256) SD1W[u] = d1W[u];
    for (int u = t; u < 1024; u += 256) SD2W[u] = tf32f(d2W[u]);
    if (t < 32) {
        SD1B[t] = d1b[t]; SD1G[t] = d1g[t]; SD1BE[t] = d1be[t];
        SD2B[t] = d2b[t]; SD2G[t] = d2g[t]; SD2BE[t] = d2be[t];
    }
    for (int idx = t; idx < 1536; idx += 256) {
        int k = idx / 96, c = idx - k * 96;
        float2 w;
        w.x = dwW[c * 32 + k];
        w.y = dwW[c * 32 + 16 + k];
        *(float2*)&SDW[idx * 2] = w;
    }
    {
        const float4* src = (const float4*)(g_X2 + (size_t)gp0 * 256);
        float4* dst = (float4*)XA;
        dst[t] = src[t];
        dst[t + 256] = src[t + 256];
    }
    __syncthreads();

    // ---- phase 1: gather ftsl -> FC[:,32:96]; E1 -> H (tf32-rounded) ----
    {
        int row = t >> 1, half = t & 1;
        int gi = SIDX[row];
        const float4* src = (const float4*)(g_ftsl + ((size_t)n * NUMPTS + gi) * 64 + half * 32);
        float4* dst = (float4*)&FC[row * FCS + 32 + half * 32];
#pragma unroll
        for (int u = 0; u < 8; u++) dst[u] = src[u];
    }
    {
        const int row = t & 127, hc = t >> 7;
        const int i = row >> 4, k = row & 15;
        const float* pl = g_PLS + (size_t)(gp0 + i) * 48;
        float px = __ldg(&pl[k]);
        float py = __ldg(&pl[16 + k]);
        float pz = __ldg(&pl[32 + k]);
#pragma unroll
        for (int u = 0; u < 16; u++) {
            int c = hc * 16 + u;
            float v = fmaf(px, SD1W[c], fmaf(py, SD1W[32 + c],
                      fmaf(pz, SD1W[64 + c], SD1B[c])));
            H[c * 128 + row] = tf32f(SD1G[c] * (eluf(v) * BNI) + SD1BE[c]);
        }
    }
    __syncthreads();

    const int i = t >> 5, lane = t & 31;
    const int g = lane >> 2, tg = lane & 3;
    const int r0 = i * 16;

    // ---- E2 (tensor): FC[r,0:32] = act(H^T[128,32] @ d2W[32,32]) ----
    {
        u32 af[4][4];
#pragma unroll
        for (int kc = 0; kc < 4; kc++) {
            int kb = kc * 8;
            af[kc][0] = __float_as_uint(H[(kb + tg)     * 128 + r0 + g]);
            af[kc][1] = __float_as_uint(H[(kb + tg)     * 128 + r0 + g + 8]);
            af[kc][2] = __float_as_uint(H[(kb + tg + 4) * 128 + r0 + g]);
            af[kc][3] = __float_as_uint(H[(kb + tg + 4) * 128 + r0 + g + 8]);
        }
        float4 dacc[4];
#pragma unroll
        for (int nj = 0; nj < 4; nj++) {
            dacc[nj] = make_float4(0.f, 0.f, 0.f, 0.f);
            int nb = nj * 8;
#pragma unroll
            for (int kc = 0; kc < 4; kc++) {
                int kb = kc * 8;
                u32 bf0 = __float_as_uint(SD2W[(kb + tg)     * 32 + nb + g]);
                u32 bf1 = __float_as_uint(SD2W[(kb + tg + 4) * 32 + nb + g]);
                mma8(dacc[nj], af[kc], bf0, bf1);
            }
        }
#pragma unroll
        for (int nj = 0; nj < 4; nj++) {
            int c0 = nj * 8 + tg * 2, c1 = c0 + 1;
            float4 d = dacc[nj];
            float2 s0, s1;
            s0.x = SD2G[c0] * (eluf(d.x + SD2B[c0]) * BNI) + SD2BE[c0];
            s0.y = SD2G[c1] * (eluf(d.y + SD2B[c1]) * BNI) + SD2BE[c1];
            s1.x = SD2G[c0] * (eluf(d.z + SD2B[c0]) * BNI) + SD2BE[c0];
            s1.y = SD2G[c1] * (eluf(d.w + SD2B[c1]) * BNI) + SD2BE[c1];
            *(float2*)&FC[(r0 + g)     * FCS + c0] = s0;
            *(float2*)&FC[(r0 + g + 8) * FCS + c0] = s1;
        }
        __syncwarp();
    }

    // ---- Phase F (tensor): fts_X[16,96] = X2[16,16] @ FC[16,96], warp-local ----
    {
        const float* X2 = &XA[i * 256];
        u32 af[2][4];
#pragma unroll
        for (int kc = 0; kc < 2; kc++) {
            int kb = kc * 8;
            af[kc][0] = tf32(X2[(g)     * 16 + kb + tg]);
            af[kc][1] = tf32(X2[(g + 8) * 16 + kb + tg]);
            af[kc][2] = tf32(X2[(g)     * 16 + kb + tg + 4]);
            af[kc][3] = tf32(X2[(g + 8) * 16 + kb + tg + 4]);
        }
        float4 dacc[12];
#pragma unroll
        for (int nj = 0; nj < 12; nj++) {
            dacc[nj] = make_float4(0.f, 0.f, 0.f, 0.f);
            int cn = nj * 8 + g;
#pragma unroll
            for (int kc = 0; kc < 2; kc++) {
                int kb = kc * 8;
                u32 bf0 = tf32(FC[(r0 + kb + tg)     * FCS + cn]);
                u32 bf1 = tf32(FC[(r0 + kb + tg + 4) * FCS + cn]);
                mma8(dacc[nj], af[kc], bf0, bf1);
            }
        }
        __syncwarp();
#pragma unroll
        for (int nj = 0; nj < 12; nj++) {
            int c = nj * 8 + tg * 2;
            float2 s0; s0.x = dacc[nj].x; s0.y = dacc[nj].y;
            float2 s1; s1.x = dacc[nj].z; s1.y = dacc[nj].w;
            *(float2*)&FC[(r0 + g)     * FCS + c] = s0;
            *(float2*)&FC[(r0 + g + 8) * FCS + c] = s1;
        }
        __syncwarp();
    }

    // ---- Phase G1: depthwise, m-paired fma2 -> g_DW ----
    {
#pragma unroll
        for (int u = 0; u < 3; u++) {
            int c = lane + 32 * u;
            u64 acc = *(const u64*)&dwb[2 * c];
#pragma unroll
            for (int k = 0; k < 16; k++) {
                u64 fd = dup2(FC[(r0 + k) * FCS + c]);
                u64 wd = *(const u64*)&SDW[(k * 96 + c) * 2];
                acc = fma2(fd, wd, acc);
            }
            *(u64*)&g_DW[(size_t)(gp0 + i) * 192 + 2 * c] = acc;
        }
    }
}

// ============================================================================
extern "C" void kernel_launch(void* const* d_in, const int* in_sizes, int n_in,
                              void* d_out, int out_size)
{
    const float* rep_pts = (const float*)d_in[0];
    const float* pts     = (const float*)d_in[1];
    const float* fts     = (const float*)d_in[2];
    const int*   pts_idx = (const int*)d_in[3];
    const float* d0W  = (const float*)d_in[4];
    const float* d0b  = (const float*)d_in[5];
    const float* d0g  = (const float*)d_in[6];
    const float* d0be = (const float*)d_in[7];
    const float* d1W  = (const float*)d_in[8];
    const float* d1b  = (const float*)d_in[9];
    const float* d1g  = (const float*)d_in[10];
    const float* d1be = (const float*)d_in[11];
    const float* d2W  = (const float*)d_in[12];
    const float* d2b  = (const float*)d_in[13];
    const float* d2g  = (const float*)d_in[14];
    const float* d2be = (const float*)d_in[15];
    const float* xcW  = (const float*)d_in[16];
    const float* xcb  = (const float*)d_in[17];
    const float* xd1W = (const float*)d_in[18];
    const float* xd1b = (const float*)d_in[19];
    const float* xd2W = (const float*)d_in[20];
    const float* xd2b = (const float*)d_in[21];
    const float* dwW  = (const float*)d_in[22];
    const float* dwb  = (const float*)d_in[23];
    const float* pwW  = (const float*)d_in[24];
    const float* pwb  = (const float*)d_in[25];
    const float* endg = (const float*)d_in[26];
    const float* endbe= (const float*)d_in[27];
    float* out = (float*)d_out;

    float *pX0, *pX1, *pX2, *pW1, *pW2;
    cudaGetSymbolAddress((void**)&pX0, g_X0);
    cudaGetSymbolAddress((void**)&pX1, g_X1);
    cudaGetSymbolAddress((void**)&pX2, g_X2);
    cudaGetSymbolAddress((void**)&pW1, g_W1t);
    cudaGetSymbolAddress((void**)&pW2, g_W2t);

    dense0_kernel<<<4096, 256>>>(fts, d0W, d0b, d0g, d0be);
    coords_kernel<<<2048, 256>>>(rep_pts, pts, pts_idx);
    cvt_weights<<<256, 256>>>(xd1W, xd2W, pwW);

    cudaFuncSetAttribute(gemmX0_tf32,
                         cudaFuncAttributeMaxDynamicSharedMemorySize, X0_SMEM);
    dim3 xgrid(2, 256);
    gemmX0_tf32<<<xgrid, 256, X0_SMEM>>>(xcW, xcb, pX0);

    dim3 ggrid(2, 256);
    gemm256_tf32<true><<<ggrid, 256>>>(pX0, pW1, xd1b, pX1);
    gemm256_tf32<false><<<ggrid, 256>>>(pX1, pW2, xd2b, pX2);

    cudaFuncSetAttribute(epi_kernel,
                         cudaFuncAttributeMaxDynamicSharedMemorySize, EPI_SM);
    epi_kernel<<<32768 / TILEP, 256, EPI_SM>>>(
        pts_idx, d1W, d1b, d1g, d1be, d2W, d2b, d2g, d2be, dwW, dwb);

    gemm_pw_tf32<<<256, 256>>>(pwb, endg, endbe, out);
}

// round 16
// speedup vs baseline: 2.4527x; 1.0278x over previous
#include <cuda_runtime.h>
#include <math.h>

typedef unsigned long long u64;
typedef unsigned int u32;

// ---- problem dims ----
#define NB      32
#define NUMPTS  2048
#define PN      1024
#define TILEP   8
#define FCS     100
#define BNI     0.9999950000374996f

// scratch
__device__ float g_ftsl[NB * NUMPTS * 64];
__device__ float g_PLS[(size_t)32768 * 48];
__device__ float g_X0 [32768 * 256];
__device__ float g_X1 [32768 * 256];
__device__ float g_X2 [32768 * 256];
__device__ float g_DW [(size_t)32768 * 192];
__device__ float g_W1t[256 * 256];
__device__ float g_W2t[256 * 256];
__device__ float g_pWt[192 * 128];

// Fast ELU (MUFU exp)
__device__ __forceinline__ float eluf(float x) {
    float e = __expf(x) - 1.0f;
    return x > 0.0f ? x : e;
}
__device__ __forceinline__ u64 fma2(u64 a, u64 b, u64 c) {
    u64 d; asm("fma.rn.f32x2 %0,%1,%2,%3;" : "=l"(d) : "l"(a), "l"(b), "l"(c)); return d;
}
__device__ __forceinline__ u64 dup2(float x) {
    u64 d; asm("mov.b64 %0,{%1,%1};" : "=l"(d) : "f"(x)); return d;
}
__device__ __forceinline__ float2 unpk(u64 v) {
    float2 r; asm("mov.b64 {%0,%1},%2;" : "=f"(r.x), "=f"(r.y) : "l"(v)); return r;
}
__device__ __forceinline__ u32 tf32(float f) {
    u32 o; asm("cvt.rna.tf32.f32 %0, %1;" : "=r"(o) : "f"(f)); return o;
}
__device__ __forceinline__ float tf32f(float f) {
    return __uint_as_float(tf32(f));
}
__device__ __forceinline__ void mma8(float4& d, const u32* a, u32 b0, u32 b1) {
    asm("mma.sync.aligned.m16n8k8.row.col.f32.tf32.tf32.f32 "
        "{%0,%1,%2,%3}, {%4,%5,%6,%7}, {%8,%9}, {%0,%1,%2,%3};"
        : "+f"(d.x), "+f"(d.y), "+f"(d.z), "+f"(d.w)
        : "r"(a[0]), "r"(a[1]), "r"(a[2]), "r"(a[3]), "r"(b0), "r"(b1));
}

// ============================================================================
// Kernel A: dense0 -> g_ftsl
// ============================================================================
__global__ void __launch_bounds__(256) dense0_kernel(
    const float* __restrict__ fts, const float* __restrict__ W,
    const float* __restrict__ b,   const float* __restrict__ g,
    const float* __restrict__ be)
{
    __shared__ float Ws[64 * 64];
    __shared__ float xs[16 * 64];
    const int t = threadIdx.x;
    const size_t row0 = (size_t)blockIdx.x * 16;

#pragma unroll
    for (int u = 0; u < 16; u++) Ws[t + 256 * u] = W[t + 256 * u];
    ((float4*)xs)[t] = ((const float4*)(fts + row0 * 64))[t];
    __syncthreads();

    const int r  = t >> 4;
    const int cb = (t & 15) * 4;
    u64 a0 = 0ull, a1 = 0ull;
#pragma unroll 8
    for (int k = 0; k < 64; k++) {
        u64 xd = dup2(xs[r * 64 + k]);
        ulonglong2 w = *(const ulonglong2*)&Ws[k * 64 + cb];
        a0 = fma2(xd, w.x, a0);
        a1 = fma2(xd, w.y, a1);
    }
    float2 f0 = unpk(a0), f1 = unpk(a1);
    float4 b4 = *(const float4*)&b[cb];
    float4 g4 = *(const float4*)&g[cb];
    float4 e4 = *(const float4*)&be[cb];
    float4 o;
    o.x = g4.x * (eluf(f0.x + b4.x) * BNI) + e4.x;
    o.y = g4.y * (eluf(f0.y + b4.y) * BNI) + e4.y;
    o.z = g4.z * (eluf(f1.x + b4.z) * BNI) + e4.z;
    o.w = g4.w * (eluf(f1.y + b4.w) * BNI) + e4.w;
    *(float4*)&g_ftsl[(row0 + r) * 64 + cb] = o;
}

// ============================================================================
// Kernel C (coords): gather neighbor coords -> g_PLS
// ============================================================================
__global__ void __launch_bounds__(256) coords_kernel(
    const float* __restrict__ rep_pts, const float* __restrict__ pts,
    const int* __restrict__ pts_idx)
{
    int idx = blockIdx.x * 256 + threadIdx.x;
    int pt = idx >> 4, k = idx & 15;
    int n = pt >> 10;
    int gi = pts_idx[idx];
    const float* pp = pts + ((size_t)n * NUMPTS + gi) * 3;
    const float* rp = rep_pts + (size_t)pt * 3;
    float* dst = g_PLS + (size_t)pt * 48;
    dst[k]      = pp[0] - rp[0];
    dst[16 + k] = pp[1] - rp[1];
    dst[32 + k] = pp[2] - rp[2];
}

// ============================================================================
// Kernel W: pre-round GEMM weights to tf32 bit patterns
// ============================================================================
__global__ void __launch_bounds__(256) cvt_weights(
    const float* __restrict__ xd1W, const float* __restrict__ xd2W,
    const float* __restrict__ pwW)
{
    int idx = blockIdx.x * 256 + threadIdx.x;
    g_W1t[idx] = tf32f(xd1W[idx]);
    g_W2t[idx] = tf32f(xd2W[idx]);
    if (idx < 192 * 128) g_pWt[idx] = tf32f(pwW[idx]);
}

// ============================================================================
// GEMM-X0 (TF32): X0[M,256] = tf32(elu(PLS[M,48] @ xcW^T + xcb))
// ============================================================================
#define X0_SMEM ((128 * 52 + 48 * 136) * 4)

__global__ void __launch_bounds__(256, 2) gemmX0_tf32(
    const float* __restrict__ xcW, const float* __restrict__ xcb,
    float* __restrict__ X0)
{
    extern __shared__ u32 smx[];
    u32 (*As)[52]  = (u32(*)[52])smx;
    u32 (*Bs)[136] = (u32(*)[136])(smx + 128 * 52);

    const int t  = threadIdx.x;
    const int m0 = blockIdx.y << 7;
    const int n0 = blockIdx.x << 7;
    const int wid = t >> 5, lane = t & 31;
    const int wm = wid >> 1, wn = wid & 1;
    const int g = lane >> 2, tg = lane & 3;

    {
        const int ar = t >> 1, ah = (t & 1) * 24;
        const float* Ar = g_PLS + (size_t)(m0 + ar) * 48 + ah;
#pragma unroll
        for (int v = 0; v < 6; v++) {
            float4 a = *(const float4*)&Ar[v * 4];
            u32* ap = &As[ar][ah + v * 4];
            ap[0] = tf32(a.x); ap[1] = tf32(a.y);
            ap[2] = tf32(a.z); ap[3] = tf32(a.w);
        }
    }
    {
        const int q = t >> 1, kh = (t & 1) * 24;
        const float* Wr = xcW + (size_t)(n0 + q) * 48 + kh;
#pragma unroll
        for (int v = 0; v < 6; v++) {
            float4 w = *(const float4*)&Wr[v * 4];
            Bs[kh + v * 4 + 0][q] = tf32(w.x);
            Bs[kh + v * 4 + 1][q] = tf32(w.y);
            Bs[kh + v * 4 + 2][q] = tf32(w.z);
            Bs[kh + v * 4 + 3][q] = tf32(w.w);
        }
    }
    __syncthreads();

    float4 acc[2][8];
#pragma unroll
    for (int i = 0; i < 2; i++)
#pragma unroll
        for (int j = 0; j < 8; j++) acc[i][j] = make_float4(0.f, 0.f, 0.f, 0.f);

#pragma unroll
    for (int kc = 0; kc < 6; kc++) {
        const int kb = kc * 8;
        u32 af[2][4];
#pragma unroll
        for (int mi = 0; mi < 2; mi++) {
            int r = wm * 32 + mi * 16;
            af[mi][0] = As[r + g][kb + tg];
            af[mi][1] = As[r + g + 8][kb + tg];
            af[mi][2] = As[r + g][kb + tg + 4];
            af[mi][3] = As[r + g + 8][kb + tg + 4];
        }
#pragma unroll
        for (int nj = 0; nj < 8; nj++) {
            int cn = wn * 64 + nj * 8 + g;
            u32 bf0 = Bs[kb + tg][cn];
            u32 bf1 = Bs[kb + tg + 4][cn];
            mma8(acc[0][nj], af[0], bf0, bf1);
            mma8(acc[1][nj], af[1], bf0, bf1);
        }
    }

#pragma unroll
    for (int nj = 0; nj < 8; nj++) {
        int col = n0 + wn * 64 + nj * 8 + tg * 2;
        float bv0 = __ldg(&xcb[col]);
        float bv1 = __ldg(&xcb[col + 1]);
#pragma unroll
        for (int mi = 0; mi < 2; mi++) {
            int row = m0 + wm * 32 + mi * 16 + g;
            float4 d = acc[mi][nj];
            float2 s0, s1;
            s0.x = tf32f(eluf(d.x + bv0)); s0.y = tf32f(eluf(d.y + bv1));
            s1.x = tf32f(eluf(d.z + bv0)); s1.y = tf32f(eluf(d.w + bv1));
            *(float2*)&X0[(size_t)row * 256 + col]       = s0;
            *(float2*)&X0[(size_t)(row + 8) * 256 + col] = s1;
        }
    }
}

// ============================================================================
// GEMM mainloop macros
// ============================================================================
#define G_STAGE_RAW(BUF) do {                                                 \
    *(uint4*)&As[BUF][ar][ak]     = *(uint4*)&a0;                             \
    *(uint4*)&As[BUF][ar][ak + 4] = *(uint4*)&a1;                             \
    *(uint4*)&Bs[BUF][bk][bn]     = *(uint4*)&b0;                             \
    *(uint4*)&Bs[BUF][bk][bn + 4] = *(uint4*)&b1;                             \
} while (0)

#define G_STAGE_ACVT(BUF) do {                                                \
    u32 av[8];                                                                \
    av[0] = tf32(a0.x); av[1] = tf32(a0.y);                                   \
    av[2] = tf32(a0.z); av[3] = tf32(a0.w);                                   \
    av[4] = tf32(a1.x); av[5] = tf32(a1.y);                                   \
    av[6] = tf32(a1.z); av[7] = tf32(a1.w);                                   \
    *(uint4*)&As[BUF][ar][ak]     = *(uint4*)&av[0];                          \
    *(uint4*)&As[BUF][ar][ak + 4] = *(uint4*)&av[4];                          \
    *(uint4*)&Bs[BUF][bk][bn]     = *(uint4*)&b0;                             \
    *(uint4*)&Bs[BUF][bk][bn + 4] = *(uint4*)&b1;                             \
} while (0)

#define G_MMA(BUF) do {                                                       \
    _Pragma("unroll")                                                         \
    for (int kk = 0; kk < 2; kk++) {                                          \
        const int kb = kk * 8;                                                \
        u32 af[2][4];                                                         \
        _Pragma("unroll")                                                     \
        for (int mi = 0; mi < 2; mi++) {                                      \
            int r = wm * 32 + mi * 16;                                        \
            af[mi][0] = As[BUF][r + g][kb + tg];                              \
            af[mi][1] = As[BUF][r + g + 8][kb + tg];                          \
            af[mi][2] = As[BUF][r + g][kb + tg + 4];                          \
            af[mi][3] = As[BUF][r + g + 8][kb + tg + 4];                      \
        }                                                                     \
        _Pragma("unroll")                                                     \
        for (int nj = 0; nj < 8; nj++) {                                      \
            int cn = wn * 64 + nj * 8 + g;                                    \
            u32 bf0 = Bs[BUF][kb + tg][cn];                                   \
            u32 bf1 = Bs[BUF][kb + tg + 4][cn];                               \
            mma8(acc[0][nj], af[0], bf0, bf1);                                \
            mma8(acc[1][nj], af[1], bf0, bf1);                                \
        }                                                                     \
    }                                                                         \
} while (0)

// ============================================================================
// GEMM (TF32): C[M,256] = act(A[M,256] @ W[256,256] + bias); inputs pre-rounded
// ============================================================================
template<bool ELU>
__global__ void __launch_bounds__(256, 2) gemm256_tf32(
    const float* __restrict__ A, const float* __restrict__ W,
    const float* __restrict__ bias, float* __restrict__ C)
{
    __shared__ u32 As[2][128][20];
    __shared__ u32 Bs[2][16][136];
    const int t  = threadIdx.x;
    const int m0 = blockIdx.y << 7;
    const int n0 = blockIdx.x << 7;
    const int wid = t >> 5, lane = t & 31;
    const int wm = wid >> 1, wn = wid & 1;
    const int g = lane >> 2, tg = lane & 3;

    float4 acc[2][8];
#pragma unroll
    for (int i = 0; i < 2; i++)
#pragma unroll
        for (int j = 0; j < 8; j++) acc[i][j] = make_float4(0.f, 0.f, 0.f, 0.f);

    const int ar = t >> 1, ak = (t & 1) * 8;
    const int bk = t >> 4, bn = (t & 15) * 8;
    const float* Arow = A + (size_t)(m0 + ar) * 256;

    float4 a0 = *(const float4*)&Arow[ak];
    float4 a1 = *(const float4*)&Arow[ak + 4];
    float4 b0 = *(const float4*)&W[(size_t)bk * 256 + n0 + bn];
    float4 b1 = *(const float4*)&W[(size_t)bk * 256 + n0 + bn + 4];

#pragma unroll 1
    for (int k0 = 0; k0 < 16; k0 += 2) {
        G_STAGE_RAW(0);
        __syncthreads();
        {
            int kn = (k0 + 1) * 16;
            a0 = *(const float4*)&Arow[kn + ak];
            a1 = *(const float4*)&Arow[kn + ak + 4];
            b0 = *(const float4*)&W[(size_t)(kn + bk) * 256 + n0 + bn];
            b1 = *(const float4*)&W[(size_t)(kn + bk) * 256 + n0 + bn + 4];
        }
        G_MMA(0);
        G_STAGE_RAW(1);
        __syncthreads();
        if (k0 < 14) {
            int kn = (k0 + 2) * 16;
            a0 = *(const float4*)&Arow[kn + ak];
            a1 = *(const float4*)&Arow[kn + ak + 4];
            b0 = *(const float4*)&W[(size_t)(kn + bk) * 256 + n0 + bn];
            b1 = *(const float4*)&W[(size_t)(kn + bk) * 256 + n0 + bn + 4];
        }
        G_MMA(1);
    }

#pragma unroll
    for (int nj = 0; nj < 8; nj++) {
        int col = n0 + wn * 64 + nj * 8 + tg * 2;
        float bv0 = __ldg(&bias[col]);
        float bv1 = __ldg(&bias[col + 1]);
#pragma unroll
        for (int mi = 0; mi < 2; mi++) {
            int row = m0 + wm * 32 + mi * 16 + g;
            float4 d = acc[mi][nj];
            float v0 = d.x + bv0, v1 = d.y + bv1;
            float v2 = d.z + bv0, v3 = d.w + bv1;
            if (ELU) {
                v0 = tf32f(eluf(v0)); v1 = tf32f(eluf(v1));
                v2 = tf32f(eluf(v2)); v3 = tf32f(eluf(v3));
            }
            float2 s0; s0.x = v0; s0.y = v1;
            float2 s1; s1.x = v2; s1.y = v3;
            *(float2*)&C[(size_t)row * 256 + col]       = s0;
            *(float2*)&C[(size_t)(row + 8) * 256 + col] = s1;
        }
    }
}

// ============================================================================
// GEMM-PW (TF32): out = endg*(elu(DW[M,192]@pWt[192,128]+pwb)*BNI)+endbe
// ============================================================================
__global__ void __launch_bounds__(256, 2) gemm_pw_tf32(
    const float* __restrict__ pwb,
    const float* __restrict__ endg, const float* __restrict__ endbe,
    float* __restrict__ out)
{
    __shared__ u32 As[2][128][20];
    __shared__ u32 Bs[2][16][136];
    const int t  = threadIdx.x;
    const int m0 = blockIdx.x << 7;
    const int wid = t >> 5, lane = t & 31;
    const int wm = wid >> 1, wn = wid & 1;
    const int g = lane >> 2, tg = lane & 3;

    float4 acc[2][8];
#pragma unroll
    for (int i = 0; i < 2; i++)
#pragma unroll
        for (int j = 0; j < 8; j++) acc[i][j] = make_float4(0.f, 0.f, 0.f, 0.f);

    const int ar = t >> 1, ak = (t & 1) * 8;
    const int bk = t >> 4, bn = (t & 15) * 8;
    const float* Arow = g_DW + (size_t)(m0 + ar) * 192;

    float4 a0 = *(const float4*)&Arow[ak];
    float4 a1 = *(const float4*)&Arow[ak + 4];
    float4 b0 = *(const float4*)&g_pWt[(size_t)bk * 128 + bn];
    float4 b1 = *(const float4*)&g_pWt[(size_t)bk * 128 + bn + 4];

#pragma unroll 1
    for (int k0 = 0; k0 < 12; k0 += 2) {
        G_STAGE_ACVT(0);
        __syncthreads();
        {
            int kn = (k0 + 1) * 16;
            a0 = *(const float4*)&Arow[kn + ak];
            a1 = *(const float4*)&Arow[kn + ak + 4];
            b0 = *(const float4*)&g_pWt[(size_t)(kn + bk) * 128 + bn];
            b1 = *(const float4*)&g_pWt[(size_t)(kn + bk) * 128 + bn + 4];
        }
        G_MMA(0);
        G_STAGE_ACVT(1);
        __syncthreads();
        if (k0 < 10) {
            int kn = (k0 + 2) * 16;
            a0 = *(const float4*)&Arow[kn + ak];
            a1 = *(const float4*)&Arow[kn + ak + 4];
            b0 = *(const float4*)&g_pWt[(size_t)(kn + bk) * 128 + bn];
            b1 = *(const float4*)&g_pWt[(size_t)(kn + bk) * 128 + bn + 4];
        }
        G_MMA(1);
    }

#pragma unroll
    for (int nj = 0; nj < 8; nj++) {
        int col = wn * 64 + nj * 8 + tg * 2;
        float bv0 = __ldg(&pwb[col]),   bv1 = __ldg(&pwb[col + 1]);
        float gv0 = __ldg(&endg[col]),  gv1 = __ldg(&endg[col + 1]);
        float ev0 = __ldg(&endbe[col]), ev1 = __ldg(&endbe[col + 1]);
#pragma unroll
        for (int mi = 0; mi < 2; mi++) {
            int row = m0 + wm * 32 + mi * 16 + g;
            float4 d = acc[mi][nj];
            float2 s0, s1;
            s0.x = gv0 * (eluf(d.x + bv0) * BNI) + ev0;
            s0.y = gv1 * (eluf(d.y + bv1) * BNI) + ev1;
            s1.x = gv0 * (eluf(d.z + bv0) * BNI) + ev0;
            s1.y = gv1 * (eluf(d.w + bv1) * BNI) + ev1;
            *(float2*)&out[(size_t)row * 128 + col]       = s0;
            *(float2*)&out[(size_t)(row + 8) * 128 + col] = s1;
        }
    }
}

// ============================================================================
// Kernel E (mega-epilogue), 3 CTAs/SM:
//   gather ftsl + E1 (H stored in-place in FC[:,0:32]) + E2 (tensor, in-place)
//   + F (tensor, X2 direct from L2) + G1 -> g_DW
// smem (floats):
//   FC [8][16][FCS] @0 (12800) | SDW @12800 (3072)
//   SD1W @15872(96) SD1B @15968 SD1G @16000 SD1BE @16032
//   SD2W @16064 (1024, tf32) | SD2B @17088 SD2G @17120 SD2BE @17152
//   SIDX @17184 (128)
// total 17312 floats = 69248 B; 3 CTAs = 210816 B (incl 1KB/CTA reserve)
// ============================================================================
#define EPI_SM (17312 * 4)

__global__ void __launch_bounds__(256, 3) epi_kernel(
    const int* __restrict__ pts_idx,
    const float* __restrict__ d1W, const float* __restrict__ d1b,
    const float* __restrict__ d1g, const float* __restrict__ d1be,
    const float* __restrict__ d2W, const float* __restrict__ d2b,
    const float* __restrict__ d2g, const float* __restrict__ d2be,
    const float* __restrict__ dwW, const float* __restrict__ dwb)
{
    extern __shared__ float sm[];
    float* FC    = sm;            // [8][16][FCS]
    float* SDW   = sm + 12800;
    float* SD1W  = sm + 15872; float* SD1B  = sm + 15968;
    float* SD1G  = sm + 16000; float* SD1BE = sm + 16032;
    float* SD2W  = sm + 16064;    // [32][32] tf32-rounded
    float* SD2B  = sm + 17088; float* SD2G  = sm + 17120;
    float* SD2BE = sm + 17152;
    int*   SIDX  = (int*)(sm + 17184);

    const int t   = threadIdx.x;
    const int gp0 = blockIdx.x * TILEP;
    const int n   = gp0 >> 10;

    // ---- phase 0: indices + weights ----
    if (t < 128) SIDX[t] = pts_idx[(size_t)gp0 * 16 + t];
    for (int u = t; u < 96; u += 256) SD1W[u] = d1W[u];
    for (int u = t; u < 1024; u += 256) SD2W[u] = tf32f(d2W[u]);
    if (t < 32) {
        SD1B[t] = d1b[t]; SD1G[t] = d1g[t]; SD1BE[t] = d1be[t];
        SD2B[t] = d2b[t]; SD2G[t] = d2g[t]; SD2BE[t] = d2be[t];
    }
    for (int idx = t; idx < 1536; idx += 256) {
        int k = idx / 96, c = idx - k * 96;
        float2 w;
        w.x = dwW[c * 32 + k];
        w.y = dwW[c * 32 + 16 + k];
        *(float2*)&SDW[idx * 2] = w;
    }
    __syncthreads();

    // ---- phase 1: gather ftsl -> FC[:,32:96]; E1 -> FC[:,0:32] (tf32 H) ----
    {
        int row = t >> 1, half = t & 1;
        int gi = SIDX[row];
        const float4* src = (const float4*)(g_ftsl + ((size_t)n * NUMPTS + gi) * 64 + half * 32);
        float4* dst = (float4*)&FC[row * FCS + 32 + half * 32];
#pragma unroll
        for (int u = 0; u < 8; u++) dst[u] = src[u];
    }
    {
        const int row = t & 127, hc = t >> 7;
        const int i = row >> 4, k = row & 15;
        const float* pl = g_PLS + (size_t)(gp0 + i) * 48;
        float px = __ldg(&pl[k]);
        float py = __ldg(&pl[16 + k]);
        float pz = __ldg(&pl[32 + k]);
        float hv[16];
#pragma unroll
        for (int u = 0; u < 16; u++) {
            int c = hc * 16 + u;
            float v = fmaf(px, SD1W[c], fmaf(py, SD1W[32 + c],
                      fmaf(pz, SD1W[64 + c], SD1B[c])));
            hv[u] = tf32f(SD1G[c] * (eluf(v) * BNI) + SD1BE[c]);
        }
#pragma unroll
        for (int u4 = 0; u4 < 4; u4++)
            *(float4*)&FC[row * FCS + hc * 16 + u4 * 4] = *(float4*)&hv[u4 * 4];
    }
    __syncthreads();

    const int i = t >> 5, lane = t & 31;
    const int g = lane >> 2, tg = lane & 3;
    const int r0 = i * 16;

    // ---- E2 (tensor): FC[r,0:32] = act(H[16,32] @ d2W[32,32]), in place ----
    // H lives in FC[r][0:32] ([row][k] = A-frag layout). Load all af first,
    // syncwarp, then overwrite (rows r0..r0+15 are warp-exclusive).
    {
        u32 af[4][4];
#pragma unroll
        for (int kc = 0; kc < 4; kc++) {
            int kb = kc * 8;
            af[kc][0] = __float_as_uint(FC[(r0 + g)     * FCS + kb + tg]);
            af[kc][1] = __float_as_uint(FC[(r0 + g + 8) * FCS + kb + tg]);
            af[kc][2] = __float_as_uint(FC[(r0 + g)     * FCS + kb + tg + 4]);
            af[kc][3] = __float_as_uint(FC[(r0 + g + 8) * FCS + kb + tg + 4]);
        }
        __syncwarp();
        float4 dacc[4];
#pragma unroll
        for (int nj = 0; nj < 4; nj++) {
            dacc[nj] = make_float4(0.f, 0.f, 0.f, 0.f);
            int nb = nj * 8;
#pragma unroll
            for (int kc = 0; kc < 4; kc++) {
                int kb = kc * 8;
                u32 bf0 = __float_as_uint(SD2W[(kb + tg)     * 32 + nb + g]);
                u32 bf1 = __float_as_uint(SD2W[(kb + tg + 4) * 32 + nb + g]);
                mma8(dacc[nj], af[kc], bf0, bf1);
            }
        }
#pragma unroll
        for (int nj = 0; nj < 4; nj++) {
            int c0 = nj * 8 + tg * 2, c1 = c0 + 1;
            float4 d = dacc[nj];
            float2 s0, s1;
            s0.x = SD2G[c0] * (eluf(d.x + SD2B[c0]) * BNI) + SD2BE[c0];
            s0.y = SD2G[c1] * (eluf(d.y + SD2B[c1]) * BNI) + SD2BE[c1];
            s1.x = SD2G[c0] * (eluf(d.z + SD2B[c0]) * BNI) + SD2BE[c0];
            s1.y = SD2G[c1] * (eluf(d.w + SD2B[c1]) * BNI) + SD2BE[c1];
            *(float2*)&FC[(r0 + g)     * FCS + c0] = s0;
            *(float2*)&FC[(r0 + g + 8) * FCS + c0] = s1;
        }
        __syncwarp();
    }

    // ---- Phase F (tensor): fts_X[16,96] = X2[16,16] @ FC[16,96], in place.
    //      X2 read directly from L2-resident g_X2; nj chunked (4 cols x 8)
    //      with read->syncwarp->write per chunk to bound registers. ----
    {
        const float* X2g = g_X2 + (size_t)(gp0 + i) * 256;
        u32 af[2][4];
#pragma unroll
        for (int kc = 0; kc < 2; kc++) {
            int kb = kc * 8;
            af[kc][0] = tf32(__ldg(&X2g[(g)     * 16 + kb + tg]));
            af[kc][1] = tf32(__ldg(&X2g[(g + 8) * 16 + kb + tg]));
            af[kc][2] = tf32(__ldg(&X2g[(g)     * 16 + kb + tg + 4]));
            af[kc][3] = tf32(__ldg(&X2g[(g + 8) * 16 + kb + tg + 4]));
        }
#pragma unroll
        for (int ch = 0; ch < 3; ch++) {
            float4 dacc[4];
#pragma unroll
            for (int j = 0; j < 4; j++) {
                int nj = ch * 4 + j;
                dacc[j] = make_float4(0.f, 0.f, 0.f, 0.f);
                int cn = nj * 8 + g;
#pragma unroll
                for (int kc = 0; kc < 2; kc++) {
                    int kb = kc * 8;
                    u32 bf0 = tf32(FC[(r0 + kb + tg)     * FCS + cn]);
                    u32 bf1 = tf32(FC[(r0 + kb + tg + 4) * FCS + cn]);
                    mma8(dacc[j], af[kc], bf0, bf1);
                }
            }
            __syncwarp();
#pragma unroll
            for (int j = 0; j < 4; j++) {
                int c = (ch * 4 + j) * 8 + tg * 2;
                float2 s0; s0.x = dacc[j].x; s0.y = dacc[j].y;
                float2 s1; s1.x = dacc[j].z; s1.y = dacc[j].w;
                *(float2*)&FC[(r0 + g)     * FCS + c] = s0;
                *(float2*)&FC[(r0 + g + 8) * FCS + c] = s1;
            }
            __syncwarp();
        }
    }

    // ---- Phase G1: depthwise, m-paired fma2 -> g_DW ----
    {
#pragma unroll
        for (int u = 0; u < 3; u++) {
            int c = lane + 32 * u;
            u64 acc = *(const u64*)&dwb[2 * c];
#pragma unroll
            for (int k = 0; k < 16; k++) {
                u64 fd = dup2(FC[(r0 + k) * FCS + c]);
                u64 wd = *(const u64*)&SDW[(k * 96 + c) * 2];
                acc = fma2(fd, wd, acc);
            }
            *(u64*)&g_DW[(size_t)(gp0 + i) * 192 + 2 * c] = acc;
        }
    }
}

// ============================================================================
extern "C" void kernel_launch(void* const* d_in, const int* in_sizes, int n_in,
                              void* d_out, int out_size)
{
    const float* rep_pts = (const float*)d_in[0];
    const float* pts     = (const float*)d_in[1];
    const float* fts     = (const float*)d_in[2];
    const int*   pts_idx = (const int*)d_in[3];
    const float* d0W  = (const float*)d_in[4];
    const float* d0b  = (const float*)d_in[5];
    const float* d0g  = (const float*)d_in[6];
    const float* d0be = (const float*)d_in[7];
    const float* d1W  = (const float*)d_in[8];
    const float* d1b  = (const float*)d_in[9];
    const float* d1g  = (const float*)d_in[10];
    const float* d1be = (const float*)d_in[11];
    const float* d2W  = (const float*)d_in[12];
    const float* d2b  = (const float*)d_in[13];
    const float* d2g  = (const float*)d_in[14];
    const float* d2be = (const float*)d_in[15];
    const float* xcW  = (const float*)d_in[16];
    const float* xcb  = (const float*)d_in[17];
    const float* xd1W = (const float*)d_in[18];
    const float* xd1b = (const float*)d_in[19];
    const float* xd2W = (const float*)d_in[20];
    const float* xd2b = (const float*)d_in[21];
    const float* dwW  = (const float*)d_in[22];
    const float* dwb  = (const float*)d_in[23];
    const float* pwW  = (const float*)d_in[24];
    const float* pwb  = (const float*)d_in[25];
    const float* endg = (const float*)d_in[26];
    const float* endbe= (const float*)d_in[27];
    float* out = (float*)d_out;

    float *pX0, *pX1, *pX2, *pW1, *pW2;
    cudaGetSymbolAddress((void**)&pX0, g_X0);
    cudaGetSymbolAddress((void**)&pX1, g_X1);
    cudaGetSymbolAddress((void**)&pX2, g_X2);
    cudaGetSymbolAddress((void**)&pW1, g_W1t);
    cudaGetSymbolAddress((void**)&pW2, g_W2t);

    dense0_kernel<<<4096, 256>>>(fts, d0W, d0b, d0g, d0be);
    coords_kernel<<<2048, 256>>>(rep_pts, pts, pts_idx);
    cvt_weights<<<256, 256>>>(xd1W, xd2W, pwW);

    cudaFuncSetAttribute(gemmX0_tf32,
                         cudaFuncAttributeMaxDynamicSharedMemorySize, X0_SMEM);
    dim3 xgrid(2, 256);
    gemmX0_tf32<<<xgrid, 256, X0_SMEM>>>(xcW, xcb, pX0);

    dim3 ggrid(2, 256);
    gemm256_tf32<true><<<ggrid, 256>>>(pX0, pW1, xd1b, pX1);
    gemm256_tf32<false><<<ggrid, 256>>>(pX1, pW2, xd2b, pX2);

    cudaFuncSetAttribute(epi_kernel,
                         cudaFuncAttributeMaxDynamicSharedMemorySize, EPI_SM);
    epi_kernel<<<32768 / TILEP, 256, EPI_SM>>>(
        pts_idx, d1W, d1b, d1g, d1be, d2W, d2b, d2g, d2be, dwW, dwb);

    gemm_pw_tf32<<<256, 256>>>(pwb, endg, endbe, out);
}

// round 17
// speedup vs baseline: 2.4847x; 1.0130x over previous
#include <cuda_runtime.h>
#include <math.h>

typedef unsigned long long u64;
typedef unsigned int u32;

// ---- problem dims ----
#define NB      32
#define NUMPTS  2048
#define PN      1024
#define TILEP   8
#define FCS     100
#define BNI     0.9999950000374996f

// scratch
__device__ float g_ftsl[NB * NUMPTS * 64];
__device__ float g_PLS[(size_t)32768 * 48];
__device__ float g_X0 [32768 * 256];
__device__ float g_X1 [32768 * 256];
__device__ float g_X2 [32768 * 256];
__device__ float g_DW [(size_t)32768 * 192];
__device__ float g_W1t[256 * 256];
__device__ float g_W2t[256 * 256];
__device__ float g_pWt[192 * 128];

// Fast ELU (MUFU exp)
__device__ __forceinline__ float eluf(float x) {
    float e = __expf(x) - 1.0f;
    return x > 0.0f ? x : e;
}
__device__ __forceinline__ u64 fma2(u64 a, u64 b, u64 c) {
    u64 d; asm("fma.rn.f32x2 %0,%1,%2,%3;" : "=l"(d) : "l"(a), "l"(b), "l"(c)); return d;
}
__device__ __forceinline__ u64 dup2(float x) {
    u64 d; asm("mov.b64 %0,{%1,%1};" : "=l"(d) : "f"(x)); return d;
}
__device__ __forceinline__ u32 tf32(float f) {
    u32 o; asm("cvt.rna.tf32.f32 %0, %1;" : "=r"(o) : "f"(f)); return o;
}
__device__ __forceinline__ float tf32f(float f) {
    return __uint_as_float(tf32(f));
}
__device__ __forceinline__ void mma8(float4& d, const u32* a, u32 b0, u32 b1) {
    asm("mma.sync.aligned.m16n8k8.row.col.f32.tf32.tf32.f32 "
        "{%0,%1,%2,%3}, {%4,%5,%6,%7}, {%8,%9}, {%0,%1,%2,%3};"
        : "+f"(d.x), "+f"(d.y), "+f"(d.z), "+f"(d.w)
        : "r"(a[0]), "r"(a[1]), "r"(a[2]), "r"(a[3]), "r"(b0), "r"(b1));
}

// ============================================================================
// Kernel A: dense0 -> g_ftsl
// ============================================================================
__global__ void __launch_bounds__(256) dense0_kernel(
    const float* __restrict__ fts, const float* __restrict__ W,
    const float* __restrict__ b,   const float* __restrict__ g,
    const float* __restrict__ be)
{
    __shared__ float Ws[64 * 64];
    __shared__ float xs[16 * 64];
    const int t = threadIdx.x;
    const size_t row0 = (size_t)blockIdx.x * 16;

#pragma unroll
    for (int u = 0; u < 16; u++) Ws[t + 256 * u] = W[t + 256 * u];
    ((float4*)xs)[t] = ((const float4*)(fts + row0 * 64))[t];
    __syncthreads();

    const int r  = t >> 4;
    const int cb = (t & 15) * 4;
    u64 a0 = 0ull, a1 = 0ull;
#pragma unroll 8
    for (int k = 0; k < 64; k++) {
        u64 xd = dup2(xs[r * 64 + k]);
        ulonglong2 w = *(const ulonglong2*)&Ws[k * 64 + cb];
        a0 = fma2(xd, w.x, a0);
        a1 = fma2(xd, w.y, a1);
    }
    float2 f0, f1;
    asm("mov.b64 {%0,%1},%2;" : "=f"(f0.x), "=f"(f0.y) : "l"(a0));
    asm("mov.b64 {%0,%1},%2;" : "=f"(f1.x), "=f"(f1.y) : "l"(a1));
    float4 b4 = *(const float4*)&b[cb];
    float4 g4 = *(const float4*)&g[cb];
    float4 e4 = *(const float4*)&be[cb];
    float4 o;
    o.x = g4.x * (eluf(f0.x + b4.x) * BNI) + e4.x;
    o.y = g4.y * (eluf(f0.y + b4.y) * BNI) + e4.y;
    o.z = g4.z * (eluf(f1.x + b4.z) * BNI) + e4.z;
    o.w = g4.w * (eluf(f1.y + b4.w) * BNI) + e4.w;
    *(float4*)&g_ftsl[(row0 + r) * 64 + cb] = o;
}

// ============================================================================
// Kernel C (coords): gather neighbor coords -> g_PLS
// ============================================================================
__global__ void __launch_bounds__(256) coords_kernel(
    const float* __restrict__ rep_pts, const float* __restrict__ pts,
    const int* __restrict__ pts_idx)
{
    int idx = blockIdx.x * 256 + threadIdx.x;
    int pt = idx >> 4, k = idx & 15;
    int n = pt >> 10;
    int gi = pts_idx[idx];
    const float* pp = pts + ((size_t)n * NUMPTS + gi) * 3;
    const float* rp = rep_pts + (size_t)pt * 3;
    float* dst = g_PLS + (size_t)pt * 48;
    dst[k]      = pp[0] - rp[0];
    dst[16 + k] = pp[1] - rp[1];
    dst[32 + k] = pp[2] - rp[2];
}

// ============================================================================
// Kernel W: pre-round GEMM weights to tf32 bit patterns
// ============================================================================
__global__ void __launch_bounds__(256) cvt_weights(
    const float* __restrict__ xd1W, const float* __restrict__ xd2W,
    const float* __restrict__ pwW)
{
    int idx = blockIdx.x * 256 + threadIdx.x;
    g_W1t[idx] = tf32f(xd1W[idx]);
    g_W2t[idx] = tf32f(xd2W[idx]);
    if (idx < 192 * 128) g_pWt[idx] = tf32f(pwW[idx]);
}

// ============================================================================
// GEMM-X0 (TF32): X0[M,256] = tf32(elu(PLS[M,48] @ xcW^T + xcb))
// ============================================================================
#define X0_SMEM ((128 * 52 + 48 * 136) * 4)

__global__ void __launch_bounds__(256, 2) gemmX0_tf32(
    const float* __restrict__ xcW, const float* __restrict__ xcb,
    float* __restrict__ X0)
{
    extern __shared__ u32 smx[];
    u32 (*As)[52]  = (u32(*)[52])smx;
    u32 (*Bs)[136] = (u32(*)[136])(smx + 128 * 52);

    const int t  = threadIdx.x;
    const int m0 = blockIdx.y << 7;
    const int n0 = blockIdx.x << 7;
    const int wid = t >> 5, lane = t & 31;
    const int wm = wid >> 1, wn = wid & 1;
    const int g = lane >> 2, tg = lane & 3;

    {
        const int ar = t >> 1, ah = (t & 1) * 24;
        const float* Ar = g_PLS + (size_t)(m0 + ar) * 48 + ah;
#pragma unroll
        for (int v = 0; v < 6; v++) {
            float4 a = *(const float4*)&Ar[v * 4];
            u32* ap = &As[ar][ah + v * 4];
            ap[0] = tf32(a.x); ap[1] = tf32(a.y);
            ap[2] = tf32(a.z); ap[3] = tf32(a.w);
        }
    }
    {
        const int q = t >> 1, kh = (t & 1) * 24;
        const float* Wr = xcW + (size_t)(n0 + q) * 48 + kh;
#pragma unroll
        for (int v = 0; v < 6; v++) {
            float4 w = *(const float4*)&Wr[v * 4];
            Bs[kh + v * 4 + 0][q] = tf32(w.x);
            Bs[kh + v * 4 + 1][q] = tf32(w.y);
            Bs[kh + v * 4 + 2][q] = tf32(w.z);
            Bs[kh + v * 4 + 3][q] = tf32(w.w);
        }
    }
    __syncthreads();

    float4 acc[2][8];
#pragma unroll
    for (int i = 0; i < 2; i++)
#pragma unroll
        for (int j = 0; j < 8; j++) acc[i][j] = make_float4(0.f, 0.f, 0.f, 0.f);

#pragma unroll
    for (int kc = 0; kc < 6; kc++) {
        const int kb = kc * 8;
        u32 af[2][4];
#pragma unroll
        for (int mi = 0; mi < 2; mi++) {
            int r = wm * 32 + mi * 16;
            af[mi][0] = As[r + g][kb + tg];
            af[mi][1] = As[r + g + 8][kb + tg];
            af[mi][2] = As[r + g][kb + tg + 4];
            af[mi][3] = As[r + g + 8][kb + tg + 4];
        }
#pragma unroll
        for (int nj = 0; nj < 8; nj++) {
            int cn = wn * 64 + nj * 8 + g;
            u32 bf0 = Bs[kb + tg][cn];
            u32 bf1 = Bs[kb + tg + 4][cn];
            mma8(acc[0][nj], af[0], bf0, bf1);
            mma8(acc[1][nj], af[1], bf0, bf1);
        }
    }

#pragma unroll
    for (int nj = 0; nj < 8; nj++) {
        int col = n0 + wn * 64 + nj * 8 + tg * 2;
        float bv0 = __ldg(&xcb[col]);
        float bv1 = __ldg(&xcb[col + 1]);
#pragma unroll
        for (int mi = 0; mi < 2; mi++) {
            int row = m0 + wm * 32 + mi * 16 + g;
            float4 d = acc[mi][nj];
            float2 s0, s1;
            s0.x = tf32f(eluf(d.x + bv0)); s0.y = tf32f(eluf(d.y + bv1));
            s1.x = tf32f(eluf(d.z + bv0)); s1.y = tf32f(eluf(d.w + bv1));
            *(float2*)&X0[(size_t)row * 256 + col]       = s0;
            *(float2*)&X0[(size_t)(row + 8) * 256 + col] = s1;
        }
    }
}

// ============================================================================
// Paired-fragment GEMM mainloop macros.
// AP[row][kk*4+tg] = (A[row][kk*8+tg], A[row][kk*8+tg+4])    stride 12 u64
// BP[kk*4+tg][n]   = (B[kk*8+tg][n],  B[kk*8+tg+4][n])       stride 132 u64
// Each mma fragment component pair is one LDS.64.
// ============================================================================
#define P_STAGE_A_RAW(BUF) do {                                               \
    uint4 s0, s1;                                                             \
    s0.x = __float_as_uint(a0.x); s0.y = __float_as_uint(a1.x);               \
    s0.z = __float_as_uint(a0.y); s0.w = __float_as_uint(a1.y);               \
    s1.x = __float_as_uint(a0.z); s1.y = __float_as_uint(a1.z);               \
    s1.z = __float_as_uint(a0.w); s1.w = __float_as_uint(a1.w);               \
    *(uint4*)&AP[BUF][ar][akk4]     = s0;                                     \
    *(uint4*)&AP[BUF][ar][akk4 + 2] = s1;                                     \
} while (0)

#define P_STAGE_A_CVT(BUF) do {                                               \
    uint4 s0, s1;                                                             \
    s0.x = tf32(a0.x); s0.y = tf32(a1.x);                                     \
    s0.z = tf32(a0.y); s0.w = tf32(a1.y);                                     \
    s1.x = tf32(a0.z); s1.y = tf32(a1.z);                                     \
    s1.z = tf32(a0.w); s1.w = tf32(a1.w);                                     \
    *(uint4*)&AP[BUF][ar][akk4]     = s0;                                     \
    *(uint4*)&AP[BUF][ar][akk4 + 2] = s1;                                     \
} while (0)

#define P_STAGE_B(BUF) do {                                                   \
    uint4 s0, s1;                                                             \
    s0.x = __float_as_uint(b0.x); s0.y = __float_as_uint(b1.x);               \
    s0.z = __float_as_uint(b0.y); s0.w = __float_as_uint(b1.y);               \
    s1.x = __float_as_uint(b0.z); s1.y = __float_as_uint(b1.z);               \
    s1.z = __float_as_uint(b0.w); s1.w = __float_as_uint(b1.w);               \
    *(uint4*)&BP[BUF][pr][nb]     = s0;                                       \
    *(uint4*)&BP[BUF][pr][nb + 2] = s1;                                       \
} while (0)

#define P_MMA(BUF) do {                                                       \
    _Pragma("unroll")                                                         \
    for (int kk = 0; kk < 2; kk++) {                                          \
        const int kp = kk * 4 + tg;                                           \
        uint2 aLo0 = AP[BUF][wm * 32 + g][kp];                                \
        uint2 aHi0 = AP[BUF][wm * 32 + g + 8][kp];                            \
        uint2 aLo1 = AP[BUF][wm * 32 + 16 + g][kp];                           \
        uint2 aHi1 = AP[BUF][wm * 32 + 24 + g][kp];                           \
        u32 af0[4] = {aLo0.x, aHi0.x, aLo0.y, aHi0.y};                        \
        u32 af1[4] = {aLo1.x, aHi1.x, aLo1.y, aHi1.y};                        \
        _Pragma("unroll")                                                     \
        for (int nj = 0; nj < 8; nj++) {                                      \
            int cn = wn * 64 + nj * 8 + g;                                    \
            uint2 bp = BP[BUF][kp][cn];                                       \
            mma8(acc[0][nj], af0, bp.x, bp.y);                                \
            mma8(acc[1][nj], af1, bp.x, bp.y);                                \
        }                                                                     \
    }                                                                         \
} while (0)

// ============================================================================
// GEMM (TF32): C[M,256] = act(A[M,256] @ W[256,256] + bias); inputs pre-rounded
// ============================================================================
template<bool ELU>
__global__ void __launch_bounds__(256, 2) gemm256_tf32(
    const float* __restrict__ A, const float* __restrict__ W,
    const float* __restrict__ bias, float* __restrict__ C)
{
    __shared__ uint2 AP[2][128][12];
    __shared__ uint2 BP[2][8][132];
    const int t  = threadIdx.x;
    const int m0 = blockIdx.y << 7;
    const int n0 = blockIdx.x << 7;
    const int wid = t >> 5, lane = t & 31;
    const int wm = wid >> 1, wn = wid & 1;
    const int g = lane >> 2, tg = lane & 3;

    float4 acc[2][8];
#pragma unroll
    for (int i = 0; i < 2; i++)
#pragma unroll
        for (int j = 0; j < 8; j++) acc[i][j] = make_float4(0.f, 0.f, 0.f, 0.f);

    const int ar = t >> 1, akk4 = (t & 1) * 4;
    const int pr = t >> 5, nb = (t & 31) * 4;
    const int bk1 = (pr >> 2) * 8 + (pr & 3);
    const float* Arow = A + (size_t)(m0 + ar) * 256 + akk4 * 2;  // akk*8

    float4 a0 = *(const float4*)&Arow[0];
    float4 a1 = *(const float4*)&Arow[4];
    float4 b0 = *(const float4*)&W[(size_t)bk1 * 256 + n0 + nb];
    float4 b1 = *(const float4*)&W[(size_t)(bk1 + 4) * 256 + n0 + nb];

#pragma unroll 1
    for (int k0 = 0; k0 < 16; k0 += 2) {
        P_STAGE_A_RAW(0); P_STAGE_B(0);
        __syncthreads();
        {
            int kn = (k0 + 1) * 16;
            a0 = *(const float4*)&Arow[kn];
            a1 = *(const float4*)&Arow[kn + 4];
            b0 = *(const float4*)&W[(size_t)(kn + bk1) * 256 + n0 + nb];
            b1 = *(const float4*)&W[(size_t)(kn + bk1 + 4) * 256 + n0 + nb];
        }
        P_MMA(0);
        P_STAGE_A_RAW(1); P_STAGE_B(1);
        __syncthreads();
        if (k0 < 14) {
            int kn = (k0 + 2) * 16;
            a0 = *(const float4*)&Arow[kn];
            a1 = *(const float4*)&Arow[kn + 4];
            b0 = *(const float4*)&W[(size_t)(kn + bk1) * 256 + n0 + nb];
            b1 = *(const float4*)&W[(size_t)(kn + bk1 + 4) * 256 + n0 + nb];
        }
        P_MMA(1);
    }

#pragma unroll
    for (int nj = 0; nj < 8; nj++) {
        int col = n0 + wn * 64 + nj * 8 + tg * 2;
        float bv0 = __ldg(&bias[col]);
        float bv1 = __ldg(&bias[col + 1]);
#pragma unroll
        for (int mi = 0; mi < 2; mi++) {
            int row = m0 + wm * 32 + mi * 16 + g;
            float4 d = acc[mi][nj];
            float v0 = d.x + bv0, v1 = d.y + bv1;
            float v2 = d.z + bv0, v3 = d.w + bv1;
            if (ELU) {
                v0 = tf32f(eluf(v0)); v1 = tf32f(eluf(v1));
                v2 = tf32f(eluf(v2)); v3 = tf32f(eluf(v3));
            }
            float2 s0; s0.x = v0; s0.y = v1;
            float2 s1; s1.x = v2; s1.y = v3;
            *(float2*)&C[(size_t)row * 256 + col]       = s0;
            *(float2*)&C[(size_t)(row + 8) * 256 + col] = s1;
        }
    }
}

// ============================================================================
// GEMM-PW (TF32): out = endg*(elu(DW[M,192]@pWt[192,128]+pwb)*BNI)+endbe
// ============================================================================
__global__ void __launch_bounds__(256, 2) gemm_pw_tf32(
    const float* __restrict__ pwb,
    const float* __restrict__ endg, const float* __restrict__ endbe,
    float* __restrict__ out)
{
    __shared__ uint2 AP[2][128][12];
    __shared__ uint2 BP[2][8][132];
    const int t  = threadIdx.x;
    const int m0 = blockIdx.x << 7;
    const int wid = t >> 5, lane = t & 31;
    const int wm = wid >> 1, wn = wid & 1;
    const int g = lane >> 2, tg = lane & 3;

    float4 acc[2][8];
#pragma unroll
    for (int i = 0; i < 2; i++)
#pragma unroll
        for (int j = 0; j < 8; j++) acc[i][j] = make_float4(0.f, 0.f, 0.f, 0.f);

    const int ar = t >> 1, akk4 = (t & 1) * 4;
    const int pr = t >> 5, nb = (t & 31) * 4;
    const int bk1 = (pr >> 2) * 8 + (pr & 3);
    const float* Arow = g_DW + (size_t)(m0 + ar) * 192 + akk4 * 2;

    float4 a0 = *(const float4*)&Arow[0];
    float4 a1 = *(const float4*)&Arow[4];
    float4 b0 = *(const float4*)&g_pWt[(size_t)bk1 * 128 + nb];
    float4 b1 = *(const float4*)&g_pWt[(size_t)(bk1 + 4) * 128 + nb];

#pragma unroll 1
    for (int k0 = 0; k0 < 12; k0 += 2) {
        P_STAGE_A_CVT(0); P_STAGE_B(0);
        __syncthreads();
        {
            int kn = (k0 + 1) * 16;
            a0 = *(const float4*)&Arow[kn];
            a1 = *(const float4*)&Arow[kn + 4];
            b0 = *(const float4*)&g_pWt[(size_t)(kn + bk1) * 128 + nb];
            b1 = *(const float4*)&g_pWt[(size_t)(kn + bk1 + 4) * 128 + nb];
        }
        P_MMA(0);
        P_STAGE_A_CVT(1); P_STAGE_B(1);
        __syncthreads();
        if (k0 < 10) {
            int kn = (k0 + 2) * 16;
            a0 = *(const float4*)&Arow[kn];
            a1 = *(const float4*)&Arow[kn + 4];
            b0 = *(const float4*)&g_pWt[(size_t)(kn + bk1) * 128 + nb];
            b1 = *(const float4*)&g_pWt[(size_t)(kn + bk1 + 4) * 128 + nb];
        }
        P_MMA(1);
    }

#pragma unroll
    for (int nj = 0; nj < 8; nj++) {
        int col = wn * 64 + nj * 8 + tg * 2;
        float bv0 = __ldg(&pwb[col]),   bv1 = __ldg(&pwb[col + 1]);
        float gv0 = __ldg(&endg[col]),  gv1 = __ldg(&endg[col + 1]);
        float ev0 = __ldg(&endbe[col]), ev1 = __ldg(&endbe[col + 1]);
#pragma unroll
        for (int mi = 0; mi < 2; mi++) {
            int row = m0 + wm * 32 + mi * 16 + g;
            float4 d = acc[mi][nj];
            float2 s0, s1;
            s0.x = gv0 * (eluf(d.x + bv0) * BNI) + ev0;
            s0.y = gv1 * (eluf(d.y + bv1) * BNI) + ev1;
            s1.x = gv0 * (eluf(d.z + bv0) * BNI) + ev0;
            s1.y = gv1 * (eluf(d.w + bv1) * BNI) + ev1;
            *(float2*)&out[(size_t)row * 128 + col]       = s0;
            *(float2*)&out[(size_t)(row + 8) * 128 + col] = s1;
        }
    }
}

// ============================================================================
// Kernel E (mega-epilogue), 3 CTAs/SM — unchanged from R16 (proven)
// ============================================================================
#define EPI_SM (17312 * 4)

__global__ void __launch_bounds__(256, 3) epi_kernel(
    const int* __restrict__ pts_idx,
    const float* __restrict__ d1W, const float* __restrict__ d1b,
    const float* __restrict__ d1g, const float* __restrict__ d1be,
    const float* __restrict__ d2W, const float* __restrict__ d2b,
    const float* __restrict__ d2g, const float* __restrict__ d2be,
    const float* __restrict__ dwW, const float* __restrict__ dwb)
{
    extern __shared__ float sm[];
    float* FC    = sm;            // [8][16][FCS]
    float* SDW   = sm + 12800;
    float* SD1W  = sm + 15872; float* SD1B  = sm + 15968;
    float* SD1G  = sm + 16000; float* SD1BE = sm + 16032;
    float* SD2W  = sm + 16064;    // [32][32] tf32-rounded
    float* SD2B  = sm + 17088; float* SD2G  = sm + 17120;
    float* SD2BE = sm + 17152;
    int*   SIDX  = (int*)(sm + 17184);

    const int t   = threadIdx.x;
    const int gp0 = blockIdx.x * TILEP;
    const int n   = gp0 >> 10;

    if (t < 128) SIDX[t] = pts_idx[(size_t)gp0 * 16 + t];
    for (int u = t; u < 96; u += 256) SD1W[u] = d1W[u];
    for (int u = t; u < 1024; u += 256) SD2W[u] = tf32f(d2W[u]);
    if (t < 32) {
        SD1B[t] = d1b[t]; SD1G[t] = d1g[t]; SD1BE[t] = d1be[t];
        SD2B[t] = d2b[t]; SD2G[t] = d2g[t]; SD2BE[t] = d2be[t];
    }
    for (int idx = t; idx < 1536; idx += 256) {
        int k = idx / 96, c = idx - k * 96;
        float2 w;
        w.x = dwW[c * 32 + k];
        w.y = dwW[c * 32 + 16 + k];
        *(float2*)&SDW[idx * 2] = w;
    }
    __syncthreads();

    {
        int row = t >> 1, half = t & 1;
        int gi = SIDX[row];
        const float4* src = (const float4*)(g_ftsl + ((size_t)n * NUMPTS + gi) * 64 + half * 32);
        float4* dst = (float4*)&FC[row * FCS + 32 + half * 32];
#pragma unroll
        for (int u = 0; u < 8; u++) dst[u] = src[u];
    }
    {
        const int row = t & 127, hc = t >> 7;
        const int i = row >> 4, k = row & 15;
        const float* pl = g_PLS + (size_t)(gp0 + i) * 48;
        float px = __ldg(&pl[k]);
        float py = __ldg(&pl[16 + k]);
        float pz = __ldg(&pl[32 + k]);
        float hv[16];
#pragma unroll
        for (int u = 0; u < 16; u++) {
            int c = hc * 16 + u;
            float v = fmaf(px, SD1W[c], fmaf(py, SD1W[32 + c],
                      fmaf(pz, SD1W[64 + c], SD1B[c])));
            hv[u] = tf32f(SD1G[c] * (eluf(v) * BNI) + SD1BE[c]);
        }
#pragma unroll
        for (int u4 = 0; u4 < 4; u4++)
            *(float4*)&FC[row * FCS + hc * 16 + u4 * 4] = *(float4*)&hv[u4 * 4];
    }
    __syncthreads();

    const int i = t >> 5, lane = t & 31;
    const int g = lane >> 2, tg = lane & 3;
    const int r0 = i * 16;

    // E2 (tensor), in place
    {
        u32 af[4][4];
#pragma unroll
        for (int kc = 0; kc < 4; kc++) {
            int kb = kc * 8;
            af[kc][0] = __float_as_uint(FC[(r0 + g)     * FCS + kb + tg]);
            af[kc][1] = __float_as_uint(FC[(r0 + g + 8) * FCS + kb + tg]);
            af[kc][2] = __float_as_uint(FC[(r0 + g)     * FCS + kb + tg + 4]);
            af[kc][3] = __float_as_uint(FC[(r0 + g + 8) * FCS + kb + tg + 4]);
        }
        __syncwarp();
        float4 dacc[4];
#pragma unroll
        for (int nj = 0; nj < 4; nj++) {
            dacc[nj] = make_float4(0.f, 0.f, 0.f, 0.f);
            int nbq = nj * 8;
#pragma unroll
            for (int kc = 0; kc < 4; kc++) {
                int kb = kc * 8;
                u32 bf0 = __float_as_uint(SD2W[(kb + tg)     * 32 + nbq + g]);
                u32 bf1 = __float_as_uint(SD2W[(kb + tg + 4) * 32 + nbq + g]);
                mma8(dacc[nj], af[kc], bf0, bf1);
            }
        }
#pragma unroll
        for (int nj = 0; nj < 4; nj++) {
            int c0 = nj * 8 + tg * 2, c1 = c0 + 1;
            float4 d = dacc[nj];
            float2 s0, s1;
            s0.x = SD2G[c0] * (eluf(d.x + SD2B[c0]) * BNI) + SD2BE[c0];
            s0.y = SD2G[c1] * (eluf(d.y + SD2B[c1]) * BNI) + SD2BE[c1];
            s1.x = SD2G[c0] * (eluf(d.z + SD2B[c0]) * BNI) + SD2BE[c0];
            s1.y = SD2G[c1] * (eluf(d.w + SD2B[c1]) * BNI) + SD2BE[c1];
            *(float2*)&FC[(r0 + g)     * FCS + c0] = s0;
            *(float2*)&FC[(r0 + g + 8) * FCS + c0] = s1;
        }
        __syncwarp();
    }

    // Phase F (tensor), X2 from L2, in place
    {
        const float* X2g = g_X2 + (size_t)(gp0 + i) * 256;
        u32 af[2][4];
#pragma unroll
        for (int kc = 0; kc < 2; kc++) {
            int kb = kc * 8;
            af[kc][0] = tf32(__ldg(&X2g[(g)     * 16 + kb + tg]));
            af[kc][1] = tf32(__ldg(&X2g[(g + 8) * 16 + kb + tg]));
            af[kc][2] = tf32(__ldg(&X2g[(g)     * 16 + kb + tg + 4]));
            af[kc][3] = tf32(__ldg(&X2g[(g + 8) * 16 + kb + tg + 4]));
        }
#pragma unroll
        for (int ch = 0; ch < 3; ch++) {
            float4 dacc[4];
#pragma unroll
            for (int j = 0; j < 4; j++) {
                int nj = ch * 4 + j;
                dacc[j] = make_float4(0.f, 0.f, 0.f, 0.f);
                int cn = nj * 8 + g;
#pragma unroll
                for (int kc = 0; kc < 2; kc++) {
                    int kb = kc * 8;
                    u32 bf0 = tf32(FC[(r0 + kb + tg)     * FCS + cn]);
                    u32 bf1 = tf32(FC[(r0 + kb + tg + 4) * FCS + cn]);
                    mma8(dacc[j], af[kc], bf0, bf1);
                }
            }
            __syncwarp();
#pragma unroll
            for (int j = 0; j < 4; j++) {
                int c = (ch * 4 + j) * 8 + tg * 2;
                float2 s0; s0.x = dacc[j].x; s0.y = dacc[j].y;
                float2 s1; s1.x = dacc[j].z; s1.y = dacc[j].w;
                *(float2*)&FC[(r0 + g)     * FCS + c] = s0;
                *(float2*)&FC[(r0 + g + 8) * FCS + c] = s1;
            }
            __syncwarp();
        }
    }

    // Phase G1: depthwise -> g_DW
    {
#pragma unroll
        for (int u = 0; u < 3; u++) {
            int c = lane + 32 * u;
            u64 acc = *(const u64*)&dwb[2 * c];
#pragma unroll
            for (int k = 0; k < 16; k++) {
                u64 fd = dup2(FC[(r0 + k) * FCS + c]);
                u64 wd = *(const u64*)&SDW[(k * 96 + c) * 2];
                acc = fma2(fd, wd, acc);
            }
            *(u64*)&g_DW[(size_t)(gp0 + i) * 192 + 2 * c] = acc;
        }
    }
}

// ============================================================================
extern "C" void kernel_launch(void* const* d_in, const int* in_sizes, int n_in,
                              void* d_out, int out_size)
{
    const float* rep_pts = (const float*)d_in[0];
    const float* pts     = (const float*)d_in[1];
    const float* fts     = (const float*)d_in[2];
    const int*   pts_idx = (const int*)d_in[3];
    const float* d0W  = (const float*)d_in[4];
    const float* d0b  = (const float*)d_in[5];
    const float* d0g  = (const float*)d_in[6];
    const float* d0be = (const float*)d_in[7];
    const float* d1W  = (const float*)d_in[8];
    const float* d1b  = (const float*)d_in[9];
    const float* d1g  = (const float*)d_in[10];
    const float* d1be = (const float*)d_in[11];
    const float* d2W  = (const float*)d_in[12];
    const float* d2b  = (const float*)d_in[13];
    const float* d2g  = (const float*)d_in[14];
    const float* d2be = (const float*)d_in[15];
    const float* xcW  = (const float*)d_in[16];
    const float* xcb  = (const float*)d_in[17];
    const float* xd1W = (const float*)d_in[18];
    const float* xd1b = (const float*)d_in[19];
    const float* xd2W = (const float*)d_in[20];
    const float* xd2b = (const float*)d_in[21];
    const float* dwW  = (const float*)d_in[22];
    const float* dwb  = (const float*)d_in[23];
    const float* pwW  = (const float*)d_in[24];
    const float* pwb  = (const float*)d_in[25];
    const float* endg = (const float*)d_in[26];
    const float* endbe= (const float*)d_in[27];
    float* out = (float*)d_out;

    float *pX0, *pX1, *pX2, *pW1, *pW2;
    cudaGetSymbolAddress((void**)&pX0, g_X0);
    cudaGetSymbolAddress((void**)&pX1, g_X1);
    cudaGetSymbolAddress((void**)&pX2, g_X2);
    cudaGetSymbolAddress((void**)&pW1, g_W1t);
    cudaGetSymbolAddress((void**)&pW2, g_W2t);

    dense0_kernel<<<4096, 256>>>(fts, d0W, d0b, d0g, d0be);
    coords_kernel<<<2048, 256>>>(rep_pts, pts, pts_idx);
    cvt_weights<<<256, 256>>>(xd1W, xd2W, pwW);

    cudaFuncSetAttribute(gemmX0_tf32,
                         cudaFuncAttributeMaxDynamicSharedMemorySize, X0_SMEM);
    dim3 xgrid(2, 256);
    gemmX0_tf32<<<xgrid, 256, X0_SMEM>>>(xcW, xcb, pX0);

    dim3 ggrid(2, 256);
    gemm256_tf32<true><<<ggrid, 256>>>(pX0, pW1, xd1b, pX1);
    gemm256_tf32<false><<<ggrid, 256>>>(pX1, pW2, xd2b, pX2);

    cudaFuncSetAttribute(epi_kernel,
                         cudaFuncAttributeMaxDynamicSharedMemorySize, EPI_SM);
    epi_kernel<<<32768 / TILEP, 256, EPI_SM>>>(
        pts_idx, d1W, d1b, d1g, d1be, d2W, d2b, d2g, d2be, dwW, dwb);

    gemm_pw_tf32<<<256, 256>>>(pwb, endg, endbe, out);
}